// round 1
// baseline (speedup 1.0000x reference)
#include <cuda_runtime.h>
#include <cuda_bf16.h>
#include <math.h>

// ---------------------------------------------------------------------------
// Transformer block, fp32 baseline.
//   x:[2,2048,1024]  -> out:[2,2048,1024]
//   tokens M = 4096, D = 1024, H = 16, hd = 64, FF = 4096
// Pipeline:
//   q = x@Wq+bq ; k = x@Wk+bk ; v = x@Wv+bv          (SGEMM x3)
//   att = softmax(q k^T) v  (per head, NO 1/sqrt(hd)) (flash kernel)
//   x1  = att@Wo + bo + x                              (SGEMM, residual)
//   x2  = LN(x1; g1,beta1)
//   h   = gelu_exact(x2@W1 + b1)                       (SGEMM, gelu)
//   x3  = h@W2 + b2 + x2                               (SGEMM, residual)
//   out = LN(x3; g2,beta2)
// ---------------------------------------------------------------------------

#define MTOK 4096
#define DDIM 1024
#define FFDIM 4096
#define NHEAD 16
#define HDIM 64
#define SEQ 2048
#define BATCH 2

// Scratch layout (floats) in one device global:
//   q, k, v, att, x1, x2, x3 : MTOK*DDIM each   (7 * 4.19M)
//   h : MTOK*FFDIM                               (16.78M)
#define OFF_Q   ((size_t)0)
#define OFF_K   (OFF_Q   + (size_t)MTOK*DDIM)
#define OFF_V   (OFF_K   + (size_t)MTOK*DDIM)
#define OFF_ATT (OFF_V   + (size_t)MTOK*DDIM)
#define OFF_X1  (OFF_ATT + (size_t)MTOK*DDIM)
#define OFF_X2  (OFF_X1  + (size_t)MTOK*DDIM)
#define OFF_X3  (OFF_X2  + (size_t)MTOK*DDIM)
#define OFF_H   (OFF_X3  + (size_t)MTOK*DDIM)
#define SCRATCH_FLOATS (OFF_H + (size_t)MTOK*FFDIM)

__device__ float g_scratch[SCRATCH_FLOATS];

// ---------------------------------------------------------------------------
// SGEMM: C[M,N] = A[M,K] @ B[K,N] + bias[N]  (+ epilogue)
// EPI: 0 = bias only, 1 = bias + exact GELU, 2 = bias + residual add
// BM=128 BN=128 BK=16, 256 threads, 8x8 per-thread microtile.
// Requires M%128==0, N%128==0, K%16==0 (true for all calls here).
// ---------------------------------------------------------------------------
template <int EPI>
__global__ __launch_bounds__(256)
void sgemm_kernel(const float* __restrict__ A, const float* __restrict__ B,
                  const float* __restrict__ bias, const float* __restrict__ res,
                  float* __restrict__ C, int M, int N, int K)
{
    const int BM = 128, BN = 128, BK = 16, TM = 8, TN = 8;
    __shared__ float As[BK * BM];   // transposed: As[k][m]
    __shared__ float Bs[BK * BN];   // Bs[k][n]

    const int cRow = blockIdx.y;
    const int cCol = blockIdx.x;
    const int tid  = threadIdx.x;
    const int tRow = tid / 16;      // 0..15
    const int tCol = tid % 16;      // 0..15

    const float* Ablk = A + (size_t)cRow * BM * K;
    const float* Bblk = B + (size_t)cCol * BN;

    float acc[TM][TN];
#pragma unroll
    for (int i = 0; i < TM; i++)
#pragma unroll
        for (int j = 0; j < TN; j++) acc[i][j] = 0.0f;

    // A tile loads: 128 rows x 16 cols, float4 per thread, 2 passes of 64 rows
    const int aRow = tid / 4;           // 0..63
    const int aCol = (tid % 4) * 4;     // 0,4,8,12
    // B tile loads: 16 rows x 128 cols, float4 per thread, 2 passes of 8 rows
    const int bRow = tid / 32;          // 0..7
    const int bCol = (tid % 32) * 4;    // 0..124

    for (int k0 = 0; k0 < K; k0 += BK) {
#pragma unroll
        for (int p = 0; p < 2; p++) {
            int r = aRow + p * 64;
            float4 t = *(const float4*)(Ablk + (size_t)r * K + k0 + aCol);
            As[(aCol + 0) * BM + r] = t.x;
            As[(aCol + 1) * BM + r] = t.y;
            As[(aCol + 2) * BM + r] = t.z;
            As[(aCol + 3) * BM + r] = t.w;
        }
#pragma unroll
        for (int p = 0; p < 2; p++) {
            int r = bRow + p * 8;
            *(float4*)(Bs + r * BN + bCol) =
                *(const float4*)(Bblk + (size_t)(k0 + r) * N + bCol);
        }
        __syncthreads();

        float regM[TM], regN[TN];
#pragma unroll
        for (int k = 0; k < BK; k++) {
#pragma unroll
            for (int i = 0; i < TM; i++) regM[i] = As[k * BM + tRow * TM + i];
#pragma unroll
            for (int j = 0; j < TN; j++) regN[j] = Bs[k * BN + tCol * TN + j];
#pragma unroll
            for (int i = 0; i < TM; i++)
#pragma unroll
                for (int j = 0; j < TN; j++)
                    acc[i][j] = fmaf(regM[i], regN[j], acc[i][j]);
        }
        __syncthreads();
    }

    // Epilogue
#pragma unroll
    for (int i = 0; i < TM; i++) {
        const int row = cRow * BM + tRow * TM + i;
#pragma unroll
        for (int j = 0; j < TN; j += 4) {
            const int col = cCol * BN + tCol * TN + j;
            float4 v;
            v.x = acc[i][j + 0] + bias[col + 0];
            v.y = acc[i][j + 1] + bias[col + 1];
            v.z = acc[i][j + 2] + bias[col + 2];
            v.w = acc[i][j + 3] + bias[col + 3];
            if (EPI == 1) {  // exact GELU: 0.5*x*(1+erf(x/sqrt(2)))
                v.x = 0.5f * v.x * (1.0f + erff(v.x * 0.70710678118654752f));
                v.y = 0.5f * v.y * (1.0f + erff(v.y * 0.70710678118654752f));
                v.z = 0.5f * v.z * (1.0f + erff(v.z * 0.70710678118654752f));
                v.w = 0.5f * v.w * (1.0f + erff(v.w * 0.70710678118654752f));
            } else if (EPI == 2) {
                const float4 r = *(const float4*)(res + (size_t)row * N + col);
                v.x += r.x; v.y += r.y; v.z += r.z; v.w += r.w;
            }
            *(float4*)(C + (size_t)row * N + col) = v;
        }
    }
}

// ---------------------------------------------------------------------------
// Flash attention (fp32, no scaling): one thread owns one query row.
// Block: 128 threads = 128 query rows. K/V tiles of 32 rows in smem.
// Q/K/V are [B*S, D] with head h occupying columns [h*64, h*64+64).
// ---------------------------------------------------------------------------
#define AT_ROWS 128
#define KT 32

__global__ __launch_bounds__(AT_ROWS)
void attn_kernel(const float* __restrict__ Q, const float* __restrict__ K,
                 const float* __restrict__ V, float* __restrict__ O)
{
    const int b = blockIdx.z;
    const int h = blockIdx.y;
    const int qr = blockIdx.x * AT_ROWS + threadIdx.x;   // query row within seq

    __shared__ float ks[KT][HDIM];
    __shared__ float vs[KT][HDIM];

    const size_t rowbase = (size_t)b * SEQ;
    const float* qp = Q + (rowbase + qr) * DDIM + h * HDIM;

    float4 qv[HDIM / 4];
    float4 ov[HDIM / 4];
#pragma unroll
    for (int d = 0; d < HDIM / 4; d++) {
        qv[d] = ((const float4*)qp)[d];
        ov[d] = make_float4(0.f, 0.f, 0.f, 0.f);
    }
    float m = -1e30f, l = 0.0f;

    const float* Kbase = K + rowbase * DDIM + h * HDIM;
    const float* Vbase = V + rowbase * DDIM + h * HDIM;

    for (int kt = 0; kt < SEQ; kt += KT) {
        __syncthreads();
        // cooperative load of K/V tiles: KT*HDIM/4 = 512 float4 per array
        for (int i = threadIdx.x; i < KT * (HDIM / 4); i += AT_ROWS) {
            const int r = i / (HDIM / 4);
            const int c = i % (HDIM / 4);
            ((float4*)ks[r])[c] = ((const float4*)(Kbase + (size_t)(kt + r) * DDIM))[c];
            ((float4*)vs[r])[c] = ((const float4*)(Vbase + (size_t)(kt + r) * DDIM))[c];
        }
        __syncthreads();

        float s[KT];
        float tmax = m;
#pragma unroll
        for (int j = 0; j < KT; j++) {
            const float4* kp = (const float4*)ks[j];
            float acc = 0.0f;
#pragma unroll
            for (int d = 0; d < HDIM / 4; d++) {
                float4 kk = kp[d];
                acc = fmaf(qv[d].x, kk.x, acc);
                acc = fmaf(qv[d].y, kk.y, acc);
                acc = fmaf(qv[d].z, kk.z, acc);
                acc = fmaf(qv[d].w, kk.w, acc);
            }
            s[j] = acc;
            tmax = fmaxf(tmax, acc);
        }

        const float scale = expf(m - tmax);   // ==1 when tmax==m
        l *= scale;
#pragma unroll
        for (int d = 0; d < HDIM / 4; d++) {
            ov[d].x *= scale; ov[d].y *= scale;
            ov[d].z *= scale; ov[d].w *= scale;
        }
        m = tmax;

#pragma unroll
        for (int j = 0; j < KT; j++) {
            const float p = expf(s[j] - m);
            l += p;
            const float4* vp = (const float4*)vs[j];
#pragma unroll
            for (int d = 0; d < HDIM / 4; d++) {
                float4 vvv = vp[d];
                ov[d].x = fmaf(p, vvv.x, ov[d].x);
                ov[d].y = fmaf(p, vvv.y, ov[d].y);
                ov[d].z = fmaf(p, vvv.z, ov[d].z);
                ov[d].w = fmaf(p, vvv.w, ov[d].w);
            }
        }
    }

    const float inv = 1.0f / l;
    float* op = O + (rowbase + qr) * DDIM + h * HDIM;
#pragma unroll
    for (int d = 0; d < HDIM / 4; d++) {
        float4 o4 = ov[d];
        o4.x *= inv; o4.y *= inv; o4.z *= inv; o4.w *= inv;
        ((float4*)op)[d] = o4;
    }
}

// ---------------------------------------------------------------------------
// LayerNorm over last dim (D=1024), one block per row, 256 threads.
// ---------------------------------------------------------------------------
__global__ __launch_bounds__(256)
void ln_kernel(const float* __restrict__ x, const float* __restrict__ g,
               const float* __restrict__ b, float* __restrict__ y)
{
    const int D = DDIM;
    const int row = blockIdx.x;
    const float* xr = x + (size_t)row * D;

    float v[4];
    float s = 0.f, s2 = 0.f;
#pragma unroll
    for (int i = 0; i < 4; i++) {
        v[i] = xr[threadIdx.x + i * 256];
        s += v[i];
        s2 = fmaf(v[i], v[i], s2);
    }
#pragma unroll
    for (int o = 16; o > 0; o >>= 1) {
        s  += __shfl_xor_sync(0xffffffffu, s, o);
        s2 += __shfl_xor_sync(0xffffffffu, s2, o);
    }
    __shared__ float ss[8], ss2[8];
    const int w = threadIdx.x >> 5;
    if ((threadIdx.x & 31) == 0) { ss[w] = s; ss2[w] = s2; }
    __syncthreads();
    if (threadIdx.x < 32) {
        s  = (threadIdx.x < 8) ? ss[threadIdx.x]  : 0.f;
        s2 = (threadIdx.x < 8) ? ss2[threadIdx.x] : 0.f;
#pragma unroll
        for (int o = 4; o > 0; o >>= 1) {
            s  += __shfl_xor_sync(0xffffffffu, s, o);
            s2 += __shfl_xor_sync(0xffffffffu, s2, o);
        }
        if (threadIdx.x == 0) { ss[0] = s; ss2[0] = s2; }
    }
    __syncthreads();
    const float mu  = ss[0] * (1.0f / D);
    const float var = ss2[0] * (1.0f / D) - mu * mu;
    const float inv = rsqrtf(var + 1e-5f);
#pragma unroll
    for (int i = 0; i < 4; i++) {
        const int c = threadIdx.x + i * 256;
        y[(size_t)row * D + c] = (v[i] - mu) * inv * g[c] + b[c];
    }
}

// ---------------------------------------------------------------------------
// Launch
// ---------------------------------------------------------------------------
extern "C" void kernel_launch(void* const* d_in, const int* in_sizes, int n_in,
                              void* d_out, int out_size)
{
    (void)in_sizes; (void)n_in; (void)out_size;
    const float* x     = (const float*)d_in[0];
    const float* Wq    = (const float*)d_in[1];
    const float* bq    = (const float*)d_in[2];
    const float* Wk    = (const float*)d_in[3];
    const float* bk    = (const float*)d_in[4];
    const float* Wv    = (const float*)d_in[5];
    const float* bv    = (const float*)d_in[6];
    const float* Wo    = (const float*)d_in[7];
    const float* bo    = (const float*)d_in[8];
    const float* W1    = (const float*)d_in[9];
    const float* b1    = (const float*)d_in[10];
    const float* W2    = (const float*)d_in[11];
    const float* b2    = (const float*)d_in[12];
    const float* g1    = (const float*)d_in[13];
    const float* beta1 = (const float*)d_in[14];
    const float* g2    = (const float*)d_in[15];
    const float* beta2 = (const float*)d_in[16];
    float* out = (float*)d_out;

    float* scr = nullptr;
    cudaGetSymbolAddress((void**)&scr, g_scratch);
    float* q   = scr + OFF_Q;
    float* k   = scr + OFF_K;
    float* v   = scr + OFF_V;
    float* att = scr + OFF_ATT;
    float* x1  = scr + OFF_X1;
    float* x2  = scr + OFF_X2;
    float* x3  = scr + OFF_X3;
    float* hbuf = scr + OFF_H;

    const dim3 gD(DDIM / 128, MTOK / 128);    // N=1024 GEMMs: (8, 32)
    const dim3 gF(FFDIM / 128, MTOK / 128);   // N=4096 GEMM:  (32, 32)

    // QKV projections
    sgemm_kernel<0><<<gD, 256>>>(x, Wq, bq, nullptr, q, MTOK, DDIM, DDIM);
    sgemm_kernel<0><<<gD, 256>>>(x, Wk, bk, nullptr, k, MTOK, DDIM, DDIM);
    sgemm_kernel<0><<<gD, 256>>>(x, Wv, bv, nullptr, v, MTOK, DDIM, DDIM);

    // Attention (no scaling)
    attn_kernel<<<dim3(SEQ / AT_ROWS, NHEAD, BATCH), AT_ROWS>>>(q, k, v, att);

    // Output projection + residual
    sgemm_kernel<2><<<gD, 256>>>(att, Wo, bo, x, x1, MTOK, DDIM, DDIM);

    // LN1
    ln_kernel<<<MTOK, 256>>>(x1, g1, beta1, x2);

    // FFN
    sgemm_kernel<1><<<gF, 256>>>(x2, W1, b1, nullptr, hbuf, MTOK, FFDIM, DDIM);
    sgemm_kernel<2><<<gD, 256>>>(hbuf, W2, b2, x2, x3, MTOK, DDIM, FFDIM);

    // LN2 -> output
    ln_kernel<<<MTOK, 256>>>(x3, g2, beta2, out);
}

// round 4
// speedup vs baseline: 1.5884x; 1.5884x over previous
#include <cuda_runtime.h>
#include <math.h>
#include <cstdint>

// ---------------------------------------------------------------------------
// Transformer block. GEMMs via mma.sync tf32 (baseline PTX, legacy tensor
// pipe). Attention fp32. M=4096, D=1024, H=16, hd=64, FF=4096.
// ---------------------------------------------------------------------------

#define MTOK 4096
#define DDIM 1024
#define FFDIM 4096
#define NHEAD 16
#define HDIM 64
#define SEQ 2048
#define BATCH 2

#define OFF_Q    ((size_t)0)
#define OFF_K    (OFF_Q   + (size_t)MTOK*DDIM)
#define OFF_V    (OFF_K   + (size_t)MTOK*DDIM)
#define OFF_ATT  (OFF_V   + (size_t)MTOK*DDIM)
#define OFF_X1   (OFF_ATT + (size_t)MTOK*DDIM)
#define OFF_X2   (OFF_X1  + (size_t)MTOK*DDIM)
#define OFF_X3   (OFF_X2  + (size_t)MTOK*DDIM)
#define OFF_H    (OFF_X3  + (size_t)MTOK*DDIM)
#define OFF_WQT  (OFF_H   + (size_t)MTOK*FFDIM)
#define OFF_WKT  (OFF_WQT + (size_t)DDIM*DDIM)
#define OFF_WVT  (OFF_WKT + (size_t)DDIM*DDIM)
#define OFF_WOT  (OFF_WVT + (size_t)DDIM*DDIM)
#define OFF_W1T  (OFF_WOT + (size_t)DDIM*DDIM)
#define OFF_W2T  (OFF_W1T + (size_t)DDIM*FFDIM)
#define SCRATCH_FLOATS (OFF_W2T + (size_t)FFDIM*DDIM)

__device__ float g_scratch[SCRATCH_FLOATS];

// ---------------- PTX helpers (baseline compute_103 compatible) ------------
__device__ __forceinline__ void cp_async16(uint32_t dst, const void* src) {
    asm volatile("cp.async.cg.shared.global [%0], [%1], 16;"
                 :: "r"(dst), "l"(src) : "memory");
}
__device__ __forceinline__ void cp_commit() {
    asm volatile("cp.async.commit_group;" ::: "memory");
}
__device__ __forceinline__ void cp_wait0() {
    asm volatile("cp.async.wait_group 0;" ::: "memory");
}
__device__ __forceinline__ uint32_t smem_u32(const void* p) {
    uint32_t a;
    asm("{ .reg .u64 t; cvta.to.shared.u64 t, %1; cvt.u32.u64 %0, t; }"
        : "=r"(a) : "l"(p));
    return a;
}
__device__ __forceinline__ uint32_t f2tf32(float v) {
    uint32_t r;
    asm("cvt.rna.tf32.f32 %0, %1;" : "=r"(r) : "f"(v));
    return r;
}
__device__ __forceinline__ void mma_tf32(float* c, const uint32_t* a,
                                         const uint32_t* b) {
    asm volatile(
        "mma.sync.aligned.m16n8k8.row.col.f32.tf32.tf32.f32 "
        "{%0,%1,%2,%3}, {%4,%5,%6,%7}, {%8,%9}, {%0,%1,%2,%3};"
        : "+f"(c[0]), "+f"(c[1]), "+f"(c[2]), "+f"(c[3])
        : "r"(a[0]), "r"(a[1]), "r"(a[2]), "r"(a[3]), "r"(b[0]), "r"(b[1]));
}

// ---------------------------------------------------------------------------
// tf32 GEMM: C[M,N] = A[M,K] @ Bt[N,K]^T + bias (+ epilogue)
// EPI: 0 bias, 1 bias+exact GELU, 2 bias+residual.
// CTA tile 128x128, BK=32, double-buffered cp.async, 8 warps (2x4), each
// warp 64x32 via 4x4 grid of m16n8k8 tf32 mma.
// ---------------------------------------------------------------------------
#define BM 128
#define BN 128
#define BK 32
#define LDA 36           // padded row (floats) -> conflict-free frag loads
#define TILE_F (128 * LDA)
#define GT_SMEM (4 * TILE_F * 4)   // 2 bufs * (A+B) * 128*36 floats

template <int EPI>
__global__ __launch_bounds__(256)
void gemm_tc(const float* __restrict__ A, const float* __restrict__ Bt,
             const float* __restrict__ bias, const float* __restrict__ res,
             float* __restrict__ C, int M, int N, int K)
{
    extern __shared__ float smf[];
    float* As = smf;                 // [2][128][LDA]
    float* Bs = smf + 2 * TILE_F;    // [2][128][LDA]
    const uint32_t As_u = smem_u32(As);
    const uint32_t Bs_u = smem_u32(Bs);

    const int tid  = threadIdx.x;
    const int warp = tid >> 5;
    const int lane = tid & 31;
    const int g    = lane >> 2;      // group id 0..7
    const int t4   = lane & 3;       // thread in group 0..3
    const int wm   = warp >> 2;      // 0..1 (64 rows each)
    const int wn   = warp & 3;       // 0..3 (32 cols each)

    const int m0 = blockIdx.y * BM;
    const int n0 = blockIdx.x * BN;

    // Tile fetch: 128 rows x 32 floats = 1024 float4; 256 threads x 4 float4.
    // row = tid>>1, thread covers 4 consecutive float4: cols (tid&1)*16..+15.
    const int ldrow = tid >> 1;            // 0..127
    const int ldoff = (tid & 1) * 16;      // float offset 0 or 16
    const float* Ag = A  + (size_t)(m0 + ldrow) * K + ldoff;
    const float* Bg = Bt + (size_t)(n0 + ldrow) * K + ldoff;
    const uint32_t Asm = As_u + (uint32_t)(ldrow * LDA + ldoff) * 4;
    const uint32_t Bsm = Bs_u + (uint32_t)(ldrow * LDA + ldoff) * 4;

    float acc[4][4][4];
#pragma unroll
    for (int mi = 0; mi < 4; mi++)
#pragma unroll
        for (int ni = 0; ni < 4; ni++)
#pragma unroll
            for (int r = 0; r < 4; r++) acc[mi][ni][r] = 0.0f;

    const int T = K >> 5;

    // prologue: buffer 0
#pragma unroll
    for (int h = 0; h < 4; h++) {
        cp_async16(Asm + h * 16, Ag + h * 4);
        cp_async16(Bsm + h * 16, Bg + h * 4);
    }
    cp_commit();

    for (int tb = 0; tb < T; tb++) {
        const int b = tb & 1;
        cp_wait0();
        __syncthreads();

        if (tb + 1 < T) {
            const uint32_t so = (uint32_t)((b ^ 1) * TILE_F) * 4;
            const size_t ko = (size_t)(tb + 1) * BK;
#pragma unroll
            for (int h = 0; h < 4; h++) {
                cp_async16(Asm + so + h * 16, Ag + ko + h * 4);
                cp_async16(Bsm + so + h * 16, Bg + ko + h * 4);
            }
            cp_commit();
        }

        const float* a  = As + b * TILE_F + (wm * 64) * LDA;
        const float* bb = Bs + b * TILE_F + (wn * 32) * LDA;
#pragma unroll
        for (int kk = 0; kk < 4; kk++) {
            const int kb = kk * 8 + t4;
            uint32_t af[4][4], bf[4][2];
#pragma unroll
            for (int mi = 0; mi < 4; mi++) {
                const float* p = a + (mi * 16 + g) * LDA + kb;
                af[mi][0] = f2tf32(p[0]);
                af[mi][1] = f2tf32(p[8 * LDA]);
                af[mi][2] = f2tf32(p[4]);
                af[mi][3] = f2tf32(p[8 * LDA + 4]);
            }
#pragma unroll
            for (int ni = 0; ni < 4; ni++) {
                const float* p = bb + (ni * 8 + g) * LDA + kb;
                bf[ni][0] = f2tf32(p[0]);
                bf[ni][1] = f2tf32(p[4]);
            }
#pragma unroll
            for (int mi = 0; mi < 4; mi++)
#pragma unroll
                for (int ni = 0; ni < 4; ni++)
                    mma_tf32(acc[mi][ni], af[mi], bf[ni]);
        }
        __syncthreads();
    }

    // ---------------- epilogue ----------------
#pragma unroll
    for (int mi = 0; mi < 4; mi++) {
        const int row0 = m0 + wm * 64 + mi * 16 + g;
#pragma unroll
        for (int ni = 0; ni < 4; ni++) {
            const int col = n0 + wn * 32 + ni * 8 + t4 * 2;
            const float b0 = bias[col], b1 = bias[col + 1];
            float v0 = acc[mi][ni][0] + b0;
            float v1 = acc[mi][ni][1] + b1;
            float v2 = acc[mi][ni][2] + b0;
            float v3 = acc[mi][ni][3] + b1;
            if (EPI == 1) {
                v0 = 0.5f * v0 * (1.0f + erff(v0 * 0.70710678118654752f));
                v1 = 0.5f * v1 * (1.0f + erff(v1 * 0.70710678118654752f));
                v2 = 0.5f * v2 * (1.0f + erff(v2 * 0.70710678118654752f));
                v3 = 0.5f * v3 * (1.0f + erff(v3 * 0.70710678118654752f));
            } else if (EPI == 2) {
                const float2 r0 = *(const float2*)(res + (size_t)row0 * N + col);
                const float2 r1 = *(const float2*)(res + (size_t)(row0 + 8) * N + col);
                v0 += r0.x; v1 += r0.y; v2 += r1.x; v3 += r1.y;
            }
            *(float2*)(C + (size_t)row0 * N + col) = make_float2(v0, v1);
            *(float2*)(C + (size_t)(row0 + 8) * N + col) = make_float2(v2, v3);
        }
    }
}

// ---------------------------------------------------------------------------
// Transpose: out[C,R] = in[R,C]^T
// ---------------------------------------------------------------------------
__global__ __launch_bounds__(256)
void transpose_kernel(const float* __restrict__ in, float* __restrict__ out,
                      int R, int C)
{
    __shared__ float t[32][33];
    const int c0 = blockIdx.x * 32, r0 = blockIdx.y * 32;
    const int tx = threadIdx.x & 31, ty = threadIdx.x >> 5;
#pragma unroll
    for (int i = ty; i < 32; i += 8)
        t[i][tx] = in[(size_t)(r0 + i) * C + c0 + tx];
    __syncthreads();
#pragma unroll
    for (int i = ty; i < 32; i += 8)
        out[(size_t)(c0 + i) * R + r0 + tx] = t[tx][i];
}

// ---------------------------------------------------------------------------
// Flash attention (fp32, no scaling): one thread per query row.
// ---------------------------------------------------------------------------
#define AT_ROWS 128
#define KT 32

__global__ __launch_bounds__(AT_ROWS)
void attn_kernel(const float* __restrict__ Q, const float* __restrict__ K,
                 const float* __restrict__ V, float* __restrict__ O)
{
    const int b = blockIdx.z;
    const int h = blockIdx.y;
    const int qr = blockIdx.x * AT_ROWS + threadIdx.x;

    __shared__ float ks[KT][HDIM];
    __shared__ float vs[KT][HDIM];

    const size_t rowbase = (size_t)b * SEQ;
    const float* qp = Q + (rowbase + qr) * DDIM + h * HDIM;

    float4 qv[HDIM / 4];
    float4 ov[HDIM / 4];
#pragma unroll
    for (int d = 0; d < HDIM / 4; d++) {
        qv[d] = ((const float4*)qp)[d];
        ov[d] = make_float4(0.f, 0.f, 0.f, 0.f);
    }
    float m = -1e30f, l = 0.0f;

    const float* Kbase = K + rowbase * DDIM + h * HDIM;
    const float* Vbase = V + rowbase * DDIM + h * HDIM;

    for (int kt = 0; kt < SEQ; kt += KT) {
        __syncthreads();
        for (int i = threadIdx.x; i < KT * (HDIM / 4); i += AT_ROWS) {
            const int r = i / (HDIM / 4);
            const int c = i % (HDIM / 4);
            ((float4*)ks[r])[c] = ((const float4*)(Kbase + (size_t)(kt + r) * DDIM))[c];
            ((float4*)vs[r])[c] = ((const float4*)(Vbase + (size_t)(kt + r) * DDIM))[c];
        }
        __syncthreads();

        float s[KT];
        float tmax = m;
#pragma unroll
        for (int j = 0; j < KT; j++) {
            const float4* kp = (const float4*)ks[j];
            float acc = 0.0f;
#pragma unroll
            for (int d = 0; d < HDIM / 4; d++) {
                float4 kk = kp[d];
                acc = fmaf(qv[d].x, kk.x, acc);
                acc = fmaf(qv[d].y, kk.y, acc);
                acc = fmaf(qv[d].z, kk.z, acc);
                acc = fmaf(qv[d].w, kk.w, acc);
            }
            s[j] = acc;
            tmax = fmaxf(tmax, acc);
        }

        const float scale = __expf(m - tmax);
        l *= scale;
#pragma unroll
        for (int d = 0; d < HDIM / 4; d++) {
            ov[d].x *= scale; ov[d].y *= scale;
            ov[d].z *= scale; ov[d].w *= scale;
        }
        m = tmax;

#pragma unroll
        for (int j = 0; j < KT; j++) {
            const float p = __expf(s[j] - m);
            l += p;
            const float4* vp = (const float4*)vs[j];
#pragma unroll
            for (int d = 0; d < HDIM / 4; d++) {
                float4 vvv = vp[d];
                ov[d].x = fmaf(p, vvv.x, ov[d].x);
                ov[d].y = fmaf(p, vvv.y, ov[d].y);
                ov[d].z = fmaf(p, vvv.z, ov[d].z);
                ov[d].w = fmaf(p, vvv.w, ov[d].w);
            }
        }
    }

    const float inv = 1.0f / l;
    float* op = O + (rowbase + qr) * DDIM + h * HDIM;
#pragma unroll
    for (int d = 0; d < HDIM / 4; d++) {
        float4 o4 = ov[d];
        o4.x *= inv; o4.y *= inv; o4.z *= inv; o4.w *= inv;
        ((float4*)op)[d] = o4;
    }
}

// ---------------------------------------------------------------------------
// LayerNorm over last dim (D=1024), one block per row, 256 threads.
// ---------------------------------------------------------------------------
__global__ __launch_bounds__(256)
void ln_kernel(const float* __restrict__ x, const float* __restrict__ g,
               const float* __restrict__ b, float* __restrict__ y)
{
    const int D = DDIM;
    const int row = blockIdx.x;
    const float* xr = x + (size_t)row * D;

    float v[4];
    float s = 0.f, s2 = 0.f;
#pragma unroll
    for (int i = 0; i < 4; i++) {
        v[i] = xr[threadIdx.x + i * 256];
        s += v[i];
        s2 = fmaf(v[i], v[i], s2);
    }
#pragma unroll
    for (int o = 16; o > 0; o >>= 1) {
        s  += __shfl_xor_sync(0xffffffffu, s, o);
        s2 += __shfl_xor_sync(0xffffffffu, s2, o);
    }
    __shared__ float ss[8], ss2[8];
    const int w = threadIdx.x >> 5;
    if ((threadIdx.x & 31) == 0) { ss[w] = s; ss2[w] = s2; }
    __syncthreads();
    if (threadIdx.x < 32) {
        s  = (threadIdx.x < 8) ? ss[threadIdx.x]  : 0.f;
        s2 = (threadIdx.x < 8) ? ss2[threadIdx.x] : 0.f;
#pragma unroll
        for (int o = 4; o > 0; o >>= 1) {
            s  += __shfl_xor_sync(0xffffffffu, s, o);
            s2 += __shfl_xor_sync(0xffffffffu, s2, o);
        }
        if (threadIdx.x == 0) { ss[0] = s; ss2[0] = s2; }
    }
    __syncthreads();
    const float mu  = ss[0] * (1.0f / D);
    const float var = ss2[0] * (1.0f / D) - mu * mu;
    const float inv = rsqrtf(var + 1e-5f);
#pragma unroll
    for (int i = 0; i < 4; i++) {
        const int c = threadIdx.x + i * 256;
        y[(size_t)row * D + c] = (v[i] - mu) * inv * g[c] + b[c];
    }
}

// ---------------------------------------------------------------------------
// Launch
// ---------------------------------------------------------------------------
extern "C" void kernel_launch(void* const* d_in, const int* in_sizes, int n_in,
                              void* d_out, int out_size)
{
    (void)in_sizes; (void)n_in; (void)out_size;
    const float* x     = (const float*)d_in[0];
    const float* Wq    = (const float*)d_in[1];
    const float* bq    = (const float*)d_in[2];
    const float* Wk    = (const float*)d_in[3];
    const float* bk    = (const float*)d_in[4];
    const float* Wv    = (const float*)d_in[5];
    const float* bv    = (const float*)d_in[6];
    const float* Wo    = (const float*)d_in[7];
    const float* bo    = (const float*)d_in[8];
    const float* W1    = (const float*)d_in[9];
    const float* b1    = (const float*)d_in[10];
    const float* W2    = (const float*)d_in[11];
    const float* b2    = (const float*)d_in[12];
    const float* g1    = (const float*)d_in[13];
    const float* beta1 = (const float*)d_in[14];
    const float* g2    = (const float*)d_in[15];
    const float* beta2 = (const float*)d_in[16];
    float* out = (float*)d_out;

    float* scr = nullptr;
    cudaGetSymbolAddress((void**)&scr, g_scratch);
    float* q    = scr + OFF_Q;
    float* k    = scr + OFF_K;
    float* v    = scr + OFF_V;
    float* att  = scr + OFF_ATT;
    float* x1   = scr + OFF_X1;
    float* x2   = scr + OFF_X2;
    float* x3   = scr + OFF_X3;
    float* hbuf = scr + OFF_H;
    float* WqT  = scr + OFF_WQT;
    float* WkT  = scr + OFF_WKT;
    float* WvT  = scr + OFF_WVT;
    float* WoT  = scr + OFF_WOT;
    float* W1T  = scr + OFF_W1T;
    float* W2T  = scr + OFF_W2T;

    cudaFuncSetAttribute(gemm_tc<0>, cudaFuncAttributeMaxDynamicSharedMemorySize, GT_SMEM);
    cudaFuncSetAttribute(gemm_tc<1>, cudaFuncAttributeMaxDynamicSharedMemorySize, GT_SMEM);
    cudaFuncSetAttribute(gemm_tc<2>, cudaFuncAttributeMaxDynamicSharedMemorySize, GT_SMEM);

    // Weight transposes -> K-major B operands
    transpose_kernel<<<dim3(DDIM / 32, DDIM / 32), 256>>>(Wq, WqT, DDIM, DDIM);
    transpose_kernel<<<dim3(DDIM / 32, DDIM / 32), 256>>>(Wk, WkT, DDIM, DDIM);
    transpose_kernel<<<dim3(DDIM / 32, DDIM / 32), 256>>>(Wv, WvT, DDIM, DDIM);
    transpose_kernel<<<dim3(DDIM / 32, DDIM / 32), 256>>>(Wo, WoT, DDIM, DDIM);
    transpose_kernel<<<dim3(FFDIM / 32, DDIM / 32), 256>>>(W1, W1T, DDIM, FFDIM);
    transpose_kernel<<<dim3(DDIM / 32, FFDIM / 32), 256>>>(W2, W2T, FFDIM, DDIM);

    const dim3 gD(DDIM / 128, MTOK / 128);
    const dim3 gF(FFDIM / 128, MTOK / 128);

    // QKV projections
    gemm_tc<0><<<gD, 256, GT_SMEM>>>(x, WqT, bq, nullptr, q, MTOK, DDIM, DDIM);
    gemm_tc<0><<<gD, 256, GT_SMEM>>>(x, WkT, bk, nullptr, k, MTOK, DDIM, DDIM);
    gemm_tc<0><<<gD, 256, GT_SMEM>>>(x, WvT, bv, nullptr, v, MTOK, DDIM, DDIM);

    // Attention (no scaling)
    attn_kernel<<<dim3(SEQ / AT_ROWS, NHEAD, BATCH), AT_ROWS>>>(q, k, v, att);

    // Output projection + residual
    gemm_tc<2><<<gD, 256, GT_SMEM>>>(att, WoT, bo, x, x1, MTOK, DDIM, DDIM);

    // LN1
    ln_kernel<<<MTOK, 256>>>(x1, g1, beta1, x2);

    // FFN
    gemm_tc<1><<<gF, 256, GT_SMEM>>>(x2, W1T, b1, nullptr, hbuf, MTOK, FFDIM, DDIM);
    gemm_tc<2><<<gD, 256, GT_SMEM>>>(hbuf, W2T, b2, x2, x3, MTOK, DDIM, FFDIM);

    // LN2 -> output
    ln_kernel<<<MTOK, 256>>>(x3, g2, beta2, out);
}

// round 5
// speedup vs baseline: 2.4491x; 1.5418x over previous
#include <cuda_runtime.h>
#include <math.h>
#include <cstdint>

// ---------------------------------------------------------------------------
// Transformer block. GEMMs + attention via mma.sync tf32 (baseline PTX,
// legacy tensor pipe). M=4096, D=1024, H=16, hd=64, FF=4096.
// ---------------------------------------------------------------------------

#define MTOK 4096
#define DDIM 1024
#define FFDIM 4096
#define NHEAD 16
#define HDIM 64
#define SEQ 2048
#define BATCH 2

#define OFF_Q    ((size_t)0)
#define OFF_K    (OFF_Q   + (size_t)MTOK*DDIM)
#define OFF_V    (OFF_K   + (size_t)MTOK*DDIM)
#define OFF_ATT  (OFF_V   + (size_t)MTOK*DDIM)
#define OFF_X1   (OFF_ATT + (size_t)MTOK*DDIM)
#define OFF_X2   (OFF_X1  + (size_t)MTOK*DDIM)
#define OFF_X3   (OFF_X2  + (size_t)MTOK*DDIM)
#define OFF_H    (OFF_X3  + (size_t)MTOK*DDIM)
#define OFF_WQT  (OFF_H   + (size_t)MTOK*FFDIM)
#define OFF_WKT  (OFF_WQT + (size_t)DDIM*DDIM)
#define OFF_WVT  (OFF_WKT + (size_t)DDIM*DDIM)
#define OFF_WOT  (OFF_WVT + (size_t)DDIM*DDIM)
#define OFF_W1T  (OFF_WOT + (size_t)DDIM*DDIM)
#define OFF_W2T  (OFF_W1T + (size_t)DDIM*FFDIM)
#define SCRATCH_FLOATS (OFF_W2T + (size_t)FFDIM*DDIM)

__device__ float g_scratch[SCRATCH_FLOATS];

// ---------------- PTX helpers (baseline compute_103 compatible) ------------
__device__ __forceinline__ void cp_async16(uint32_t dst, const void* src) {
    asm volatile("cp.async.cg.shared.global [%0], [%1], 16;"
                 :: "r"(dst), "l"(src) : "memory");
}
__device__ __forceinline__ void cp_commit() {
    asm volatile("cp.async.commit_group;" ::: "memory");
}
__device__ __forceinline__ void cp_wait0() {
    asm volatile("cp.async.wait_group 0;" ::: "memory");
}
__device__ __forceinline__ void cp_wait1() {
    asm volatile("cp.async.wait_group 1;" ::: "memory");
}
__device__ __forceinline__ uint32_t smem_u32(const void* p) {
    uint32_t a;
    asm("{ .reg .u64 t; cvta.to.shared.u64 t, %1; cvt.u32.u64 %0, t; }"
        : "=r"(a) : "l"(p));
    return a;
}
__device__ __forceinline__ uint32_t f2tf32(float v) {
    uint32_t r;
    asm("cvt.rna.tf32.f32 %0, %1;" : "=r"(r) : "f"(v));
    return r;
}
__device__ __forceinline__ void mma_tf32(float* c, const uint32_t* a,
                                         const uint32_t* b) {
    asm volatile(
        "mma.sync.aligned.m16n8k8.row.col.f32.tf32.tf32.f32 "
        "{%0,%1,%2,%3}, {%4,%5,%6,%7}, {%8,%9}, {%0,%1,%2,%3};"
        : "+f"(c[0]), "+f"(c[1]), "+f"(c[2]), "+f"(c[3])
        : "r"(a[0]), "r"(a[1]), "r"(a[2]), "r"(a[3]), "r"(b[0]), "r"(b[1]));
}

// Fast exp on the FMA pipe (no MUFU): exp(x) = 2^(x*log2e), deg-5 poly on
// [-0.5, 0.5], exponent via int bit trick. x <= 0 in all call sites.
__device__ __forceinline__ float fexp(float x) {
    float t = x * 1.4426950408889634f;
    t = fmaxf(t, -126.0f);
    const float fn = rintf(t);
    const float f = t - fn;
    float p = 1.33336500e-3f;
    p = fmaf(p, f, 9.61823766e-3f);
    p = fmaf(p, f, 5.55041087e-2f);
    p = fmaf(p, f, 2.40226507e-1f);
    p = fmaf(p, f, 6.93147182e-1f);
    p = fmaf(p, f, 1.0f);
    const int n = (int)fn;
    return p * __int_as_float((n + 127) << 23);
}

// ---------------------------------------------------------------------------
// tf32 GEMM: C[M,N] = A[M,K] @ Bt[N,K]^T + bias (+ epilogue)
// EPI: 0 bias, 1 bias+exact GELU, 2 bias+residual.
// ---------------------------------------------------------------------------
#define BM 128
#define BN 128
#define BK 32
#define LDA 36
#define TILE_F (128 * LDA)
#define GT_SMEM (4 * TILE_F * 4)

template <int EPI>
__global__ __launch_bounds__(256)
void gemm_tc(const float* __restrict__ A, const float* __restrict__ Bt,
             const float* __restrict__ bias, const float* __restrict__ res,
             float* __restrict__ C, int M, int N, int K)
{
    extern __shared__ float smf[];
    float* As = smf;
    float* Bs = smf + 2 * TILE_F;
    const uint32_t As_u = smem_u32(As);
    const uint32_t Bs_u = smem_u32(Bs);

    const int tid  = threadIdx.x;
    const int warp = tid >> 5;
    const int lane = tid & 31;
    const int g    = lane >> 2;
    const int t4   = lane & 3;
    const int wm   = warp >> 2;
    const int wn   = warp & 3;

    const int m0 = blockIdx.y * BM;
    const int n0 = blockIdx.x * BN;

    const int ldrow = tid >> 1;
    const int ldoff = (tid & 1) * 16;
    const float* Ag = A  + (size_t)(m0 + ldrow) * K + ldoff;
    const float* Bg = Bt + (size_t)(n0 + ldrow) * K + ldoff;
    const uint32_t Asm = As_u + (uint32_t)(ldrow * LDA + ldoff) * 4;
    const uint32_t Bsm = Bs_u + (uint32_t)(ldrow * LDA + ldoff) * 4;

    float acc[4][4][4];
#pragma unroll
    for (int mi = 0; mi < 4; mi++)
#pragma unroll
        for (int ni = 0; ni < 4; ni++)
#pragma unroll
            for (int r = 0; r < 4; r++) acc[mi][ni][r] = 0.0f;

    const int T = K >> 5;

#pragma unroll
    for (int h = 0; h < 4; h++) {
        cp_async16(Asm + h * 16, Ag + h * 4);
        cp_async16(Bsm + h * 16, Bg + h * 4);
    }
    cp_commit();

    for (int tb = 0; tb < T; tb++) {
        const int b = tb & 1;
        cp_wait0();
        __syncthreads();

        if (tb + 1 < T) {
            const uint32_t so = (uint32_t)((b ^ 1) * TILE_F) * 4;
            const size_t ko = (size_t)(tb + 1) * BK;
#pragma unroll
            for (int h = 0; h < 4; h++) {
                cp_async16(Asm + so + h * 16, Ag + ko + h * 4);
                cp_async16(Bsm + so + h * 16, Bg + ko + h * 4);
            }
            cp_commit();
        }

        const float* a  = As + b * TILE_F + (wm * 64) * LDA;
        const float* bb = Bs + b * TILE_F + (wn * 32) * LDA;
#pragma unroll
        for (int kk = 0; kk < 4; kk++) {
            const int kb = kk * 8 + t4;
            uint32_t af[4][4], bf[4][2];
#pragma unroll
            for (int mi = 0; mi < 4; mi++) {
                const float* p = a + (mi * 16 + g) * LDA + kb;
                af[mi][0] = f2tf32(p[0]);
                af[mi][1] = f2tf32(p[8 * LDA]);
                af[mi][2] = f2tf32(p[4]);
                af[mi][3] = f2tf32(p[8 * LDA + 4]);
            }
#pragma unroll
            for (int ni = 0; ni < 4; ni++) {
                const float* p = bb + (ni * 8 + g) * LDA + kb;
                bf[ni][0] = f2tf32(p[0]);
                bf[ni][1] = f2tf32(p[4]);
            }
#pragma unroll
            for (int mi = 0; mi < 4; mi++)
#pragma unroll
                for (int ni = 0; ni < 4; ni++)
                    mma_tf32(acc[mi][ni], af[mi], bf[ni]);
        }
        __syncthreads();
    }

#pragma unroll
    for (int mi = 0; mi < 4; mi++) {
        const int row0 = m0 + wm * 64 + mi * 16 + g;
#pragma unroll
        for (int ni = 0; ni < 4; ni++) {
            const int col = n0 + wn * 32 + ni * 8 + t4 * 2;
            const float b0 = bias[col], b1 = bias[col + 1];
            float v0 = acc[mi][ni][0] + b0;
            float v1 = acc[mi][ni][1] + b1;
            float v2 = acc[mi][ni][2] + b0;
            float v3 = acc[mi][ni][3] + b1;
            if (EPI == 1) {
                v0 = 0.5f * v0 * (1.0f + erff(v0 * 0.70710678118654752f));
                v1 = 0.5f * v1 * (1.0f + erff(v1 * 0.70710678118654752f));
                v2 = 0.5f * v2 * (1.0f + erff(v2 * 0.70710678118654752f));
                v3 = 0.5f * v3 * (1.0f + erff(v3 * 0.70710678118654752f));
            } else if (EPI == 2) {
                const float2 r0 = *(const float2*)(res + (size_t)row0 * N + col);
                const float2 r1 = *(const float2*)(res + (size_t)(row0 + 8) * N + col);
                v0 += r0.x; v1 += r0.y; v2 += r1.x; v3 += r1.y;
            }
            *(float2*)(C + (size_t)row0 * N + col) = make_float2(v0, v1);
            *(float2*)(C + (size_t)(row0 + 8) * N + col) = make_float2(v2, v3);
        }
    }
}

// ---------------------------------------------------------------------------
// Transpose: out[C,R] = in[R,C]^T
// ---------------------------------------------------------------------------
__global__ __launch_bounds__(256)
void transpose_kernel(const float* __restrict__ in, float* __restrict__ out,
                      int R, int C)
{
    __shared__ float t[32][33];
    const int c0 = blockIdx.x * 32, r0 = blockIdx.y * 32;
    const int tx = threadIdx.x & 31, ty = threadIdx.x >> 5;
#pragma unroll
    for (int i = ty; i < 32; i += 8)
        t[i][tx] = in[(size_t)(r0 + i) * C + c0 + tx];
    __syncthreads();
#pragma unroll
    for (int i = ty; i < 32; i += 8)
        out[(size_t)(c0 + i) * R + r0 + tx] = t[tx][i];
}

// ---------------------------------------------------------------------------
// Tensor-core flash attention (tf32 mma, fp32 softmax, no scaling).
// CTA: 128 q-rows x one head. 8 warps x 16 q-rows. 16 iters of 128 keys.
// ---------------------------------------------------------------------------
#define LDK 68    // K tile stride (floats): bank = 4g+t4, conflict-free
#define LDV 72    // V tile stride: bank = 8t4+g, conflict-free
#define LDP 132   // P tile stride: bank = 4g+t4, conflict-free
#define NKB (SEQ / 128)

#define AT_SMEM_FLOATS (128*LDP + 2*128*LDK + 2*128*LDV)
#define AT_SMEM ((AT_SMEM_FLOATS) * 4)   // 210,944 bytes

__global__ __launch_bounds__(256)
void attn_tc_kernel(const float* __restrict__ Q, const float* __restrict__ K,
                    const float* __restrict__ V, float* __restrict__ O)
{
    extern __shared__ float sm[];
    float* sP = sm;                       // [128][LDP] (also Q staging)
    float* sK = sm + 128 * LDP;           // [2][128][LDK]
    float* sV = sK + 2 * 128 * LDK;       // [2][128][LDV]
    const uint32_t sK_u = smem_u32(sK);
    const uint32_t sV_u = smem_u32(sV);

    const int bz   = blockIdx.z;
    const int h    = blockIdx.y;
    const int q0   = blockIdx.x * 128;
    const int tid  = threadIdx.x;
    const int warp = tid >> 5;
    const int lane = tid & 31;
    const int g    = lane >> 2;
    const int t4   = lane & 3;

    const size_t base = (size_t)bz * SEQ;
    const float* Qg = Q + (base + q0) * DDIM + h * HDIM;
    const float* Kg = K + base * DDIM + h * HDIM;
    const float* Vg = V + base * DDIM + h * HDIM;

    // ---- stage Q tile into sP (stride LDK) and build A-fragments ----
    for (int i = tid; i < 128 * 16; i += 256) {
        const int r = i >> 4, c = (i & 15) * 4;
        *(float4*)&sP[r * LDK + c] = *(const float4*)(Qg + (size_t)r * DDIM + c);
    }
    __syncthreads();

    uint32_t qf[8][4];
    {
        const float* qrow = sP + (warp * 16 + g) * LDK + t4;
#pragma unroll
        for (int ks = 0; ks < 8; ks++) {
            qf[ks][0] = f2tf32(qrow[ks * 8]);
            qf[ks][1] = f2tf32(qrow[8 * LDK + ks * 8]);
            qf[ks][2] = f2tf32(qrow[ks * 8 + 4]);
            qf[ks][3] = f2tf32(qrow[8 * LDK + ks * 8 + 4]);
        }
    }
    __syncthreads();

    float oacc[8][4];
#pragma unroll
    for (int n = 0; n < 8; n++)
#pragma unroll
        for (int r = 0; r < 4; r++) oacc[n][r] = 0.0f;
    float m0 = -1e30f, m1 = -1e30f, l0 = 0.0f, l1 = 0.0f;

    // ---- K/V tile loader (cp.async, 16B) ----
    const int ldr = tid >> 1;             // row 0..127
    const int ldc = (tid & 1) * 8;        // float col 0 or 8 (two float4 each)
    // each thread: rows {ldr}, cols [ldc, ldc+8) via 2 float4 per tile... ->
    // total per tile: 128 rows x 16 float4 = 2048; 256 thr x 8 = 2048.

    // prologue: tiles for kb=0 into buffer 0
#pragma unroll
    for (int i = 0; i < 8; i++) {
        const int idx = tid + i * 256;
        const int r = idx >> 4, c = (idx & 15) * 4;
        cp_async16(sK_u + (uint32_t)(r * LDK + c) * 4, Kg + (size_t)r * DDIM + c);
        cp_async16(sV_u + (uint32_t)(r * LDV + c) * 4, Vg + (size_t)r * DDIM + c);
    }
    cp_commit();
    (void)ldr; (void)ldc;

    for (int kb = 0; kb < NKB; kb++) {
        const int buf = kb & 1;

        if (kb + 1 < NKB) {
            const float* Kt = Kg + (size_t)(kb + 1) * 128 * DDIM;
            const float* Vt = Vg + (size_t)(kb + 1) * 128 * DDIM;
            const uint32_t ko = (uint32_t)((buf ^ 1) * 128 * LDK) * 4;
            const uint32_t vo = (uint32_t)((buf ^ 1) * 128 * LDV) * 4;
#pragma unroll
            for (int i = 0; i < 8; i++) {
                const int idx = tid + i * 256;
                const int r = idx >> 4, c = (idx & 15) * 4;
                cp_async16(sK_u + ko + (uint32_t)(r * LDK + c) * 4,
                           Kt + (size_t)r * DDIM + c);
                cp_async16(sV_u + vo + (uint32_t)(r * LDV + c) * 4,
                           Vt + (size_t)r * DDIM + c);
            }
            cp_commit();
            cp_wait1();
        } else {
            cp_wait0();
        }
        __syncthreads();

        // ---- S = Q @ K^T  (per warp: 16 x 128) ----
        float sc[16][4];
#pragma unroll
        for (int nt = 0; nt < 16; nt++) {
#pragma unroll
            for (int r = 0; r < 4; r++) sc[nt][r] = 0.0f;
        }
        const float* kbase = sK + buf * 128 * LDK;
#pragma unroll
        for (int nt = 0; nt < 16; nt++) {
            const float* kp = kbase + (nt * 8 + g) * LDK + t4;
#pragma unroll
            for (int ks = 0; ks < 8; ks++) {
                uint32_t bf[2];
                bf[0] = f2tf32(kp[ks * 8]);
                bf[1] = f2tf32(kp[ks * 8 + 4]);
                mma_tf32(sc[nt], qf[ks], bf);
            }
        }

        // ---- online softmax ----
        float mx0 = m0, mx1 = m1;
#pragma unroll
        for (int nt = 0; nt < 16; nt++) {
            mx0 = fmaxf(mx0, fmaxf(sc[nt][0], sc[nt][1]));
            mx1 = fmaxf(mx1, fmaxf(sc[nt][2], sc[nt][3]));
        }
        mx0 = fmaxf(mx0, __shfl_xor_sync(0xffffffffu, mx0, 1));
        mx0 = fmaxf(mx0, __shfl_xor_sync(0xffffffffu, mx0, 2));
        mx1 = fmaxf(mx1, __shfl_xor_sync(0xffffffffu, mx1, 1));
        mx1 = fmaxf(mx1, __shfl_xor_sync(0xffffffffu, mx1, 2));

        const float s0 = fexp(m0 - mx0);
        const float s1 = fexp(m1 - mx1);
        m0 = mx0; m1 = mx1;
        l0 *= s0;  l1 *= s1;
#pragma unroll
        for (int n = 0; n < 8; n++) {
            oacc[n][0] *= s0; oacc[n][1] *= s0;
            oacc[n][2] *= s1; oacc[n][3] *= s1;
        }

        const int prow = warp * 16 + g;
        float ls0 = 0.0f, ls1 = 0.0f;
#pragma unroll
        for (int nt = 0; nt < 16; nt++) {
            const float p0 = fexp(sc[nt][0] - mx0);
            const float p1 = fexp(sc[nt][1] - mx0);
            const float p2 = fexp(sc[nt][2] - mx1);
            const float p3 = fexp(sc[nt][3] - mx1);
            ls0 += p0 + p1;
            ls1 += p2 + p3;
            const int col = nt * 8 + 2 * t4;
            *(float2*)&sP[prow * LDP + col] = make_float2(p0, p1);
            *(float2*)&sP[(prow + 8) * LDP + col] = make_float2(p2, p3);
        }
        l0 += ls0; l1 += ls1;
        __syncthreads();

        // ---- O += P @ V  (per warp: 16 x 64, k = 128 keys) ----
        const float* vbase = sV + buf * 128 * LDV;
        const float* prow_p = sP + prow * LDP + t4;
#pragma unroll
        for (int ks = 0; ks < 16; ks++) {
            uint32_t af[4];
            af[0] = f2tf32(prow_p[ks * 8]);
            af[1] = f2tf32(prow_p[8 * LDP + ks * 8]);
            af[2] = f2tf32(prow_p[ks * 8 + 4]);
            af[3] = f2tf32(prow_p[8 * LDP + ks * 8 + 4]);
            const float* vp = vbase + (ks * 8 + t4) * LDV + g;
#pragma unroll
            for (int nt = 0; nt < 8; nt++) {
                uint32_t bf[2];
                bf[0] = f2tf32(vp[nt * 8]);
                bf[1] = f2tf32(vp[4 * LDV + nt * 8]);
                mma_tf32(oacc[nt], af, bf);
            }
        }
        __syncthreads();
    }

    // ---- finalize: row sums across quad, normalize, write ----
    l0 += __shfl_xor_sync(0xffffffffu, l0, 1);
    l0 += __shfl_xor_sync(0xffffffffu, l0, 2);
    l1 += __shfl_xor_sync(0xffffffffu, l1, 1);
    l1 += __shfl_xor_sync(0xffffffffu, l1, 2);
    const float inv0 = 1.0f / l0;
    const float inv1 = 1.0f / l1;

    const size_t row = base + q0 + warp * 16 + g;
    float* Og = O + row * DDIM + h * HDIM;
#pragma unroll
    for (int nt = 0; nt < 8; nt++) {
        const int col = nt * 8 + 2 * t4;
        *(float2*)(Og + col) =
            make_float2(oacc[nt][0] * inv0, oacc[nt][1] * inv0);
        *(float2*)(Og + 8 * DDIM + col) =
            make_float2(oacc[nt][2] * inv1, oacc[nt][3] * inv1);
    }
}

// ---------------------------------------------------------------------------
// LayerNorm over last dim (D=1024), one block per row, 256 threads.
// ---------------------------------------------------------------------------
__global__ __launch_bounds__(256)
void ln_kernel(const float* __restrict__ x, const float* __restrict__ g,
               const float* __restrict__ b, float* __restrict__ y)
{
    const int D = DDIM;
    const int row = blockIdx.x;
    const float* xr = x + (size_t)row * D;

    float v[4];
    float s = 0.f, s2 = 0.f;
#pragma unroll
    for (int i = 0; i < 4; i++) {
        v[i] = xr[threadIdx.x + i * 256];
        s += v[i];
        s2 = fmaf(v[i], v[i], s2);
    }
#pragma unroll
    for (int o = 16; o > 0; o >>= 1) {
        s  += __shfl_xor_sync(0xffffffffu, s, o);
        s2 += __shfl_xor_sync(0xffffffffu, s2, o);
    }
    __shared__ float ss[8], ss2[8];
    const int w = threadIdx.x >> 5;
    if ((threadIdx.x & 31) == 0) { ss[w] = s; ss2[w] = s2; }
    __syncthreads();
    if (threadIdx.x < 32) {
        s  = (threadIdx.x < 8) ? ss[threadIdx.x]  : 0.f;
        s2 = (threadIdx.x < 8) ? ss2[threadIdx.x] : 0.f;
#pragma unroll
        for (int o = 4; o > 0; o >>= 1) {
            s  += __shfl_xor_sync(0xffffffffu, s, o);
            s2 += __shfl_xor_sync(0xffffffffu, s2, o);
        }
        if (threadIdx.x == 0) { ss[0] = s; ss2[0] = s2; }
    }
    __syncthreads();
    const float mu  = ss[0] * (1.0f / D);
    const float var = ss2[0] * (1.0f / D) - mu * mu;
    const float inv = rsqrtf(var + 1e-5f);
#pragma unroll
    for (int i = 0; i < 4; i++) {
        const int c = threadIdx.x + i * 256;
        y[(size_t)row * D + c] = (v[i] - mu) * inv * g[c] + b[c];
    }
}

// ---------------------------------------------------------------------------
// Launch
// ---------------------------------------------------------------------------
extern "C" void kernel_launch(void* const* d_in, const int* in_sizes, int n_in,
                              void* d_out, int out_size)
{
    (void)in_sizes; (void)n_in; (void)out_size;
    const float* x     = (const float*)d_in[0];
    const float* Wq    = (const float*)d_in[1];
    const float* bq    = (const float*)d_in[2];
    const float* Wk    = (const float*)d_in[3];
    const float* bk    = (const float*)d_in[4];
    const float* Wv    = (const float*)d_in[5];
    const float* bv    = (const float*)d_in[6];
    const float* Wo    = (const float*)d_in[7];
    const float* bo    = (const float*)d_in[8];
    const float* W1    = (const float*)d_in[9];
    const float* b1    = (const float*)d_in[10];
    const float* W2    = (const float*)d_in[11];
    const float* b2    = (const float*)d_in[12];
    const float* g1    = (const float*)d_in[13];
    const float* beta1 = (const float*)d_in[14];
    const float* g2    = (const float*)d_in[15];
    const float* beta2 = (const float*)d_in[16];
    float* out = (float*)d_out;

    float* scr = nullptr;
    cudaGetSymbolAddress((void**)&scr, g_scratch);
    float* q    = scr + OFF_Q;
    float* k    = scr + OFF_K;
    float* v    = scr + OFF_V;
    float* att  = scr + OFF_ATT;
    float* x1   = scr + OFF_X1;
    float* x2   = scr + OFF_X2;
    float* x3   = scr + OFF_X3;
    float* hbuf = scr + OFF_H;
    float* WqT  = scr + OFF_WQT;
    float* WkT  = scr + OFF_WKT;
    float* WvT  = scr + OFF_WVT;
    float* WoT  = scr + OFF_WOT;
    float* W1T  = scr + OFF_W1T;
    float* W2T  = scr + OFF_W2T;

    cudaFuncSetAttribute(gemm_tc<0>, cudaFuncAttributeMaxDynamicSharedMemorySize, GT_SMEM);
    cudaFuncSetAttribute(gemm_tc<1>, cudaFuncAttributeMaxDynamicSharedMemorySize, GT_SMEM);
    cudaFuncSetAttribute(gemm_tc<2>, cudaFuncAttributeMaxDynamicSharedMemorySize, GT_SMEM);
    cudaFuncSetAttribute(attn_tc_kernel, cudaFuncAttributeMaxDynamicSharedMemorySize, AT_SMEM);

    // Weight transposes -> K-major B operands
    transpose_kernel<<<dim3(DDIM / 32, DDIM / 32), 256>>>(Wq, WqT, DDIM, DDIM);
    transpose_kernel<<<dim3(DDIM / 32, DDIM / 32), 256>>>(Wk, WkT, DDIM, DDIM);
    transpose_kernel<<<dim3(DDIM / 32, DDIM / 32), 256>>>(Wv, WvT, DDIM, DDIM);
    transpose_kernel<<<dim3(DDIM / 32, DDIM / 32), 256>>>(Wo, WoT, DDIM, DDIM);
    transpose_kernel<<<dim3(FFDIM / 32, DDIM / 32), 256>>>(W1, W1T, DDIM, FFDIM);
    transpose_kernel<<<dim3(DDIM / 32, FFDIM / 32), 256>>>(W2, W2T, FFDIM, DDIM);

    const dim3 gD(DDIM / 128, MTOK / 128);
    const dim3 gF(FFDIM / 128, MTOK / 128);

    // QKV projections
    gemm_tc<0><<<gD, 256, GT_SMEM>>>(x, WqT, bq, nullptr, q, MTOK, DDIM, DDIM);
    gemm_tc<0><<<gD, 256, GT_SMEM>>>(x, WkT, bk, nullptr, k, MTOK, DDIM, DDIM);
    gemm_tc<0><<<gD, 256, GT_SMEM>>>(x, WvT, bv, nullptr, v, MTOK, DDIM, DDIM);

    // Attention (tf32 tensor cores, no scaling)
    attn_tc_kernel<<<dim3(SEQ / 128, NHEAD, BATCH), 256, AT_SMEM>>>(q, k, v, att);

    // Output projection + residual
    gemm_tc<2><<<gD, 256, GT_SMEM>>>(att, WoT, bo, x, x1, MTOK, DDIM, DDIM);

    // LN1
    ln_kernel<<<MTOK, 256>>>(x1, g1, beta1, x2);

    // FFN
    gemm_tc<1><<<gF, 256, GT_SMEM>>>(x2, W1T, b1, nullptr, hbuf, MTOK, FFDIM, DDIM);
    gemm_tc<2><<<gD, 256, GT_SMEM>>>(hbuf, W2T, b2, x2, x3, MTOK, DDIM, FFDIM);

    // LN2 -> output
    ln_kernel<<<MTOK, 256>>>(x3, g2, beta2, out);
}

// round 7
// speedup vs baseline: 2.6928x; 1.0995x over previous
#include <cuda_runtime.h>
#include <math.h>
#include <cstdint>

// ---------------------------------------------------------------------------
// Transformer block. GEMMs + attention via mma.sync tf32.
// Weights pre-rounded to tf32 at transpose; activations rounded at frag load.
// M=4096, D=1024, H=16, hd=64, FF=4096.
// ---------------------------------------------------------------------------

#define MTOK 4096
#define DDIM 1024
#define QKVD 3072
#define FFDIM 4096
#define NHEAD 16
#define HDIM 64
#define SEQ 2048
#define BATCH 2

#define OFF_QKV  ((size_t)0)
#define OFF_ATT  (OFF_QKV  + (size_t)MTOK*QKVD)
#define OFF_X1   (OFF_ATT  + (size_t)MTOK*DDIM)
#define OFF_X2   (OFF_X1   + (size_t)MTOK*DDIM)
#define OFF_X3   (OFF_X2   + (size_t)MTOK*DDIM)
#define OFF_H    (OFF_X3   + (size_t)MTOK*DDIM)
#define OFF_WQKVT (OFF_H   + (size_t)MTOK*FFDIM)
#define OFF_WOT  (OFF_WQKVT + (size_t)QKVD*DDIM)
#define OFF_W1T  (OFF_WOT  + (size_t)DDIM*DDIM)
#define OFF_W2T  (OFF_W1T  + (size_t)DDIM*FFDIM)
#define OFF_BQKV (OFF_W2T  + (size_t)FFDIM*DDIM)
#define SCRATCH_FLOATS (OFF_BQKV + (size_t)QKVD)

__device__ float g_scratch[SCRATCH_FLOATS];

// ---------------- PTX helpers ----------------
__device__ __forceinline__ void cp_async16(uint32_t dst, const void* src) {
    asm volatile("cp.async.cg.shared.global [%0], [%1], 16;"
                 :: "r"(dst), "l"(src) : "memory");
}
__device__ __forceinline__ void cp_commit() {
    asm volatile("cp.async.commit_group;" ::: "memory");
}
__device__ __forceinline__ void cp_wait0() {
    asm volatile("cp.async.wait_group 0;" ::: "memory");
}
__device__ __forceinline__ void cp_wait1() {
    asm volatile("cp.async.wait_group 1;" ::: "memory");
}
__device__ __forceinline__ uint32_t smem_u32(const void* p) {
    uint32_t a;
    asm("{ .reg .u64 t; cvta.to.shared.u64 t, %1; cvt.u32.u64 %0, t; }"
        : "=r"(a) : "l"(p));
    return a;
}
__device__ __forceinline__ uint32_t f2tf32(float v) {
    uint32_t r;
    asm("cvt.rna.tf32.f32 %0, %1;" : "=r"(r) : "f"(v));
    return r;
}
__device__ __forceinline__ void mma_tf32(float* c, const uint32_t* a,
                                         const uint32_t* b) {
    asm volatile(
        "mma.sync.aligned.m16n8k8.row.col.f32.tf32.tf32.f32 "
        "{%0,%1,%2,%3}, {%4,%5,%6,%7}, {%8,%9}, {%0,%1,%2,%3};"
        : "+f"(c[0]), "+f"(c[1]), "+f"(c[2]), "+f"(c[3])
        : "r"(a[0]), "r"(a[1]), "r"(a[2]), "r"(a[3]), "r"(b[0]), "r"(b[1]));
}

// Fast exp on the FMA pipe (no MUFU).
__device__ __forceinline__ float fexp(float x) {
    float t = x * 1.4426950408889634f;
    t = fmaxf(t, -126.0f);
    const float fn = rintf(t);
    const float f = t - fn;
    float p = 1.33336500e-3f;
    p = fmaf(p, f, 9.61823766e-3f);
    p = fmaf(p, f, 5.55041087e-2f);
    p = fmaf(p, f, 2.40226507e-1f);
    p = fmaf(p, f, 6.93147182e-1f);
    p = fmaf(p, f, 1.0f);
    const int n = (int)fn;
    return p * __int_as_float((n + 127) << 23);
}

// ---------------------------------------------------------------------------
// tf32 GEMM: C[M,N] = A[M,K] @ Bt[N,K]^T + bias (+ epilogue)
// CTA tile 256x128, BK=32, 512 threads, double-buffered cp.async.
// A fragments rounded (cvt.rna); B (weights) pre-rounded at transpose.
// ---------------------------------------------------------------------------
#define BM 256
#define BN 128
#define BK 32
#define LDA 36
#define ATILE_F (256 * LDA)
#define BTILE_F (128 * LDA)
#define GT_SMEM ((2 * ATILE_F + 2 * BTILE_F) * 4)   // 110592 bytes

template <int EPI>
__global__ __launch_bounds__(512)
void gemm_tc(const float* __restrict__ A, const float* __restrict__ Bt,
             const float* __restrict__ bias, const float* __restrict__ res,
             float* __restrict__ C, int M, int N, int K)
{
    extern __shared__ float smf[];
    float* As = smf;                       // [2][256][LDA]
    float* Bs = smf + 2 * ATILE_F;         // [2][128][LDA]
    const uint32_t As_u = smem_u32(As);
    const uint32_t Bs_u = smem_u32(Bs);

    const int tid  = threadIdx.x;
    const int warp = tid >> 5;
    const int lane = tid & 31;
    const int g    = lane >> 2;
    const int t4   = lane & 3;
    const int wm   = warp >> 2;
    const int wn   = warp & 3;

    const int m0 = blockIdx.y * BM;
    const int n0 = blockIdx.x * BN;

    const int arow = tid >> 1;
    const int aoff = (tid & 1) * 16;
    const float* Ag = A + (size_t)(m0 + arow) * K + aoff;
    const uint32_t Asm = As_u + (uint32_t)(arow * LDA + aoff) * 4;
    const int brow = tid >> 2;
    const int boff = (tid & 3) * 8;
    const float* Bg = Bt + (size_t)(n0 + brow) * K + boff;
    const uint32_t Bsm = Bs_u + (uint32_t)(brow * LDA + boff) * 4;

    float acc[4][4][4];
#pragma unroll
    for (int mi = 0; mi < 4; mi++)
#pragma unroll
        for (int ni = 0; ni < 4; ni++)
#pragma unroll
            for (int r = 0; r < 4; r++) acc[mi][ni][r] = 0.0f;

    const int T = K >> 5;

#pragma unroll
    for (int h = 0; h < 4; h++) cp_async16(Asm + h * 16, Ag + h * 4);
#pragma unroll
    for (int h = 0; h < 2; h++) cp_async16(Bsm + h * 16, Bg + h * 4);
    cp_commit();

    for (int tb = 0; tb < T; tb++) {
        const int b = tb & 1;
        if (tb + 1 < T) {
            const uint32_t ao = (uint32_t)((b ^ 1) * ATILE_F) * 4;
            const uint32_t bo = (uint32_t)((b ^ 1) * BTILE_F) * 4;
            const size_t ko = (size_t)(tb + 1) * BK;
#pragma unroll
            for (int h = 0; h < 4; h++)
                cp_async16(Asm + ao + h * 16, Ag + ko + h * 4);
#pragma unroll
            for (int h = 0; h < 2; h++)
                cp_async16(Bsm + bo + h * 16, Bg + ko + h * 4);
            cp_commit();
            cp_wait1();
        } else {
            cp_wait0();
        }
        __syncthreads();

        const float*    a  = As + b * ATILE_F + (wm * 64) * LDA;
        const uint32_t* bb = (const uint32_t*)(Bs + b * BTILE_F + (wn * 32) * LDA);
#pragma unroll
        for (int kk = 0; kk < 4; kk++) {
            const int kb = kk * 8 + t4;
            uint32_t af[4][4], bf[4][2];
#pragma unroll
            for (int mi = 0; mi < 4; mi++) {
                const float* p = a + (mi * 16 + g) * LDA + kb;
                af[mi][0] = f2tf32(p[0]);
                af[mi][1] = f2tf32(p[8 * LDA]);
                af[mi][2] = f2tf32(p[4]);
                af[mi][3] = f2tf32(p[8 * LDA + 4]);
            }
#pragma unroll
            for (int ni = 0; ni < 4; ni++) {
                const uint32_t* p = bb + (ni * 8 + g) * LDA + kb;
                bf[ni][0] = p[0];
                bf[ni][1] = p[4];
            }
#pragma unroll
            for (int mi = 0; mi < 4; mi++)
#pragma unroll
                for (int ni = 0; ni < 4; ni++)
                    mma_tf32(acc[mi][ni], af[mi], bf[ni]);
        }
        __syncthreads();
    }

    // ---------------- epilogue ----------------
#pragma unroll
    for (int mi = 0; mi < 4; mi++) {
        const int row0 = m0 + wm * 64 + mi * 16 + g;
#pragma unroll
        for (int ni = 0; ni < 4; ni++) {
            const int col = n0 + wn * 32 + ni * 8 + t4 * 2;
            const float b0 = bias[col], b1 = bias[col + 1];
            float v0 = acc[mi][ni][0] + b0;
            float v1 = acc[mi][ni][1] + b1;
            float v2 = acc[mi][ni][2] + b0;
            float v3 = acc[mi][ni][3] + b1;
            if (EPI == 1) {
                v0 = 0.5f * v0 * (1.0f + erff(v0 * 0.70710678118654752f));
                v1 = 0.5f * v1 * (1.0f + erff(v1 * 0.70710678118654752f));
                v2 = 0.5f * v2 * (1.0f + erff(v2 * 0.70710678118654752f));
                v3 = 0.5f * v3 * (1.0f + erff(v3 * 0.70710678118654752f));
            } else if (EPI == 2) {
                const float2 r0 = *(const float2*)(res + (size_t)row0 * N + col);
                const float2 r1 = *(const float2*)(res + (size_t)(row0 + 8) * N + col);
                v0 += r0.x; v1 += r0.y; v2 += r1.x; v3 += r1.y;
            }
            *(float2*)(C + (size_t)row0 * N + col) = make_float2(v0, v1);
            *(float2*)(C + (size_t)(row0 + 8) * N + col) = make_float2(v2, v3);
        }
    }
}

// ---------------------------------------------------------------------------
// Transpose + round weights to tf32: out[C,R] = rna_tf32(in[R,C]^T)
// ---------------------------------------------------------------------------
__global__ __launch_bounds__(256)
void transpose_kernel(const float* __restrict__ in, float* __restrict__ out,
                      int R, int C)
{
    __shared__ float t[32][33];
    const int c0 = blockIdx.x * 32, r0 = blockIdx.y * 32;
    const int tx = threadIdx.x & 31, ty = threadIdx.x >> 5;
#pragma unroll
    for (int i = ty; i < 32; i += 8)
        t[i][tx] = in[(size_t)(r0 + i) * C + c0 + tx];
    __syncthreads();
#pragma unroll
    for (int i = ty; i < 32; i += 8)
        out[(size_t)(c0 + i) * R + r0 + tx] =
            __uint_as_float(f2tf32(t[tx][i]));
}

__global__ void bias_concat_kernel(const float* __restrict__ bq,
                                   const float* __restrict__ bk,
                                   const float* __restrict__ bv,
                                   float* __restrict__ bqkv)
{
    const int i = blockIdx.x * 256 + threadIdx.x;
    if (i < DDIM) bqkv[i] = bq[i];
    else if (i < 2 * DDIM) bqkv[i] = bk[i - DDIM];
    else bqkv[i] = bv[i - 2 * DDIM];
}

// ---------------------------------------------------------------------------
// Tensor-core flash attention (tf32 mma, cvt.rna fragments, no scaling).
// Q/K/V live in the fused QKV buffer with row stride QKVD.
// ---------------------------------------------------------------------------
#define LDK 68
#define LDV 72
#define LDP 132
#define NKB (SEQ / 128)
#define AT_SMEM ((128*LDP + 2*128*LDK + 2*128*LDV) * 4)

__global__ __launch_bounds__(256)
void attn_tc_kernel(const float* __restrict__ QKV, float* __restrict__ O)
{
    extern __shared__ float sm[];
    float* sP = sm;                       // [128][LDP] (also Q staging)
    float* sK = sm + 128 * LDP;           // [2][128][LDK]
    float* sV = sK + 2 * 128 * LDK;       // [2][128][LDV]
    const uint32_t sK_u = smem_u32(sK);
    const uint32_t sV_u = smem_u32(sV);

    const int bz   = blockIdx.z;
    const int h    = blockIdx.y;
    const int q0   = blockIdx.x * 128;
    const int tid  = threadIdx.x;
    const int warp = tid >> 5;
    const int lane = tid & 31;
    const int g    = lane >> 2;
    const int t4   = lane & 3;

    const size_t base = (size_t)bz * SEQ;
    const float* Qg = QKV + (base + q0) * QKVD + h * HDIM;
    const float* Kg = QKV + base * QKVD + DDIM + h * HDIM;
    const float* Vg = QKV + base * QKVD + 2 * DDIM + h * HDIM;

    for (int i = tid; i < 128 * 16; i += 256) {
        const int r = i >> 4, c = (i & 15) * 4;
        *(float4*)&sP[r * LDK + c] = *(const float4*)(Qg + (size_t)r * QKVD + c);
    }
    __syncthreads();

    uint32_t qf[8][4];
    {
        const float* qrow = sP + (warp * 16 + g) * LDK + t4;
#pragma unroll
        for (int ks = 0; ks < 8; ks++) {
            qf[ks][0] = f2tf32(qrow[ks * 8]);
            qf[ks][1] = f2tf32(qrow[8 * LDK + ks * 8]);
            qf[ks][2] = f2tf32(qrow[ks * 8 + 4]);
            qf[ks][3] = f2tf32(qrow[8 * LDK + ks * 8 + 4]);
        }
    }
    __syncthreads();

    float oacc[8][4];
#pragma unroll
    for (int n = 0; n < 8; n++)
#pragma unroll
        for (int r = 0; r < 4; r++) oacc[n][r] = 0.0f;
    float m0 = -1e30f, m1 = -1e30f, l0 = 0.0f, l1 = 0.0f;

#pragma unroll
    for (int i = 0; i < 8; i++) {
        const int idx = tid + i * 256;
        const int r = idx >> 4, c = (idx & 15) * 4;
        cp_async16(sK_u + (uint32_t)(r * LDK + c) * 4, Kg + (size_t)r * QKVD + c);
        cp_async16(sV_u + (uint32_t)(r * LDV + c) * 4, Vg + (size_t)r * QKVD + c);
    }
    cp_commit();

    for (int kb = 0; kb < NKB; kb++) {
        const int buf = kb & 1;

        if (kb + 1 < NKB) {
            const float* Kt = Kg + (size_t)(kb + 1) * 128 * QKVD;
            const float* Vt = Vg + (size_t)(kb + 1) * 128 * QKVD;
            const uint32_t ko = (uint32_t)((buf ^ 1) * 128 * LDK) * 4;
            const uint32_t vo = (uint32_t)((buf ^ 1) * 128 * LDV) * 4;
#pragma unroll
            for (int i = 0; i < 8; i++) {
                const int idx = tid + i * 256;
                const int r = idx >> 4, c = (idx & 15) * 4;
                cp_async16(sK_u + ko + (uint32_t)(r * LDK + c) * 4,
                           Kt + (size_t)r * QKVD + c);
                cp_async16(sV_u + vo + (uint32_t)(r * LDV + c) * 4,
                           Vt + (size_t)r * QKVD + c);
            }
            cp_commit();
            cp_wait1();
        } else {
            cp_wait0();
        }
        __syncthreads();

        // ---- S = Q @ K^T ----
        float sc[16][4];
#pragma unroll
        for (int nt = 0; nt < 16; nt++) {
#pragma unroll
            for (int r = 0; r < 4; r++) sc[nt][r] = 0.0f;
        }
        const float* kbase = sK + buf * 128 * LDK;
#pragma unroll
        for (int nt = 0; nt < 16; nt++) {
            const float* kp = kbase + (nt * 8 + g) * LDK + t4;
#pragma unroll
            for (int ks = 0; ks < 8; ks++) {
                uint32_t bf[2];
                bf[0] = f2tf32(kp[ks * 8]);
                bf[1] = f2tf32(kp[ks * 8 + 4]);
                mma_tf32(sc[nt], qf[ks], bf);
            }
        }

        // ---- online softmax ----
        float mx0 = m0, mx1 = m1;
#pragma unroll
        for (int nt = 0; nt < 16; nt++) {
            mx0 = fmaxf(mx0, fmaxf(sc[nt][0], sc[nt][1]));
            mx1 = fmaxf(mx1, fmaxf(sc[nt][2], sc[nt][3]));
        }
        mx0 = fmaxf(mx0, __shfl_xor_sync(0xffffffffu, mx0, 1));
        mx0 = fmaxf(mx0, __shfl_xor_sync(0xffffffffu, mx0, 2));
        mx1 = fmaxf(mx1, __shfl_xor_sync(0xffffffffu, mx1, 1));
        mx1 = fmaxf(mx1, __shfl_xor_sync(0xffffffffu, mx1, 2));

        const float s0 = fexp(m0 - mx0);
        const float s1 = fexp(m1 - mx1);
        m0 = mx0; m1 = mx1;
        l0 *= s0;  l1 *= s1;
#pragma unroll
        for (int n = 0; n < 8; n++) {
            oacc[n][0] *= s0; oacc[n][1] *= s0;
            oacc[n][2] *= s1; oacc[n][3] *= s1;
        }

        const int prow = warp * 16 + g;
        float ls0 = 0.0f, ls1 = 0.0f;
#pragma unroll
        for (int nt = 0; nt < 16; nt++) {
            const float p0 = fexp(sc[nt][0] - mx0);
            const float p1 = fexp(sc[nt][1] - mx0);
            const float p2 = fexp(sc[nt][2] - mx1);
            const float p3 = fexp(sc[nt][3] - mx1);
            ls0 += p0 + p1;
            ls1 += p2 + p3;
            const int col = nt * 8 + 2 * t4;
            *(float2*)&sP[prow * LDP + col] = make_float2(p0, p1);
            *(float2*)&sP[(prow + 8) * LDP + col] = make_float2(p2, p3);
        }
        l0 += ls0; l1 += ls1;
        __syncthreads();

        // ---- O += P @ V ----
        const float* vbase = sV + buf * 128 * LDV;
        const float* prow_p = sP + prow * LDP + t4;
#pragma unroll
        for (int ks = 0; ks < 16; ks++) {
            uint32_t af[4];
            af[0] = f2tf32(prow_p[ks * 8]);
            af[1] = f2tf32(prow_p[8 * LDP + ks * 8]);
            af[2] = f2tf32(prow_p[ks * 8 + 4]);
            af[3] = f2tf32(prow_p[8 * LDP + ks * 8 + 4]);
            const float* vp = vbase + (ks * 8 + t4) * LDV + g;
#pragma unroll
            for (int nt = 0; nt < 8; nt++) {
                uint32_t bf[2];
                bf[0] = f2tf32(vp[nt * 8]);
                bf[1] = f2tf32(vp[4 * LDV + nt * 8]);
                mma_tf32(oacc[nt], af, bf);
            }
        }
        __syncthreads();
    }

    l0 += __shfl_xor_sync(0xffffffffu, l0, 1);
    l0 += __shfl_xor_sync(0xffffffffu, l0, 2);
    l1 += __shfl_xor_sync(0xffffffffu, l1, 1);
    l1 += __shfl_xor_sync(0xffffffffu, l1, 2);
    const float inv0 = 1.0f / l0;
    const float inv1 = 1.0f / l1;

    const size_t row = base + q0 + warp * 16 + g;
    float* Og = O + row * DDIM + h * HDIM;
#pragma unroll
    for (int nt = 0; nt < 8; nt++) {
        const int col = nt * 8 + 2 * t4;
        *(float2*)(Og + col) =
            make_float2(oacc[nt][0] * inv0, oacc[nt][1] * inv0);
        *(float2*)(Og + 8 * DDIM + col) =
            make_float2(oacc[nt][2] * inv1, oacc[nt][3] * inv1);
    }
}

// ---------------------------------------------------------------------------
// LayerNorm over last dim (D=1024), one block per row, 256 threads.
// ---------------------------------------------------------------------------
__global__ __launch_bounds__(256)
void ln_kernel(const float* __restrict__ x, const float* __restrict__ g,
               const float* __restrict__ b, float* __restrict__ y)
{
    const int D = DDIM;
    const int row = blockIdx.x;
    const float* xr = x + (size_t)row * D;

    float v[4];
    float s = 0.f, s2 = 0.f;
#pragma unroll
    for (int i = 0; i < 4; i++) {
        v[i] = xr[threadIdx.x + i * 256];
        s += v[i];
        s2 = fmaf(v[i], v[i], s2);
    }
#pragma unroll
    for (int o = 16; o > 0; o >>= 1) {
        s  += __shfl_xor_sync(0xffffffffu, s, o);
        s2 += __shfl_xor_sync(0xffffffffu, s2, o);
    }
    __shared__ float ss[8], ss2[8];
    const int w = threadIdx.x >> 5;
    if ((threadIdx.x & 31) == 0) { ss[w] = s; ss2[w] = s2; }
    __syncthreads();
    if (threadIdx.x < 32) {
        s  = (threadIdx.x < 8) ? ss[threadIdx.x]  : 0.f;
        s2 = (threadIdx.x < 8) ? ss2[threadIdx.x] : 0.f;
#pragma unroll
        for (int o = 4; o > 0; o >>= 1) {
            s  += __shfl_xor_sync(0xffffffffu, s, o);
            s2 += __shfl_xor_sync(0xffffffffu, s2, o);
        }
        if (threadIdx.x == 0) { ss[0] = s; ss2[0] = s2; }
    }
    __syncthreads();
    const float mu  = ss[0] * (1.0f / D);
    const float var = ss2[0] * (1.0f / D) - mu * mu;
    const float inv = rsqrtf(var + 1e-5f);
#pragma unroll
    for (int i = 0; i < 4; i++) {
        const int c = threadIdx.x + i * 256;
        y[(size_t)row * D + c] = (v[i] - mu) * inv * g[c] + b[c];
    }
}

// ---------------------------------------------------------------------------
// Launch
// ---------------------------------------------------------------------------
extern "C" void kernel_launch(void* const* d_in, const int* in_sizes, int n_in,
                              void* d_out, int out_size)
{
    (void)in_sizes; (void)n_in; (void)out_size;
    const float* x     = (const float*)d_in[0];
    const float* Wq    = (const float*)d_in[1];
    const float* bq    = (const float*)d_in[2];
    const float* Wk    = (const float*)d_in[3];
    const float* bk    = (const float*)d_in[4];
    const float* Wv    = (const float*)d_in[5];
    const float* bv    = (const float*)d_in[6];
    const float* Wo    = (const float*)d_in[7];
    const float* bo    = (const float*)d_in[8];
    const float* W1    = (const float*)d_in[9];
    const float* b1    = (const float*)d_in[10];
    const float* W2    = (const float*)d_in[11];
    const float* b2    = (const float*)d_in[12];
    const float* g1    = (const float*)d_in[13];
    const float* beta1 = (const float*)d_in[14];
    const float* g2    = (const float*)d_in[15];
    const float* beta2 = (const float*)d_in[16];
    float* out = (float*)d_out;

    float* scr = nullptr;
    cudaGetSymbolAddress((void**)&scr, g_scratch);
    float* qkv   = scr + OFF_QKV;
    float* att   = scr + OFF_ATT;
    float* x1    = scr + OFF_X1;
    float* x2    = scr + OFF_X2;
    float* x3    = scr + OFF_X3;
    float* hbuf  = scr + OFF_H;
    float* WqkvT = scr + OFF_WQKVT;
    float* WoT   = scr + OFF_WOT;
    float* W1T   = scr + OFF_W1T;
    float* W2T   = scr + OFF_W2T;
    float* bqkv  = scr + OFF_BQKV;

    cudaFuncSetAttribute(gemm_tc<0>, cudaFuncAttributeMaxDynamicSharedMemorySize, GT_SMEM);
    cudaFuncSetAttribute(gemm_tc<1>, cudaFuncAttributeMaxDynamicSharedMemorySize, GT_SMEM);
    cudaFuncSetAttribute(gemm_tc<2>, cudaFuncAttributeMaxDynamicSharedMemorySize, GT_SMEM);
    cudaFuncSetAttribute(attn_tc_kernel, cudaFuncAttributeMaxDynamicSharedMemorySize, AT_SMEM);

    // Weight prep (transpose + round to tf32)
    transpose_kernel<<<dim3(DDIM / 32, DDIM / 32), 256>>>(Wq, WqkvT, DDIM, DDIM);
    transpose_kernel<<<dim3(DDIM / 32, DDIM / 32), 256>>>(Wk, WqkvT + (size_t)DDIM * DDIM, DDIM, DDIM);
    transpose_kernel<<<dim3(DDIM / 32, DDIM / 32), 256>>>(Wv, WqkvT + (size_t)2 * DDIM * DDIM, DDIM, DDIM);
    transpose_kernel<<<dim3(DDIM / 32, DDIM / 32), 256>>>(Wo, WoT, DDIM, DDIM);
    transpose_kernel<<<dim3(FFDIM / 32, DDIM / 32), 256>>>(W1, W1T, DDIM, FFDIM);
    transpose_kernel<<<dim3(DDIM / 32, FFDIM / 32), 256>>>(W2, W2T, FFDIM, DDIM);
    bias_concat_kernel<<<QKVD / 256, 256>>>(bq, bk, bv, bqkv);

    // Fused QKV projection: [4096, 3072]
    gemm_tc<0><<<dim3(QKVD / BN, MTOK / BM), 512, GT_SMEM>>>(
        x, WqkvT, bqkv, nullptr, qkv, MTOK, QKVD, DDIM);

    // Attention (tf32 tensor cores, no scaling)
    attn_tc_kernel<<<dim3(SEQ / 128, NHEAD, BATCH), 256, AT_SMEM>>>(qkv, att);

    // Output projection + residual
    gemm_tc<2><<<dim3(DDIM / BN, MTOK / BM), 512, GT_SMEM>>>(
        att, WoT, bo, x, x1, MTOK, DDIM, DDIM);

    // LN1
    ln_kernel<<<MTOK, 256>>>(x1, g1, beta1, x2);

    // FFN
    gemm_tc<1><<<dim3(FFDIM / BN, MTOK / BM), 512, GT_SMEM>>>(
        x2, W1T, b1, nullptr, hbuf, MTOK, FFDIM, DDIM);
    gemm_tc<2><<<dim3(DDIM / BN, MTOK / BM), 512, GT_SMEM>>>(
        hbuf, W2T, b2, x2, x3, MTOK, DDIM, FFDIM);

    // LN2 -> output
    ln_kernel<<<MTOK, 256>>>(x3, g2, beta2, out);
}

// round 8
// speedup vs baseline: 4.0839x; 1.5166x over previous
#include <cuda_runtime.h>
#include <cuda_fp16.h>
#include <math.h>
#include <cstdint>

// ---------------------------------------------------------------------------
// Transformer block. Big GEMMs via mma.sync fp16 (fp32 accum); attention via
// mma.sync tf32. M=4096, D=1024, H=16, hd=64, FF=4096.
// ---------------------------------------------------------------------------

#define MTOK 4096
#define DDIM 1024
#define QKVD 3072
#define FFDIM 4096
#define NHEAD 16
#define HDIM 64
#define SEQ 2048
#define BATCH 2

// scratch layout (units: floats; half buffers use 2 halfs per slot)
#define OFF_QKV   ((size_t)0)                                  // f32 [4096,3072]
#define OFF_X1    (OFF_QKV  + (size_t)MTOK*QKVD)               // f32
#define OFF_X2    (OFF_X1   + (size_t)MTOK*DDIM)               // f32
#define OFF_X3    (OFF_X2   + (size_t)MTOK*DDIM)               // f32
#define OFF_ATTH  (OFF_X3   + (size_t)MTOK*DDIM)               // f16 [4096,1024]
#define OFF_X2H   (OFF_ATTH + (size_t)MTOK*DDIM/2)             // f16
#define OFF_HH    (OFF_X2H  + (size_t)MTOK*DDIM/2)             // f16 [4096,4096]
#define OFF_XH    (OFF_HH   + (size_t)MTOK*FFDIM/2)            // f16
#define OFF_WQKVT (OFF_XH   + (size_t)MTOK*DDIM/2)             // f16 [3072,1024]
#define OFF_WOT   (OFF_WQKVT+ (size_t)QKVD*DDIM/2)             // f16 [1024,1024]
#define OFF_W1T   (OFF_WOT  + (size_t)DDIM*DDIM/2)             // f16 [4096,1024]
#define OFF_W2T   (OFF_W1T  + (size_t)DDIM*FFDIM/2)            // f16 [1024,4096]
#define OFF_BQKV  (OFF_W2T  + (size_t)FFDIM*DDIM/2)            // f32 [3072]
#define SCRATCH_FLOATS (OFF_BQKV + (size_t)QKVD)

__device__ float g_scratch[SCRATCH_FLOATS];

// ---------------- PTX helpers ----------------
__device__ __forceinline__ void cp_async16(uint32_t dst, const void* src) {
    asm volatile("cp.async.cg.shared.global [%0], [%1], 16;"
                 :: "r"(dst), "l"(src) : "memory");
}
__device__ __forceinline__ void cp_commit() {
    asm volatile("cp.async.commit_group;" ::: "memory");
}
__device__ __forceinline__ void cp_wait0() {
    asm volatile("cp.async.wait_group 0;" ::: "memory");
}
__device__ __forceinline__ void cp_wait1() {
    asm volatile("cp.async.wait_group 1;" ::: "memory");
}
__device__ __forceinline__ uint32_t smem_u32(const void* p) {
    uint32_t a;
    asm("{ .reg .u64 t; cvta.to.shared.u64 t, %1; cvt.u32.u64 %0, t; }"
        : "=r"(a) : "l"(p));
    return a;
}
__device__ __forceinline__ uint32_t f2tf32(float v) {
    uint32_t r;
    asm("cvt.rna.tf32.f32 %0, %1;" : "=r"(r) : "f"(v));
    return r;
}
__device__ __forceinline__ void mma_tf32(float* c, const uint32_t* a,
                                         const uint32_t* b) {
    asm volatile(
        "mma.sync.aligned.m16n8k8.row.col.f32.tf32.tf32.f32 "
        "{%0,%1,%2,%3}, {%4,%5,%6,%7}, {%8,%9}, {%0,%1,%2,%3};"
        : "+f"(c[0]), "+f"(c[1]), "+f"(c[2]), "+f"(c[3])
        : "r"(a[0]), "r"(a[1]), "r"(a[2]), "r"(a[3]), "r"(b[0]), "r"(b[1]));
}
__device__ __forceinline__ void mma_f16(float* c, const uint32_t* a,
                                        const uint32_t* b) {
    asm volatile(
        "mma.sync.aligned.m16n8k16.row.col.f32.f16.f16.f32 "
        "{%0,%1,%2,%3}, {%4,%5,%6,%7}, {%8,%9}, {%0,%1,%2,%3};"
        : "+f"(c[0]), "+f"(c[1]), "+f"(c[2]), "+f"(c[3])
        : "r"(a[0]), "r"(a[1]), "r"(a[2]), "r"(a[3]), "r"(b[0]), "r"(b[1]));
}

// Fast exp on the FMA pipe (no MUFU).
__device__ __forceinline__ float fexp(float x) {
    float t = x * 1.4426950408889634f;
    t = fmaxf(t, -126.0f);
    const float fn = rintf(t);
    const float f = t - fn;
    float p = 1.33336500e-3f;
    p = fmaf(p, f, 9.61823766e-3f);
    p = fmaf(p, f, 5.55041087e-2f);
    p = fmaf(p, f, 2.40226507e-1f);
    p = fmaf(p, f, 6.93147182e-1f);
    p = fmaf(p, f, 1.0f);
    const int n = (int)fn;
    return p * __int_as_float((n + 127) << 23);
}

// ---------------------------------------------------------------------------
// fp16 GEMM: C[M,N] = A[M,K] @ Bt[N,K]^T + bias (+ epilogue)
// A, Bt in fp16; acc fp32. CTA tile 256x128, BK=32 halfs, 512 threads,
// double-buffered cp.async. Row stride 72 halfs (S2=36 -> conflict-free).
// EPI: 0 bias, 1 bias+GELU, 2 bias+residual. HOUT: write half instead of float.
// ---------------------------------------------------------------------------
#define BM 256
#define BN 128
#define S2 36                      // row stride in half2 (32-bit) units
#define ATILE_H (256 * 72)         // halfs per A buffer
#define BTILE_H (128 * 72)
#define GT_SMEM ((2 * ATILE_H + 2 * BTILE_H) * 2)   // 110592 bytes

template <int EPI, int HOUT>
__global__ __launch_bounds__(512)
void gemm_h(const __half* __restrict__ A, const __half* __restrict__ Bt,
            const float* __restrict__ bias, const float* __restrict__ res,
            void* __restrict__ Cout, int M, int N, int K)
{
    extern __shared__ __half smh[];
    __half* As = smh;                      // [2][256][72]
    __half* Bs = smh + 2 * ATILE_H;        // [2][128][72]
    const uint32_t As_u = smem_u32(As);
    const uint32_t Bs_u = smem_u32(Bs);

    const int tid  = threadIdx.x;
    const int warp = tid >> 5;
    const int lane = tid & 31;
    const int g    = lane >> 2;
    const int t4   = lane & 3;
    const int wm   = warp >> 2;     // 0..3, 64 rows
    const int wn   = warp & 3;      // 0..3, 32 cols

    const int m0 = blockIdx.y * BM;
    const int n0 = blockIdx.x * BN;

    // A loader: 256 rows x 64B payload = 1024 x 16B; 512 thr x 2.
    const int arow = tid >> 1;
    const int a16  = (tid & 1) * 2;        // 16B chunk {a16, a16+1}
    const __half* Ag = A + (size_t)(m0 + arow) * K + a16 * 8;
    const uint32_t Asm = As_u + (uint32_t)(arow * 144 + a16 * 16);
    // B loader: 128 rows x 64B = 512 x 16B; 1 per thread.
    const int brow = tid >> 2;
    const int b16  = tid & 3;
    const __half* Bg = Bt + (size_t)(n0 + brow) * K + b16 * 8;
    const uint32_t Bsm = Bs_u + (uint32_t)(brow * 144 + b16 * 16);

    float acc[4][4][4];
#pragma unroll
    for (int mi = 0; mi < 4; mi++)
#pragma unroll
        for (int ni = 0; ni < 4; ni++)
#pragma unroll
            for (int r = 0; r < 4; r++) acc[mi][ni][r] = 0.0f;

    const int T = K >> 5;    // BK = 32 halfs

    cp_async16(Asm, Ag);
    cp_async16(Asm + 16, Ag + 8);
    cp_async16(Bsm, Bg);
    cp_commit();

    for (int tb = 0; tb < T; tb++) {
        const int b = tb & 1;
        if (tb + 1 < T) {
            const uint32_t ao = (uint32_t)((b ^ 1) * ATILE_H) * 2;
            const uint32_t bo = (uint32_t)((b ^ 1) * BTILE_H) * 2;
            const size_t ko = (size_t)(tb + 1) * 32;
            cp_async16(Asm + ao, Ag + ko);
            cp_async16(Asm + ao + 16, Ag + ko + 8);
            cp_async16(Bsm + bo, Bg + ko);
            cp_commit();
            cp_wait1();
        } else {
            cp_wait0();
        }
        __syncthreads();

        const uint32_t* a2 = (const uint32_t*)(As + b * ATILE_H) + (wm * 64) * S2;
        const uint32_t* b2 = (const uint32_t*)(Bs + b * BTILE_H) + (wn * 32) * S2;
#pragma unroll
        for (int kk = 0; kk < 2; kk++) {
            const int kb = kk * 8 + t4;
            uint32_t af[4][4], bf[4][2];
#pragma unroll
            for (int mi = 0; mi < 4; mi++) {
                const uint32_t* p = a2 + (mi * 16 + g) * S2 + kb;
                af[mi][0] = p[0];
                af[mi][1] = p[8 * S2];
                af[mi][2] = p[4];
                af[mi][3] = p[8 * S2 + 4];
            }
#pragma unroll
            for (int ni = 0; ni < 4; ni++) {
                const uint32_t* p = b2 + (ni * 8 + g) * S2 + kb;
                bf[ni][0] = p[0];
                bf[ni][1] = p[4];
            }
#pragma unroll
            for (int mi = 0; mi < 4; mi++)
#pragma unroll
                for (int ni = 0; ni < 4; ni++)
                    mma_f16(acc[mi][ni], af[mi], bf[ni]);
        }
        __syncthreads();
    }

    // ---------------- epilogue ----------------
    float* Cf = (float*)Cout;
    __half* Ch = (__half*)Cout;
#pragma unroll
    for (int mi = 0; mi < 4; mi++) {
        const int row0 = m0 + wm * 64 + mi * 16 + g;
#pragma unroll
        for (int ni = 0; ni < 4; ni++) {
            const int col = n0 + wn * 32 + ni * 8 + t4 * 2;
            const float b0 = bias[col], b1 = bias[col + 1];
            float v0 = acc[mi][ni][0] + b0;
            float v1 = acc[mi][ni][1] + b1;
            float v2 = acc[mi][ni][2] + b0;
            float v3 = acc[mi][ni][3] + b1;
            if (EPI == 1) {
                v0 = 0.5f * v0 * (1.0f + erff(v0 * 0.70710678118654752f));
                v1 = 0.5f * v1 * (1.0f + erff(v1 * 0.70710678118654752f));
                v2 = 0.5f * v2 * (1.0f + erff(v2 * 0.70710678118654752f));
                v3 = 0.5f * v3 * (1.0f + erff(v3 * 0.70710678118654752f));
            } else if (EPI == 2) {
                const float2 r0 = *(const float2*)(res + (size_t)row0 * N + col);
                const float2 r1 = *(const float2*)(res + (size_t)(row0 + 8) * N + col);
                v0 += r0.x; v1 += r0.y; v2 += r1.x; v3 += r1.y;
            }
            if (HOUT) {
                *(__half2*)(Ch + (size_t)row0 * N + col) = __floats2half2_rn(v0, v1);
                *(__half2*)(Ch + (size_t)(row0 + 8) * N + col) = __floats2half2_rn(v2, v3);
            } else {
                *(float2*)(Cf + (size_t)row0 * N + col) = make_float2(v0, v1);
                *(float2*)(Cf + (size_t)(row0 + 8) * N + col) = make_float2(v2, v3);
            }
        }
    }
}

// ---------------------------------------------------------------------------
// Transpose weights to [N][K] fp16: out[C,R] = (half)in[R,C]
// ---------------------------------------------------------------------------
__global__ __launch_bounds__(256)
void transpose_h_kernel(const float* __restrict__ in, __half* __restrict__ out,
                        int R, int C)
{
    __shared__ float t[32][33];
    const int c0 = blockIdx.x * 32, r0 = blockIdx.y * 32;
    const int tx = threadIdx.x & 31, ty = threadIdx.x >> 5;
#pragma unroll
    for (int i = ty; i < 32; i += 8)
        t[i][tx] = in[(size_t)(r0 + i) * C + c0 + tx];
    __syncthreads();
#pragma unroll
    for (int i = ty; i < 32; i += 8)
        out[(size_t)(c0 + i) * R + r0 + tx] = __float2half_rn(t[tx][i]);
}

__global__ void bias_concat_kernel(const float* __restrict__ bq,
                                   const float* __restrict__ bk,
                                   const float* __restrict__ bv,
                                   float* __restrict__ bqkv)
{
    const int i = blockIdx.x * 256 + threadIdx.x;
    if (i < DDIM) bqkv[i] = bq[i];
    else if (i < 2 * DDIM) bqkv[i] = bk[i - DDIM];
    else bqkv[i] = bv[i - 2 * DDIM];
}

// fp32 -> fp16 bulk convert (4 elems per thread)
__global__ __launch_bounds__(256)
void f2h_kernel(const float* __restrict__ in, __half* __restrict__ out)
{
    const int i = blockIdx.x * 256 + threadIdx.x;
    const float4 v = ((const float4*)in)[i];
    ((__half2*)out)[2 * i]     = __floats2half2_rn(v.x, v.y);
    ((__half2*)out)[2 * i + 1] = __floats2half2_rn(v.z, v.w);
}

// ---------------------------------------------------------------------------
// Tensor-core flash attention (tf32 mma, fp32 softmax, no scaling).
// Reads fp32 fused QKV (stride QKVD); writes fp16 att (stride DDIM).
// ---------------------------------------------------------------------------
#define LDK 68
#define LDV 72
#define LDP 132
#define NKB (SEQ / 128)
#define AT_SMEM ((128*LDP + 2*128*LDK + 2*128*LDV) * 4)

__global__ __launch_bounds__(256)
void attn_tc_kernel(const float* __restrict__ QKV, __half* __restrict__ O)
{
    extern __shared__ float sm[];
    float* sP = sm;                       // [128][LDP] (also Q staging)
    float* sK = sm + 128 * LDP;           // [2][128][LDK]
    float* sV = sK + 2 * 128 * LDK;       // [2][128][LDV]
    const uint32_t sK_u = smem_u32(sK);
    const uint32_t sV_u = smem_u32(sV);

    const int bz   = blockIdx.z;
    const int h    = blockIdx.y;
    const int q0   = blockIdx.x * 128;
    const int tid  = threadIdx.x;
    const int warp = tid >> 5;
    const int lane = tid & 31;
    const int g    = lane >> 2;
    const int t4   = lane & 3;

    const size_t base = (size_t)bz * SEQ;
    const float* Qg = QKV + (base + q0) * QKVD + h * HDIM;
    const float* Kg = QKV + base * QKVD + DDIM + h * HDIM;
    const float* Vg = QKV + base * QKVD + 2 * DDIM + h * HDIM;

    for (int i = tid; i < 128 * 16; i += 256) {
        const int r = i >> 4, c = (i & 15) * 4;
        *(float4*)&sP[r * LDK + c] = *(const float4*)(Qg + (size_t)r * QKVD + c);
    }
    __syncthreads();

    uint32_t qf[8][4];
    {
        const float* qrow = sP + (warp * 16 + g) * LDK + t4;
#pragma unroll
        for (int ks = 0; ks < 8; ks++) {
            qf[ks][0] = f2tf32(qrow[ks * 8]);
            qf[ks][1] = f2tf32(qrow[8 * LDK + ks * 8]);
            qf[ks][2] = f2tf32(qrow[ks * 8 + 4]);
            qf[ks][3] = f2tf32(qrow[8 * LDK + ks * 8 + 4]);
        }
    }
    __syncthreads();

    float oacc[8][4];
#pragma unroll
    for (int n = 0; n < 8; n++)
#pragma unroll
        for (int r = 0; r < 4; r++) oacc[n][r] = 0.0f;
    float m0 = -1e30f, m1 = -1e30f, l0 = 0.0f, l1 = 0.0f;

#pragma unroll
    for (int i = 0; i < 8; i++) {
        const int idx = tid + i * 256;
        const int r = idx >> 4, c = (idx & 15) * 4;
        cp_async16(sK_u + (uint32_t)(r * LDK + c) * 4, Kg + (size_t)r * QKVD + c);
        cp_async16(sV_u + (uint32_t)(r * LDV + c) * 4, Vg + (size_t)r * QKVD + c);
    }
    cp_commit();

    for (int kb = 0; kb < NKB; kb++) {
        const int buf = kb & 1;

        if (kb + 1 < NKB) {
            const float* Kt = Kg + (size_t)(kb + 1) * 128 * QKVD;
            const float* Vt = Vg + (size_t)(kb + 1) * 128 * QKVD;
            const uint32_t ko = (uint32_t)((buf ^ 1) * 128 * LDK) * 4;
            const uint32_t vo = (uint32_t)((buf ^ 1) * 128 * LDV) * 4;
#pragma unroll
            for (int i = 0; i < 8; i++) {
                const int idx = tid + i * 256;
                const int r = idx >> 4, c = (idx & 15) * 4;
                cp_async16(sK_u + ko + (uint32_t)(r * LDK + c) * 4,
                           Kt + (size_t)r * QKVD + c);
                cp_async16(sV_u + vo + (uint32_t)(r * LDV + c) * 4,
                           Vt + (size_t)r * QKVD + c);
            }
            cp_commit();
            cp_wait1();
        } else {
            cp_wait0();
        }
        __syncthreads();

        float sc[16][4];
#pragma unroll
        for (int nt = 0; nt < 16; nt++) {
#pragma unroll
            for (int r = 0; r < 4; r++) sc[nt][r] = 0.0f;
        }
        const float* kbase = sK + buf * 128 * LDK;
#pragma unroll
        for (int nt = 0; nt < 16; nt++) {
            const float* kp = kbase + (nt * 8 + g) * LDK + t4;
#pragma unroll
            for (int ks = 0; ks < 8; ks++) {
                uint32_t bf[2];
                bf[0] = f2tf32(kp[ks * 8]);
                bf[1] = f2tf32(kp[ks * 8 + 4]);
                mma_tf32(sc[nt], qf[ks], bf);
            }
        }

        float mx0 = m0, mx1 = m1;
#pragma unroll
        for (int nt = 0; nt < 16; nt++) {
            mx0 = fmaxf(mx0, fmaxf(sc[nt][0], sc[nt][1]));
            mx1 = fmaxf(mx1, fmaxf(sc[nt][2], sc[nt][3]));
        }
        mx0 = fmaxf(mx0, __shfl_xor_sync(0xffffffffu, mx0, 1));
        mx0 = fmaxf(mx0, __shfl_xor_sync(0xffffffffu, mx0, 2));
        mx1 = fmaxf(mx1, __shfl_xor_sync(0xffffffffu, mx1, 1));
        mx1 = fmaxf(mx1, __shfl_xor_sync(0xffffffffu, mx1, 2));

        const float s0 = fexp(m0 - mx0);
        const float s1 = fexp(m1 - mx1);
        m0 = mx0; m1 = mx1;
        l0 *= s0;  l1 *= s1;
#pragma unroll
        for (int n = 0; n < 8; n++) {
            oacc[n][0] *= s0; oacc[n][1] *= s0;
            oacc[n][2] *= s1; oacc[n][3] *= s1;
        }

        const int prow = warp * 16 + g;
        float ls0 = 0.0f, ls1 = 0.0f;
#pragma unroll
        for (int nt = 0; nt < 16; nt++) {
            const float p0 = fexp(sc[nt][0] - mx0);
            const float p1 = fexp(sc[nt][1] - mx0);
            const float p2 = fexp(sc[nt][2] - mx1);
            const float p3 = fexp(sc[nt][3] - mx1);
            ls0 += p0 + p1;
            ls1 += p2 + p3;
            const int col = nt * 8 + 2 * t4;
            *(float2*)&sP[prow * LDP + col] = make_float2(p0, p1);
            *(float2*)&sP[(prow + 8) * LDP + col] = make_float2(p2, p3);
        }
        l0 += ls0; l1 += ls1;
        __syncthreads();

        const float* vbase = sV + buf * 128 * LDV;
        const float* prow_p = sP + prow * LDP + t4;
#pragma unroll
        for (int ks = 0; ks < 16; ks++) {
            uint32_t af[4];
            af[0] = f2tf32(prow_p[ks * 8]);
            af[1] = f2tf32(prow_p[8 * LDP + ks * 8]);
            af[2] = f2tf32(prow_p[ks * 8 + 4]);
            af[3] = f2tf32(prow_p[8 * LDP + ks * 8 + 4]);
            const float* vp = vbase + (ks * 8 + t4) * LDV + g;
#pragma unroll
            for (int nt = 0; nt < 8; nt++) {
                uint32_t bf[2];
                bf[0] = f2tf32(vp[nt * 8]);
                bf[1] = f2tf32(vp[4 * LDV + nt * 8]);
                mma_tf32(oacc[nt], af, bf);
            }
        }
        __syncthreads();
    }

    l0 += __shfl_xor_sync(0xffffffffu, l0, 1);
    l0 += __shfl_xor_sync(0xffffffffu, l0, 2);
    l1 += __shfl_xor_sync(0xffffffffu, l1, 1);
    l1 += __shfl_xor_sync(0xffffffffu, l1, 2);
    const float inv0 = 1.0f / l0;
    const float inv1 = 1.0f / l1;

    const size_t row = base + q0 + warp * 16 + g;
    __half* Og = O + row * DDIM + h * HDIM;
#pragma unroll
    for (int nt = 0; nt < 8; nt++) {
        const int col = nt * 8 + 2 * t4;
        *(__half2*)(Og + col) =
            __floats2half2_rn(oacc[nt][0] * inv0, oacc[nt][1] * inv0);
        *(__half2*)(Og + 8 * DDIM + col) =
            __floats2half2_rn(oacc[nt][2] * inv1, oacc[nt][3] * inv1);
    }
}

// ---------------------------------------------------------------------------
// LayerNorm (D=1024), one block per row; optional fp16 twin output.
// ---------------------------------------------------------------------------
__global__ __launch_bounds__(256)
void ln_kernel(const float* __restrict__ x, const float* __restrict__ g,
               const float* __restrict__ b, float* __restrict__ y,
               __half* __restrict__ yh)
{
    const int D = DDIM;
    const int row = blockIdx.x;
    const float* xr = x + (size_t)row * D;

    float v[4];
    float s = 0.f, s2 = 0.f;
#pragma unroll
    for (int i = 0; i < 4; i++) {
        v[i] = xr[threadIdx.x + i * 256];
        s += v[i];
        s2 = fmaf(v[i], v[i], s2);
    }
#pragma unroll
    for (int o = 16; o > 0; o >>= 1) {
        s  += __shfl_xor_sync(0xffffffffu, s, o);
        s2 += __shfl_xor_sync(0xffffffffu, s2, o);
    }
    __shared__ float ss[8], ss2[8];
    const int w = threadIdx.x >> 5;
    if ((threadIdx.x & 31) == 0) { ss[w] = s; ss2[w] = s2; }
    __syncthreads();
    if (threadIdx.x < 32) {
        s  = (threadIdx.x < 8) ? ss[threadIdx.x]  : 0.f;
        s2 = (threadIdx.x < 8) ? ss2[threadIdx.x] : 0.f;
#pragma unroll
        for (int o = 4; o > 0; o >>= 1) {
            s  += __shfl_xor_sync(0xffffffffu, s, o);
            s2 += __shfl_xor_sync(0xffffffffu, s2, o);
        }
        if (threadIdx.x == 0) { ss[0] = s; ss2[0] = s2; }
    }
    __syncthreads();
    const float mu  = ss[0] * (1.0f / D);
    const float var = ss2[0] * (1.0f / D) - mu * mu;
    const float inv = rsqrtf(var + 1e-5f);
#pragma unroll
    for (int i = 0; i < 4; i++) {
        const int c = threadIdx.x + i * 256;
        const float val = (v[i] - mu) * inv * g[c] + b[c];
        y[(size_t)row * D + c] = val;
        if (yh) yh[(size_t)row * D + c] = __float2half_rn(val);
    }
}

// ---------------------------------------------------------------------------
// Launch
// ---------------------------------------------------------------------------
extern "C" void kernel_launch(void* const* d_in, const int* in_sizes, int n_in,
                              void* d_out, int out_size)
{
    (void)in_sizes; (void)n_in; (void)out_size;
    const float* x     = (const float*)d_in[0];
    const float* Wq    = (const float*)d_in[1];
    const float* bq    = (const float*)d_in[2];
    const float* Wk    = (const float*)d_in[3];
    const float* bk    = (const float*)d_in[4];
    const float* Wv    = (const float*)d_in[5];
    const float* bv    = (const float*)d_in[6];
    const float* Wo    = (const float*)d_in[7];
    const float* bo    = (const float*)d_in[8];
    const float* W1    = (const float*)d_in[9];
    const float* b1    = (const float*)d_in[10];
    const float* W2    = (const float*)d_in[11];
    const float* b2    = (const float*)d_in[12];
    const float* g1    = (const float*)d_in[13];
    const float* beta1 = (const float*)d_in[14];
    const float* g2    = (const float*)d_in[15];
    const float* beta2 = (const float*)d_in[16];
    float* out = (float*)d_out;

    float* scr = nullptr;
    cudaGetSymbolAddress((void**)&scr, g_scratch);
    float*  qkv   = scr + OFF_QKV;
    float*  x1    = scr + OFF_X1;
    float*  x2    = scr + OFF_X2;
    float*  x3    = scr + OFF_X3;
    __half* atth  = (__half*)(scr + OFF_ATTH);
    __half* x2h   = (__half*)(scr + OFF_X2H);
    __half* hh    = (__half*)(scr + OFF_HH);
    __half* xh    = (__half*)(scr + OFF_XH);
    __half* WqkvT = (__half*)(scr + OFF_WQKVT);
    __half* WoT   = (__half*)(scr + OFF_WOT);
    __half* W1T   = (__half*)(scr + OFF_W1T);
    __half* W2T   = (__half*)(scr + OFF_W2T);
    float*  bqkv  = scr + OFF_BQKV;

    cudaFuncSetAttribute(gemm_h<0,0>, cudaFuncAttributeMaxDynamicSharedMemorySize, GT_SMEM);
    cudaFuncSetAttribute(gemm_h<1,1>, cudaFuncAttributeMaxDynamicSharedMemorySize, GT_SMEM);
    cudaFuncSetAttribute(gemm_h<2,0>, cudaFuncAttributeMaxDynamicSharedMemorySize, GT_SMEM);
    cudaFuncSetAttribute(attn_tc_kernel, cudaFuncAttributeMaxDynamicSharedMemorySize, AT_SMEM);

    // Input + weight prep (fp16 conversion once, RN)
    f2h_kernel<<<(MTOK * DDIM / 4) / 256, 256>>>(x, xh);
    transpose_h_kernel<<<dim3(DDIM / 32, DDIM / 32), 256>>>(Wq, WqkvT, DDIM, DDIM);
    transpose_h_kernel<<<dim3(DDIM / 32, DDIM / 32), 256>>>(Wk, WqkvT + (size_t)DDIM * DDIM, DDIM, DDIM);
    transpose_h_kernel<<<dim3(DDIM / 32, DDIM / 32), 256>>>(Wv, WqkvT + (size_t)2 * DDIM * DDIM, DDIM, DDIM);
    transpose_h_kernel<<<dim3(DDIM / 32, DDIM / 32), 256>>>(Wo, WoT, DDIM, DDIM);
    transpose_h_kernel<<<dim3(FFDIM / 32, DDIM / 32), 256>>>(W1, W1T, DDIM, FFDIM);
    transpose_h_kernel<<<dim3(DDIM / 32, FFDIM / 32), 256>>>(W2, W2T, FFDIM, DDIM);
    bias_concat_kernel<<<QKVD / 256, 256>>>(bq, bk, bv, bqkv);

    // Fused QKV projection (fp16 in, fp32 out)
    gemm_h<0,0><<<dim3(QKVD / BN, MTOK / BM), 512, GT_SMEM>>>(
        xh, WqkvT, bqkv, nullptr, qkv, MTOK, QKVD, DDIM);

    // Attention (tf32, writes fp16 att)
    attn_tc_kernel<<<dim3(SEQ / 128, NHEAD, BATCH), 256, AT_SMEM>>>(qkv, atth);

    // Output projection + residual (fp32 out)
    gemm_h<2,0><<<dim3(DDIM / BN, MTOK / BM), 512, GT_SMEM>>>(
        atth, WoT, bo, x, x1, MTOK, DDIM, DDIM);

    // LN1 -> x2 (fp32) + x2h (fp16)
    ln_kernel<<<MTOK, 256>>>(x1, g1, beta1, x2, x2h);

    // FFN
    gemm_h<1,1><<<dim3(FFDIM / BN, MTOK / BM), 512, GT_SMEM>>>(
        x2h, W1T, b1, nullptr, hh, MTOK, FFDIM, DDIM);
    gemm_h<2,0><<<dim3(DDIM / BN, MTOK / BM), 512, GT_SMEM>>>(
        hh, W2T, b2, x2, x3, MTOK, DDIM, FFDIM);

    // LN2 -> output
    ln_kernel<<<MTOK, 256>>>(x3, g2, beta2, out, nullptr);
}

// round 9
// speedup vs baseline: 5.0479x; 1.2361x over previous
#include <cuda_runtime.h>
#include <cuda_fp16.h>
#include <math.h>
#include <cstdint>

// ---------------------------------------------------------------------------
// Transformer block. All GEMMs + attention via mma.sync fp16 (fp32 accum).
// M=4096, D=1024, H=16, hd=64, FF=4096.
// ---------------------------------------------------------------------------

#define MTOK 4096
#define DDIM 1024
#define QKVD 3072
#define FFDIM 4096
#define NHEAD 16
#define HDIM 64
#define SEQ 2048
#define BATCH 2

// scratch layout (units: floats)
#define OFF_QKVH  ((size_t)0)                                  // f16 [4096,3072]
#define OFF_X1    (OFF_QKVH + (size_t)MTOK*QKVD/2)             // f32
#define OFF_X2    (OFF_X1   + (size_t)MTOK*DDIM)               // f32
#define OFF_X3    (OFF_X2   + (size_t)MTOK*DDIM)               // f32
#define OFF_ATTH  (OFF_X3   + (size_t)MTOK*DDIM)               // f16
#define OFF_X2H   (OFF_ATTH + (size_t)MTOK*DDIM/2)             // f16
#define OFF_HH    (OFF_X2H  + (size_t)MTOK*DDIM/2)             // f16 [4096,4096]
#define OFF_XH    (OFF_HH   + (size_t)MTOK*FFDIM/2)            // f16
#define OFF_WQKVT (OFF_XH   + (size_t)MTOK*DDIM/2)             // f16 [3072,1024]
#define OFF_WOT   (OFF_WQKVT+ (size_t)QKVD*DDIM/2)             // f16
#define OFF_W1T   (OFF_WOT  + (size_t)DDIM*DDIM/2)             // f16
#define OFF_W2T   (OFF_W1T  + (size_t)DDIM*FFDIM/2)            // f16
#define OFF_BQKV  (OFF_W2T  + (size_t)FFDIM*DDIM/2)            // f32 [3072]
#define SCRATCH_FLOATS (OFF_BQKV + (size_t)QKVD)

__device__ float g_scratch[SCRATCH_FLOATS];

// ---------------- PTX helpers ----------------
__device__ __forceinline__ void cp_async16(uint32_t dst, const void* src) {
    asm volatile("cp.async.cg.shared.global [%0], [%1], 16;"
                 :: "r"(dst), "l"(src) : "memory");
}
__device__ __forceinline__ void cp_commit() {
    asm volatile("cp.async.commit_group;" ::: "memory");
}
__device__ __forceinline__ void cp_wait0() {
    asm volatile("cp.async.wait_group 0;" ::: "memory");
}
__device__ __forceinline__ void cp_wait1() {
    asm volatile("cp.async.wait_group 1;" ::: "memory");
}
__device__ __forceinline__ uint32_t smem_u32(const void* p) {
    uint32_t a;
    asm("{ .reg .u64 t; cvta.to.shared.u64 t, %1; cvt.u32.u64 %0, t; }"
        : "=r"(a) : "l"(p));
    return a;
}
__device__ __forceinline__ void mma_f16(float* c, const uint32_t* a,
                                        const uint32_t* b) {
    asm volatile(
        "mma.sync.aligned.m16n8k16.row.col.f32.f16.f16.f32 "
        "{%0,%1,%2,%3}, {%4,%5,%6,%7}, {%8,%9}, {%0,%1,%2,%3};"
        : "+f"(c[0]), "+f"(c[1]), "+f"(c[2]), "+f"(c[3])
        : "r"(a[0]), "r"(a[1]), "r"(a[2]), "r"(a[3]), "r"(b[0]), "r"(b[1]));
}
__device__ __forceinline__ void ldmatrix_x4_trans(uint32_t* r, uint32_t addr) {
    asm volatile(
        "ldmatrix.sync.aligned.m8n8.x4.trans.shared.b16 {%0,%1,%2,%3}, [%4];"
        : "=r"(r[0]), "=r"(r[1]), "=r"(r[2]), "=r"(r[3]) : "r"(addr));
}

// Fast exp on the FMA pipe (no MUFU).
__device__ __forceinline__ float fexp(float x) {
    float t = x * 1.4426950408889634f;
    t = fmaxf(t, -126.0f);
    const float fn = rintf(t);
    const float f = t - fn;
    float p = 1.33336500e-3f;
    p = fmaf(p, f, 9.61823766e-3f);
    p = fmaf(p, f, 5.55041087e-2f);
    p = fmaf(p, f, 2.40226507e-1f);
    p = fmaf(p, f, 6.93147182e-1f);
    p = fmaf(p, f, 1.0f);
    const int n = (int)fn;
    return p * __int_as_float((n + 127) << 23);
}

// ---------------------------------------------------------------------------
// fp16 GEMM: C[M,N] = A[M,K] @ Bt[N,K]^T + bias (+ epilogue)
// CTA 256x128, BK=32 halfs, 512 threads, double-buffered cp.async.
// ---------------------------------------------------------------------------
#define BM 256
#define BN 128
#define S2 36
#define ATILE_H (256 * 72)
#define BTILE_H (128 * 72)
#define GT_SMEM ((2 * ATILE_H + 2 * BTILE_H) * 2)

template <int EPI, int HOUT>
__global__ __launch_bounds__(512)
void gemm_h(const __half* __restrict__ A, const __half* __restrict__ Bt,
            const float* __restrict__ bias, const float* __restrict__ res,
            void* __restrict__ Cout, int M, int N, int K)
{
    extern __shared__ __half smh[];
    __half* As = smh;
    __half* Bs = smh + 2 * ATILE_H;
    const uint32_t As_u = smem_u32(As);
    const uint32_t Bs_u = smem_u32(Bs);

    const int tid  = threadIdx.x;
    const int warp = tid >> 5;
    const int lane = tid & 31;
    const int g    = lane >> 2;
    const int t4   = lane & 3;
    const int wm   = warp >> 2;
    const int wn   = warp & 3;

    const int m0 = blockIdx.y * BM;
    const int n0 = blockIdx.x * BN;

    const int arow = tid >> 1;
    const int a16  = (tid & 1) * 2;
    const __half* Ag = A + (size_t)(m0 + arow) * K + a16 * 8;
    const uint32_t Asm = As_u + (uint32_t)(arow * 144 + a16 * 16);
    const int brow = tid >> 2;
    const int b16  = tid & 3;
    const __half* Bg = Bt + (size_t)(n0 + brow) * K + b16 * 8;
    const uint32_t Bsm = Bs_u + (uint32_t)(brow * 144 + b16 * 16);

    float acc[4][4][4];
#pragma unroll
    for (int mi = 0; mi < 4; mi++)
#pragma unroll
        for (int ni = 0; ni < 4; ni++)
#pragma unroll
            for (int r = 0; r < 4; r++) acc[mi][ni][r] = 0.0f;

    const int T = K >> 5;

    cp_async16(Asm, Ag);
    cp_async16(Asm + 16, Ag + 8);
    cp_async16(Bsm, Bg);
    cp_commit();

    for (int tb = 0; tb < T; tb++) {
        const int b = tb & 1;
        if (tb + 1 < T) {
            const uint32_t ao = (uint32_t)((b ^ 1) * ATILE_H) * 2;
            const uint32_t bo = (uint32_t)((b ^ 1) * BTILE_H) * 2;
            const size_t ko = (size_t)(tb + 1) * 32;
            cp_async16(Asm + ao, Ag + ko);
            cp_async16(Asm + ao + 16, Ag + ko + 8);
            cp_async16(Bsm + bo, Bg + ko);
            cp_commit();
            cp_wait1();
        } else {
            cp_wait0();
        }
        __syncthreads();

        const uint32_t* a2 = (const uint32_t*)(As + b * ATILE_H) + (wm * 64) * S2;
        const uint32_t* b2 = (const uint32_t*)(Bs + b * BTILE_H) + (wn * 32) * S2;
#pragma unroll
        for (int kk = 0; kk < 2; kk++) {
            const int kb = kk * 8 + t4;
            uint32_t af[4][4], bf[4][2];
#pragma unroll
            for (int mi = 0; mi < 4; mi++) {
                const uint32_t* p = a2 + (mi * 16 + g) * S2 + kb;
                af[mi][0] = p[0];
                af[mi][1] = p[8 * S2];
                af[mi][2] = p[4];
                af[mi][3] = p[8 * S2 + 4];
            }
#pragma unroll
            for (int ni = 0; ni < 4; ni++) {
                const uint32_t* p = b2 + (ni * 8 + g) * S2 + kb;
                bf[ni][0] = p[0];
                bf[ni][1] = p[4];
            }
#pragma unroll
            for (int mi = 0; mi < 4; mi++)
#pragma unroll
                for (int ni = 0; ni < 4; ni++)
                    mma_f16(acc[mi][ni], af[mi], bf[ni]);
        }
        __syncthreads();
    }

    float* Cf = (float*)Cout;
    __half* Ch = (__half*)Cout;
#pragma unroll
    for (int mi = 0; mi < 4; mi++) {
        const int row0 = m0 + wm * 64 + mi * 16 + g;
#pragma unroll
        for (int ni = 0; ni < 4; ni++) {
            const int col = n0 + wn * 32 + ni * 8 + t4 * 2;
            const float b0 = bias[col], b1 = bias[col + 1];
            float v0 = acc[mi][ni][0] + b0;
            float v1 = acc[mi][ni][1] + b1;
            float v2 = acc[mi][ni][2] + b0;
            float v3 = acc[mi][ni][3] + b1;
            if (EPI == 1) {
                v0 = 0.5f * v0 * (1.0f + erff(v0 * 0.70710678118654752f));
                v1 = 0.5f * v1 * (1.0f + erff(v1 * 0.70710678118654752f));
                v2 = 0.5f * v2 * (1.0f + erff(v2 * 0.70710678118654752f));
                v3 = 0.5f * v3 * (1.0f + erff(v3 * 0.70710678118654752f));
            } else if (EPI == 2) {
                const float2 r0 = *(const float2*)(res + (size_t)row0 * N + col);
                const float2 r1 = *(const float2*)(res + (size_t)(row0 + 8) * N + col);
                v0 += r0.x; v1 += r0.y; v2 += r1.x; v3 += r1.y;
            }
            if (HOUT) {
                *(__half2*)(Ch + (size_t)row0 * N + col) = __floats2half2_rn(v0, v1);
                *(__half2*)(Ch + (size_t)(row0 + 8) * N + col) = __floats2half2_rn(v2, v3);
            } else {
                *(float2*)(Cf + (size_t)row0 * N + col) = make_float2(v0, v1);
                *(float2*)(Cf + (size_t)(row0 + 8) * N + col) = make_float2(v2, v3);
            }
        }
    }
}

// ---------------------------------------------------------------------------
// Transpose weights to [N][K] fp16
// ---------------------------------------------------------------------------
__global__ __launch_bounds__(256)
void transpose_h_kernel(const float* __restrict__ in, __half* __restrict__ out,
                        int R, int C)
{
    __shared__ float t[32][33];
    const int c0 = blockIdx.x * 32, r0 = blockIdx.y * 32;
    const int tx = threadIdx.x & 31, ty = threadIdx.x >> 5;
#pragma unroll
    for (int i = ty; i < 32; i += 8)
        t[i][tx] = in[(size_t)(r0 + i) * C + c0 + tx];
    __syncthreads();
#pragma unroll
    for (int i = ty; i < 32; i += 8)
        out[(size_t)(c0 + i) * R + r0 + tx] = __float2half_rn(t[tx][i]);
}

__global__ void bias_concat_kernel(const float* __restrict__ bq,
                                   const float* __restrict__ bk,
                                   const float* __restrict__ bv,
                                   float* __restrict__ bqkv)
{
    const int i = blockIdx.x * 256 + threadIdx.x;
    if (i < DDIM) bqkv[i] = bq[i];
    else if (i < 2 * DDIM) bqkv[i] = bk[i - DDIM];
    else bqkv[i] = bv[i - 2 * DDIM];
}

__global__ __launch_bounds__(256)
void f2h_kernel(const float* __restrict__ in, __half* __restrict__ out)
{
    const int i = blockIdx.x * 256 + threadIdx.x;
    const float4 v = ((const float4*)in)[i];
    ((__half2*)out)[2 * i]     = __floats2half2_rn(v.x, v.y);
    ((__half2*)out)[2 * i + 1] = __floats2half2_rn(v.z, v.w);
}

// ---------------------------------------------------------------------------
// fp16 tensor-core flash attention (no scaling). QKV fp16 (stride QKVD),
// writes fp16 att. smem: P [128][136]h, K/V [2][128][72]h each.
// ---------------------------------------------------------------------------
#define SPW 68            // P stride in 32-bit words (136 halfs)
#define SKW 36            // K/V stride in 32-bit words (72 halfs)
#define NKB (SEQ / 128)
#define AT_P_BYTES (128 * 136 * 2)
#define AT_K_BYTES (2 * 128 * 144)
#define AT_SMEM (AT_P_BYTES + 2 * AT_K_BYTES)   // 108544

__global__ __launch_bounds__(256)
void attn_h_kernel(const __half* __restrict__ QKV, __half* __restrict__ O)
{
    extern __shared__ char smc[];
    __half* sP = (__half*)smc;                       // [128][136]
    __half* sK = (__half*)(smc + AT_P_BYTES);        // [2][128][72]
    __half* sV = (__half*)(smc + AT_P_BYTES + AT_K_BYTES);
    const uint32_t sP_u = smem_u32(sP);
    const uint32_t sK_u = smem_u32(sK);
    const uint32_t sV_u = smem_u32(sV);

    const int bz   = blockIdx.z;
    const int h    = blockIdx.y;
    const int q0   = blockIdx.x * 128;
    const int tid  = threadIdx.x;
    const int warp = tid >> 5;
    const int lane = tid & 31;
    const int g    = lane >> 2;
    const int t4   = lane & 3;

    const size_t base = (size_t)bz * SEQ;
    const __half* Qg = QKV + (base + q0) * QKVD + h * HDIM;
    const __half* Kg = QKV + base * QKVD + DDIM + h * HDIM;
    const __half* Vg = QKV + base * QKVD + 2 * DDIM + h * HDIM;

    // stage Q tile [128][64]h into sP region (stride 72 halfs)
    for (int i = tid; i < 128 * 8; i += 256) {
        const int r = i >> 3, c = (i & 7) * 8;
        *(uint4*)(sP + r * 72 + c) = *(const uint4*)(Qg + (size_t)r * QKVD + c);
    }
    __syncthreads();

    // Q fragments: 4 k-steps of 16 dims
    uint32_t qf[4][4];
    {
        const uint32_t* qrow = (const uint32_t*)sP + (warp * 16 + g) * SKW;
#pragma unroll
        for (int ks = 0; ks < 4; ks++) {
            qf[ks][0] = qrow[ks * 8 + t4];
            qf[ks][1] = qrow[8 * SKW + ks * 8 + t4];
            qf[ks][2] = qrow[ks * 8 + t4 + 4];
            qf[ks][3] = qrow[8 * SKW + ks * 8 + t4 + 4];
        }
    }
    __syncthreads();

    float oacc[8][4];
#pragma unroll
    for (int n = 0; n < 8; n++)
#pragma unroll
        for (int r = 0; r < 4; r++) oacc[n][r] = 0.0f;
    float m0 = -1e30f, m1 = -1e30f, l0 = 0.0f, l1 = 0.0f;

    // ldmatrix per-lane base offset for V (within a tile)
    const int lmat = lane >> 3;             // 0..3
    const int lrow = lane & 7;
    const uint32_t vlane = (uint32_t)(((lmat & 1) * 8 + lrow) * 144 +
                                      ((lmat >> 1) * 8) * 2);

    // prologue K/V tiles: 128 rows x 8 chunks of 16B, 256 thr x 4
#pragma unroll
    for (int i = 0; i < 4; i++) {
        const int idx = tid + i * 256;
        const int r = idx >> 3, c = (idx & 7) * 8;
        cp_async16(sK_u + (uint32_t)(r * 144 + c * 2), Kg + (size_t)r * QKVD + c);
        cp_async16(sV_u + (uint32_t)(r * 144 + c * 2), Vg + (size_t)r * QKVD + c);
    }
    cp_commit();

    for (int kb = 0; kb < NKB; kb++) {
        const int buf = kb & 1;

        if (kb + 1 < NKB) {
            const __half* Kt = Kg + (size_t)(kb + 1) * 128 * QKVD;
            const __half* Vt = Vg + (size_t)(kb + 1) * 128 * QKVD;
            const uint32_t so = (uint32_t)((buf ^ 1) * 128 * 144);
#pragma unroll
            for (int i = 0; i < 4; i++) {
                const int idx = tid + i * 256;
                const int r = idx >> 3, c = (idx & 7) * 8;
                cp_async16(sK_u + so + (uint32_t)(r * 144 + c * 2),
                           Kt + (size_t)r * QKVD + c);
                cp_async16(sV_u + so + (uint32_t)(r * 144 + c * 2),
                           Vt + (size_t)r * QKVD + c);
            }
            cp_commit();
            cp_wait1();
        } else {
            cp_wait0();
        }
        __syncthreads();

        // ---- S = Q @ K^T (16 x 128 per warp) ----
        float sc[16][4];
#pragma unroll
        for (int nt = 0; nt < 16; nt++) {
#pragma unroll
            for (int r = 0; r < 4; r++) sc[nt][r] = 0.0f;
        }
        const uint32_t* kwords = (const uint32_t*)(sK + buf * 128 * 72);
#pragma unroll
        for (int nt = 0; nt < 16; nt++) {
            const uint32_t* kp = kwords + (nt * 8 + g) * SKW;
#pragma unroll
            for (int ks = 0; ks < 4; ks++) {
                uint32_t bf[2];
                bf[0] = kp[ks * 8 + t4];
                bf[1] = kp[ks * 8 + t4 + 4];
                mma_f16(sc[nt], qf[ks], bf);
            }
        }

        // ---- online softmax ----
        float mx0 = m0, mx1 = m1;
#pragma unroll
        for (int nt = 0; nt < 16; nt++) {
            mx0 = fmaxf(mx0, fmaxf(sc[nt][0], sc[nt][1]));
            mx1 = fmaxf(mx1, fmaxf(sc[nt][2], sc[nt][3]));
        }
        mx0 = fmaxf(mx0, __shfl_xor_sync(0xffffffffu, mx0, 1));
        mx0 = fmaxf(mx0, __shfl_xor_sync(0xffffffffu, mx0, 2));
        mx1 = fmaxf(mx1, __shfl_xor_sync(0xffffffffu, mx1, 1));
        mx1 = fmaxf(mx1, __shfl_xor_sync(0xffffffffu, mx1, 2));

        const float s0 = fexp(m0 - mx0);
        const float s1 = fexp(m1 - mx1);
        m0 = mx0; m1 = mx1;
        l0 *= s0;  l1 *= s1;
#pragma unroll
        for (int n = 0; n < 8; n++) {
            oacc[n][0] *= s0; oacc[n][1] *= s0;
            oacc[n][2] *= s1; oacc[n][3] *= s1;
        }

        const int prow = warp * 16 + g;
        uint32_t* pw0 = (uint32_t*)sP + prow * SPW;
        uint32_t* pw1 = (uint32_t*)sP + (prow + 8) * SPW;
        float ls0 = 0.0f, ls1 = 0.0f;
#pragma unroll
        for (int nt = 0; nt < 16; nt++) {
            const float p0 = fexp(sc[nt][0] - mx0);
            const float p1 = fexp(sc[nt][1] - mx0);
            const float p2 = fexp(sc[nt][2] - mx1);
            const float p3 = fexp(sc[nt][3] - mx1);
            ls0 += p0 + p1;
            ls1 += p2 + p3;
            const __half2 h01 = __floats2half2_rn(p0, p1);
            const __half2 h23 = __floats2half2_rn(p2, p3);
            pw0[nt * 4 + t4] = *(const uint32_t*)&h01;
            pw1[nt * 4 + t4] = *(const uint32_t*)&h23;
        }
        l0 += ls0; l1 += ls1;
        __syncthreads();

        // ---- O += P @ V (16 x 64 per warp, k = 128 keys) ----
        const uint32_t vbase = sV_u + (uint32_t)(buf * 128 * 144) + vlane;
        const uint32_t* pa0 = (const uint32_t*)sP + prow * SPW + t4;
        const uint32_t* pa1 = (const uint32_t*)sP + (prow + 8) * SPW + t4;
#pragma unroll
        for (int ks = 0; ks < 8; ks++) {
            uint32_t af[4];
            af[0] = pa0[ks * 8];
            af[1] = pa1[ks * 8];
            af[2] = pa0[ks * 8 + 4];
            af[3] = pa1[ks * 8 + 4];
            const uint32_t vks = vbase + (uint32_t)(ks * 16 * 144);
#pragma unroll
            for (int nt2 = 0; nt2 < 4; nt2++) {
                uint32_t vr[4];
                ldmatrix_x4_trans(vr, vks + (uint32_t)(nt2 * 32));
                mma_f16(oacc[nt2 * 2],     af, vr);
                mma_f16(oacc[nt2 * 2 + 1], af, vr + 2);
            }
        }
        __syncthreads();
    }

    l0 += __shfl_xor_sync(0xffffffffu, l0, 1);
    l0 += __shfl_xor_sync(0xffffffffu, l0, 2);
    l1 += __shfl_xor_sync(0xffffffffu, l1, 1);
    l1 += __shfl_xor_sync(0xffffffffu, l1, 2);
    const float inv0 = 1.0f / l0;
    const float inv1 = 1.0f / l1;

    const size_t row = base + q0 + warp * 16 + g;
    __half* Og = O + row * DDIM + h * HDIM;
#pragma unroll
    for (int nt = 0; nt < 8; nt++) {
        const int col = nt * 8 + 2 * t4;
        *(__half2*)(Og + col) =
            __floats2half2_rn(oacc[nt][0] * inv0, oacc[nt][1] * inv0);
        *(__half2*)(Og + 8 * DDIM + col) =
            __floats2half2_rn(oacc[nt][2] * inv1, oacc[nt][3] * inv1);
    }
}

// ---------------------------------------------------------------------------
// LayerNorm (D=1024), one block per row; optional fp16 twin output.
// ---------------------------------------------------------------------------
__global__ __launch_bounds__(256)
void ln_kernel(const float* __restrict__ x, const float* __restrict__ g,
               const float* __restrict__ b, float* __restrict__ y,
               __half* __restrict__ yh)
{
    const int D = DDIM;
    const int row = blockIdx.x;
    const float* xr = x + (size_t)row * D;

    float v[4];
    float s = 0.f, s2 = 0.f;
#pragma unroll
    for (int i = 0; i < 4; i++) {
        v[i] = xr[threadIdx.x + i * 256];
        s += v[i];
        s2 = fmaf(v[i], v[i], s2);
    }
#pragma unroll
    for (int o = 16; o > 0; o >>= 1) {
        s  += __shfl_xor_sync(0xffffffffu, s, o);
        s2 += __shfl_xor_sync(0xffffffffu, s2, o);
    }
    __shared__ float ss[8], ss2[8];
    const int w = threadIdx.x >> 5;
    if ((threadIdx.x & 31) == 0) { ss[w] = s; ss2[w] = s2; }
    __syncthreads();
    if (threadIdx.x < 32) {
        s  = (threadIdx.x < 8) ? ss[threadIdx.x]  : 0.f;
        s2 = (threadIdx.x < 8) ? ss2[threadIdx.x] : 0.f;
#pragma unroll
        for (int o = 4; o > 0; o >>= 1) {
            s  += __shfl_xor_sync(0xffffffffu, s, o);
            s2 += __shfl_xor_sync(0xffffffffu, s2, o);
        }
        if (threadIdx.x == 0) { ss[0] = s; ss2[0] = s2; }
    }
    __syncthreads();
    const float mu  = ss[0] * (1.0f / D);
    const float var = ss2[0] * (1.0f / D) - mu * mu;
    const float inv = rsqrtf(var + 1e-5f);
#pragma unroll
    for (int i = 0; i < 4; i++) {
        const int c = threadIdx.x + i * 256;
        const float val = (v[i] - mu) * inv * g[c] + b[c];
        y[(size_t)row * D + c] = val;
        if (yh) yh[(size_t)row * D + c] = __float2half_rn(val);
    }
}

// ---------------------------------------------------------------------------
// Launch
// ---------------------------------------------------------------------------
extern "C" void kernel_launch(void* const* d_in, const int* in_sizes, int n_in,
                              void* d_out, int out_size)
{
    (void)in_sizes; (void)n_in; (void)out_size;
    const float* x     = (const float*)d_in[0];
    const float* Wq    = (const float*)d_in[1];
    const float* bq    = (const float*)d_in[2];
    const float* Wk    = (const float*)d_in[3];
    const float* bk    = (const float*)d_in[4];
    const float* Wv    = (const float*)d_in[5];
    const float* bv    = (const float*)d_in[6];
    const float* Wo    = (const float*)d_in[7];
    const float* bo    = (const float*)d_in[8];
    const float* W1    = (const float*)d_in[9];
    const float* b1    = (const float*)d_in[10];
    const float* W2    = (const float*)d_in[11];
    const float* b2    = (const float*)d_in[12];
    const float* g1    = (const float*)d_in[13];
    const float* beta1 = (const float*)d_in[14];
    const float* g2    = (const float*)d_in[15];
    const float* beta2 = (const float*)d_in[16];
    float* out = (float*)d_out;

    float* scr = nullptr;
    cudaGetSymbolAddress((void**)&scr, g_scratch);
    __half* qkvh  = (__half*)(scr + OFF_QKVH);
    float*  x1    = scr + OFF_X1;
    float*  x2    = scr + OFF_X2;
    float*  x3    = scr + OFF_X3;
    __half* atth  = (__half*)(scr + OFF_ATTH);
    __half* x2h   = (__half*)(scr + OFF_X2H);
    __half* hh    = (__half*)(scr + OFF_HH);
    __half* xh    = (__half*)(scr + OFF_XH);
    __half* WqkvT = (__half*)(scr + OFF_WQKVT);
    __half* WoT   = (__half*)(scr + OFF_WOT);
    __half* W1T   = (__half*)(scr + OFF_W1T);
    __half* W2T   = (__half*)(scr + OFF_W2T);
    float*  bqkv  = scr + OFF_BQKV;

    cudaFuncSetAttribute(gemm_h<0,1>, cudaFuncAttributeMaxDynamicSharedMemorySize, GT_SMEM);
    cudaFuncSetAttribute(gemm_h<1,1>, cudaFuncAttributeMaxDynamicSharedMemorySize, GT_SMEM);
    cudaFuncSetAttribute(gemm_h<2,0>, cudaFuncAttributeMaxDynamicSharedMemorySize, GT_SMEM);
    cudaFuncSetAttribute(attn_h_kernel, cudaFuncAttributeMaxDynamicSharedMemorySize, AT_SMEM);

    // prep
    f2h_kernel<<<(MTOK * DDIM / 4) / 256, 256>>>(x, xh);
    transpose_h_kernel<<<dim3(DDIM / 32, DDIM / 32), 256>>>(Wq, WqkvT, DDIM, DDIM);
    transpose_h_kernel<<<dim3(DDIM / 32, DDIM / 32), 256>>>(Wk, WqkvT + (size_t)DDIM * DDIM, DDIM, DDIM);
    transpose_h_kernel<<<dim3(DDIM / 32, DDIM / 32), 256>>>(Wv, WqkvT + (size_t)2 * DDIM * DDIM, DDIM, DDIM);
    transpose_h_kernel<<<dim3(DDIM / 32, DDIM / 32), 256>>>(Wo, WoT, DDIM, DDIM);
    transpose_h_kernel<<<dim3(FFDIM / 32, DDIM / 32), 256>>>(W1, W1T, DDIM, FFDIM);
    transpose_h_kernel<<<dim3(DDIM / 32, FFDIM / 32), 256>>>(W2, W2T, FFDIM, DDIM);
    bias_concat_kernel<<<QKVD / 256, 256>>>(bq, bk, bv, bqkv);

    // fused QKV projection -> fp16
    gemm_h<0,1><<<dim3(QKVD / BN, MTOK / BM), 512, GT_SMEM>>>(
        xh, WqkvT, bqkv, nullptr, qkvh, MTOK, QKVD, DDIM);

    // attention (fp16 tensor cores, no scaling)
    attn_h_kernel<<<dim3(SEQ / 128, NHEAD, BATCH), 256, AT_SMEM>>>(qkvh, atth);

    // output projection + residual
    gemm_h<2,0><<<dim3(DDIM / BN, MTOK / BM), 512, GT_SMEM>>>(
        atth, WoT, bo, x, x1, MTOK, DDIM, DDIM);

    // LN1
    ln_kernel<<<MTOK, 256>>>(x1, g1, beta1, x2, x2h);

    // FFN
    gemm_h<1,1><<<dim3(FFDIM / BN, MTOK / BM), 512, GT_SMEM>>>(
        x2h, W1T, b1, nullptr, hh, MTOK, FFDIM, DDIM);
    gemm_h<2,0><<<dim3(DDIM / BN, MTOK / BM), 512, GT_SMEM>>>(
        hh, W2T, b2, x2, x3, MTOK, DDIM, FFDIM);

    // LN2 -> output
    ln_kernel<<<MTOK, 256>>>(x3, g2, beta2, out, nullptr);
}

// round 10
// speedup vs baseline: 5.1077x; 1.0118x over previous
#include <cuda_runtime.h>
#include <cuda_fp16.h>
#include <math.h>
#include <cstdint>

// ---------------------------------------------------------------------------
// Transformer block. All GEMMs + attention via mma.sync fp16 (fp32 accum),
// fragment loads via ldmatrix. M=4096, D=1024, H=16, hd=64, FF=4096.
// ---------------------------------------------------------------------------

#define MTOK 4096
#define DDIM 1024
#define QKVD 3072
#define FFDIM 4096
#define NHEAD 16
#define HDIM 64
#define SEQ 2048
#define BATCH 2

// scratch layout (units: floats)
#define OFF_QKVH  ((size_t)0)
#define OFF_X1    (OFF_QKVH + (size_t)MTOK*QKVD/2)
#define OFF_X2    (OFF_X1   + (size_t)MTOK*DDIM)
#define OFF_X3    (OFF_X2   + (size_t)MTOK*DDIM)
#define OFF_ATTH  (OFF_X3   + (size_t)MTOK*DDIM)
#define OFF_X2H   (OFF_ATTH + (size_t)MTOK*DDIM/2)
#define OFF_HH    (OFF_X2H  + (size_t)MTOK*DDIM/2)
#define OFF_XH    (OFF_HH   + (size_t)MTOK*FFDIM/2)
#define OFF_WQKVT (OFF_XH   + (size_t)MTOK*DDIM/2)
#define OFF_WOT   (OFF_WQKVT+ (size_t)QKVD*DDIM/2)
#define OFF_W1T   (OFF_WOT  + (size_t)DDIM*DDIM/2)
#define OFF_W2T   (OFF_W1T  + (size_t)DDIM*FFDIM/2)
#define OFF_BQKV  (OFF_W2T  + (size_t)FFDIM*DDIM/2)
#define SCRATCH_FLOATS (OFF_BQKV + (size_t)QKVD)

__device__ float g_scratch[SCRATCH_FLOATS];

// ---------------- PTX helpers ----------------
__device__ __forceinline__ void cp_async16(uint32_t dst, const void* src) {
    asm volatile("cp.async.cg.shared.global [%0], [%1], 16;"
                 :: "r"(dst), "l"(src) : "memory");
}
__device__ __forceinline__ void cp_commit() {
    asm volatile("cp.async.commit_group;" ::: "memory");
}
__device__ __forceinline__ void cp_wait0() {
    asm volatile("cp.async.wait_group 0;" ::: "memory");
}
__device__ __forceinline__ void cp_wait1() {
    asm volatile("cp.async.wait_group 1;" ::: "memory");
}
__device__ __forceinline__ uint32_t smem_u32(const void* p) {
    uint32_t a;
    asm("{ .reg .u64 t; cvta.to.shared.u64 t, %1; cvt.u32.u64 %0, t; }"
        : "=r"(a) : "l"(p));
    return a;
}
__device__ __forceinline__ void mma_f16(float* c, const uint32_t* a,
                                        const uint32_t* b) {
    asm volatile(
        "mma.sync.aligned.m16n8k16.row.col.f32.f16.f16.f32 "
        "{%0,%1,%2,%3}, {%4,%5,%6,%7}, {%8,%9}, {%0,%1,%2,%3};"
        : "+f"(c[0]), "+f"(c[1]), "+f"(c[2]), "+f"(c[3])
        : "r"(a[0]), "r"(a[1]), "r"(a[2]), "r"(a[3]), "r"(b[0]), "r"(b[1]));
}
__device__ __forceinline__ void ldmx4(uint32_t* r, uint32_t addr) {
    asm volatile(
        "ldmatrix.sync.aligned.m8n8.x4.shared.b16 {%0,%1,%2,%3}, [%4];"
        : "=r"(r[0]), "=r"(r[1]), "=r"(r[2]), "=r"(r[3]) : "r"(addr));
}
__device__ __forceinline__ void ldmx4_trans(uint32_t* r, uint32_t addr) {
    asm volatile(
        "ldmatrix.sync.aligned.m8n8.x4.trans.shared.b16 {%0,%1,%2,%3}, [%4];"
        : "=r"(r[0]), "=r"(r[1]), "=r"(r[2]), "=r"(r[3]) : "r"(addr));
}

// Fast exp on the FMA pipe (no MUFU).
__device__ __forceinline__ float fexp(float x) {
    float t = x * 1.4426950408889634f;
    t = fmaxf(t, -126.0f);
    const float fn = rintf(t);
    const float f = t - fn;
    float p = 1.33336500e-3f;
    p = fmaf(p, f, 9.61823766e-3f);
    p = fmaf(p, f, 5.55041087e-2f);
    p = fmaf(p, f, 2.40226507e-1f);
    p = fmaf(p, f, 6.93147182e-1f);
    p = fmaf(p, f, 1.0f);
    const int n = (int)fn;
    return p * __int_as_float((n + 127) << 23);
}

// ---------------------------------------------------------------------------
// fp16 GEMM: C[M,N] = A[M,K] @ Bt[N,K]^T + bias (+ epilogue)
// CTA 256x128, BK=32 halfs, 512 threads, double-buffered cp.async,
// fragment loads via ldmatrix.x4 (row stride 144 B: conflict-free).
// ---------------------------------------------------------------------------
#define BM 256
#define BN 128
#define ATILE_B (256 * 144)        // bytes per A buffer
#define BTILE_B (128 * 144)
#define GT_SMEM (2 * ATILE_B + 2 * BTILE_B)

template <int EPI, int HOUT>
__global__ __launch_bounds__(512)
void gemm_h(const __half* __restrict__ A, const __half* __restrict__ Bt,
            const float* __restrict__ bias, const float* __restrict__ res,
            void* __restrict__ Cout, int M, int N, int K)
{
    extern __shared__ __half smh[];
    const uint32_t As_u = smem_u32(smh);
    const uint32_t Bs_u = As_u + 2 * ATILE_B;

    const int tid  = threadIdx.x;
    const int warp = tid >> 5;
    const int lane = tid & 31;
    const int g    = lane >> 2;
    const int t4   = lane & 3;
    const int wm   = warp >> 2;
    const int wn   = warp & 3;

    const int m0 = blockIdx.y * BM;
    const int n0 = blockIdx.x * BN;

    const int arow = tid >> 1;
    const int a16  = (tid & 1) * 2;
    const __half* Ag = A + (size_t)(m0 + arow) * K + a16 * 8;
    const uint32_t Asm = As_u + (uint32_t)(arow * 144 + a16 * 16);
    const int brow = tid >> 2;
    const int b16  = tid & 3;
    const __half* Bg = Bt + (size_t)(n0 + brow) * K + b16 * 8;
    const uint32_t Bsm = Bs_u + (uint32_t)(brow * 144 + b16 * 16);

    // ldmatrix per-lane offsets
    const uint32_t aLane = (uint32_t)((wm * 64 + (lane & 15)) * 144 +
                                      (lane >> 4) * 16);
    const uint32_t bLane = (uint32_t)((wn * 32 + (lane >> 4) * 8 + (lane & 7)) * 144 +
                                      ((lane >> 3) & 1) * 16);

    float acc[4][4][4];
#pragma unroll
    for (int mi = 0; mi < 4; mi++)
#pragma unroll
        for (int ni = 0; ni < 4; ni++)
#pragma unroll
            for (int r = 0; r < 4; r++) acc[mi][ni][r] = 0.0f;

    const int T = K >> 5;

    cp_async16(Asm, Ag);
    cp_async16(Asm + 16, Ag + 8);
    cp_async16(Bsm, Bg);
    cp_commit();

    for (int tb = 0; tb < T; tb++) {
        const int b = tb & 1;
        if (tb + 1 < T) {
            const uint32_t ao = (uint32_t)((b ^ 1) * ATILE_B);
            const uint32_t bo = (uint32_t)((b ^ 1) * BTILE_B);
            const size_t ko = (size_t)(tb + 1) * 32;
            cp_async16(Asm + ao, Ag + ko);
            cp_async16(Asm + ao + 16, Ag + ko + 8);
            cp_async16(Bsm + bo, Bg + ko);
            cp_commit();
            cp_wait1();
        } else {
            cp_wait0();
        }
        __syncthreads();

        const uint32_t aBase = As_u + (uint32_t)(b * ATILE_B) + aLane;
        const uint32_t bBase = Bs_u + (uint32_t)(b * BTILE_B) + bLane;
#pragma unroll
        for (int kk = 0; kk < 2; kk++) {
            uint32_t af[4][4], bf4[2][4];
#pragma unroll
            for (int mi = 0; mi < 4; mi++)
                ldmx4(af[mi], aBase + mi * (16 * 144) + kk * 32);
#pragma unroll
            for (int p = 0; p < 2; p++)
                ldmx4(bf4[p], bBase + p * (16 * 144) + kk * 32);
#pragma unroll
            for (int mi = 0; mi < 4; mi++)
#pragma unroll
                for (int ni = 0; ni < 4; ni++)
                    mma_f16(acc[mi][ni], af[mi], bf4[ni >> 1] + (ni & 1) * 2);
        }
        __syncthreads();
    }

    float* Cf = (float*)Cout;
    __half* Ch = (__half*)Cout;
#pragma unroll
    for (int mi = 0; mi < 4; mi++) {
        const int row0 = m0 + wm * 64 + mi * 16 + g;
#pragma unroll
        for (int ni = 0; ni < 4; ni++) {
            const int col = n0 + wn * 32 + ni * 8 + t4 * 2;
            const float b0 = bias[col], b1 = bias[col + 1];
            float v0 = acc[mi][ni][0] + b0;
            float v1 = acc[mi][ni][1] + b1;
            float v2 = acc[mi][ni][2] + b0;
            float v3 = acc[mi][ni][3] + b1;
            if (EPI == 1) {
                v0 = 0.5f * v0 * (1.0f + erff(v0 * 0.70710678118654752f));
                v1 = 0.5f * v1 * (1.0f + erff(v1 * 0.70710678118654752f));
                v2 = 0.5f * v2 * (1.0f + erff(v2 * 0.70710678118654752f));
                v3 = 0.5f * v3 * (1.0f + erff(v3 * 0.70710678118654752f));
            } else if (EPI == 2) {
                const float2 r0 = *(const float2*)(res + (size_t)row0 * N + col);
                const float2 r1 = *(const float2*)(res + (size_t)(row0 + 8) * N + col);
                v0 += r0.x; v1 += r0.y; v2 += r1.x; v3 += r1.y;
            }
            if (HOUT) {
                *(__half2*)(Ch + (size_t)row0 * N + col) = __floats2half2_rn(v0, v1);
                *(__half2*)(Ch + (size_t)(row0 + 8) * N + col) = __floats2half2_rn(v2, v3);
            } else {
                *(float2*)(Cf + (size_t)row0 * N + col) = make_float2(v0, v1);
                *(float2*)(Cf + (size_t)(row0 + 8) * N + col) = make_float2(v2, v3);
            }
        }
    }
}

// ---------------------------------------------------------------------------
// Merged weight prep: all 6 transposes in ONE kernel (fp32 -> fp16^T).
// blocks [0,4096): Wq/Wk/Wv/Wo (1024x1024 each); [4096,8192): W1 (1024x4096);
// [8192,12288): W2 (4096x1024).
// ---------------------------------------------------------------------------
__global__ __launch_bounds__(256)
void prep_weights(const float* __restrict__ Wq, const float* __restrict__ Wk,
                  const float* __restrict__ Wv, const float* __restrict__ Wo,
                  const float* __restrict__ W1, const float* __restrict__ W2,
                  __half* __restrict__ WqkvT, __half* __restrict__ WoT,
                  __half* __restrict__ W1T, __half* __restrict__ W2T)
{
    const int b = blockIdx.x;
    const float* in;
    __half* out;
    int R, C, tile;
    if (b < 4096) {
        const int w = b >> 10;
        tile = b & 1023;
        R = 1024; C = 1024;
        in  = (w == 0) ? Wq : (w == 1) ? Wk : (w == 2) ? Wv : Wo;
        out = (w < 3) ? WqkvT + (size_t)w * 1024 * 1024 : WoT;
    } else if (b < 8192) {
        tile = b - 4096; R = 1024; C = 4096; in = W1; out = W1T;
    } else {
        tile = b - 8192; R = 4096; C = 1024; in = W2; out = W2T;
    }
    const int tcx = C >> 5;
    const int c0 = (tile % tcx) * 32, r0 = (tile / tcx) * 32;

    __shared__ float t[32][33];
    const int tx = threadIdx.x & 31, ty = threadIdx.x >> 5;
#pragma unroll
    for (int i = ty; i < 32; i += 8)
        t[i][tx] = in[(size_t)(r0 + i) * C + c0 + tx];
    __syncthreads();
#pragma unroll
    for (int i = ty; i < 32; i += 8)
        out[(size_t)(c0 + i) * R + r0 + tx] = __float2half_rn(t[tx][i]);
}

__global__ void bias_concat_kernel(const float* __restrict__ bq,
                                   const float* __restrict__ bk,
                                   const float* __restrict__ bv,
                                   float* __restrict__ bqkv)
{
    const int i = blockIdx.x * 256 + threadIdx.x;
    if (i < DDIM) bqkv[i] = bq[i];
    else if (i < 2 * DDIM) bqkv[i] = bk[i - DDIM];
    else bqkv[i] = bv[i - 2 * DDIM];
}

__global__ __launch_bounds__(256)
void f2h_kernel(const float* __restrict__ in, __half* __restrict__ out)
{
    const int i = blockIdx.x * 256 + threadIdx.x;
    const float4 v = ((const float4*)in)[i];
    ((__half2*)out)[2 * i]     = __floats2half2_rn(v.x, v.y);
    ((__half2*)out)[2 * i + 1] = __floats2half2_rn(v.z, v.w);
}

// ---------------------------------------------------------------------------
// fp16 tensor-core flash attention (no scaling). ldmatrix for K and V frags.
// ---------------------------------------------------------------------------
#define SPW 68            // P stride in 32-bit words (136 halfs)
#define NKB (SEQ / 128)
#define AT_P_BYTES (128 * 136 * 2)
#define AT_K_BYTES (2 * 128 * 144)
#define AT_SMEM (AT_P_BYTES + 2 * AT_K_BYTES)

__global__ __launch_bounds__(256)
void attn_h_kernel(const __half* __restrict__ QKV, __half* __restrict__ O)
{
    extern __shared__ char smc[];
    __half* sP = (__half*)smc;                       // [128][136]
    const uint32_t sP_u = smem_u32(sP);
    const uint32_t sK_u = sP_u + AT_P_BYTES;
    const uint32_t sV_u = sK_u + AT_K_BYTES;
    __half* sQstage = sP;                            // Q staged at stride 72

    const int bz   = blockIdx.z;
    const int h    = blockIdx.y;
    const int q0   = blockIdx.x * 128;
    const int tid  = threadIdx.x;
    const int warp = tid >> 5;
    const int lane = tid & 31;
    const int g    = lane >> 2;
    const int t4   = lane & 3;

    const size_t base = (size_t)bz * SEQ;
    const __half* Qg = QKV + (base + q0) * QKVD + h * HDIM;
    const __half* Kg = QKV + base * QKVD + DDIM + h * HDIM;
    const __half* Vg = QKV + base * QKVD + 2 * DDIM + h * HDIM;

    // stage Q tile [128][64]h (stride 72 halfs)
    for (int i = tid; i < 128 * 8; i += 256) {
        const int r = i >> 3, c = (i & 7) * 8;
        *(uint4*)(sQstage + r * 72 + c) = *(const uint4*)(Qg + (size_t)r * QKVD + c);
    }
    __syncthreads();

    // Q fragments: 4 k-steps of 16 dims (scalar loads, one time)
    uint32_t qf[4][4];
    {
        const uint32_t* qrow = (const uint32_t*)sQstage + (warp * 16 + g) * 36;
#pragma unroll
        for (int ks = 0; ks < 4; ks++) {
            qf[ks][0] = qrow[ks * 8 + t4];
            qf[ks][1] = qrow[8 * 36 + ks * 8 + t4];
            qf[ks][2] = qrow[ks * 8 + t4 + 4];
            qf[ks][3] = qrow[8 * 36 + ks * 8 + t4 + 4];
        }
    }
    __syncthreads();

    float oacc[8][4];
#pragma unroll
    for (int n = 0; n < 8; n++)
#pragma unroll
        for (int r = 0; r < 4; r++) oacc[n][r] = 0.0f;
    float m0 = -1e30f, m1 = -1e30f, l0 = 0.0f, l1 = 0.0f;

    // ldmatrix per-lane offsets
    const uint32_t kLane = (uint32_t)(((lane >> 4) * 8 + (lane & 7)) * 144 +
                                      ((lane >> 3) & 1) * 16);
    const int lmat = lane >> 3;
    const int lrow = lane & 7;
    const uint32_t vLane = (uint32_t)(((lmat & 1) * 8 + lrow) * 144 +
                                      ((lmat >> 1) * 8) * 2);

    // prologue K/V tiles
#pragma unroll
    for (int i = 0; i < 4; i++) {
        const int idx = tid + i * 256;
        const int r = idx >> 3, c = (idx & 7) * 8;
        cp_async16(sK_u + (uint32_t)(r * 144 + c * 2), Kg + (size_t)r * QKVD + c);
        cp_async16(sV_u + (uint32_t)(r * 144 + c * 2), Vg + (size_t)r * QKVD + c);
    }
    cp_commit();

    for (int kb = 0; kb < NKB; kb++) {
        const int buf = kb & 1;

        if (kb + 1 < NKB) {
            const __half* Kt = Kg + (size_t)(kb + 1) * 128 * QKVD;
            const __half* Vt = Vg + (size_t)(kb + 1) * 128 * QKVD;
            const uint32_t so = (uint32_t)((buf ^ 1) * 128 * 144);
#pragma unroll
            for (int i = 0; i < 4; i++) {
                const int idx = tid + i * 256;
                const int r = idx >> 3, c = (idx & 7) * 8;
                cp_async16(sK_u + so + (uint32_t)(r * 144 + c * 2),
                           Kt + (size_t)r * QKVD + c);
                cp_async16(sV_u + so + (uint32_t)(r * 144 + c * 2),
                           Vt + (size_t)r * QKVD + c);
            }
            cp_commit();
            cp_wait1();
        } else {
            cp_wait0();
        }
        __syncthreads();

        // ---- S = Q @ K^T (16 x 128 per warp) via ldmatrix K frags ----
        float sc[16][4];
#pragma unroll
        for (int nt = 0; nt < 16; nt++) {
#pragma unroll
            for (int r = 0; r < 4; r++) sc[nt][r] = 0.0f;
        }
        const uint32_t kBase = sK_u + (uint32_t)(buf * 128 * 144) + kLane;
#pragma unroll
        for (int p = 0; p < 8; p++) {
            const uint32_t kp = kBase + (uint32_t)(p * 16 * 144);
#pragma unroll
            for (int ks = 0; ks < 4; ks++) {
                uint32_t kf[4];
                ldmx4(kf, kp + ks * 32);
                mma_f16(sc[2 * p],     qf[ks], kf);
                mma_f16(sc[2 * p + 1], qf[ks], kf + 2);
            }
        }

        // ---- online softmax ----
        float mx0 = m0, mx1 = m1;
#pragma unroll
        for (int nt = 0; nt < 16; nt++) {
            mx0 = fmaxf(mx0, fmaxf(sc[nt][0], sc[nt][1]));
            mx1 = fmaxf(mx1, fmaxf(sc[nt][2], sc[nt][3]));
        }
        mx0 = fmaxf(mx0, __shfl_xor_sync(0xffffffffu, mx0, 1));
        mx0 = fmaxf(mx0, __shfl_xor_sync(0xffffffffu, mx0, 2));
        mx1 = fmaxf(mx1, __shfl_xor_sync(0xffffffffu, mx1, 1));
        mx1 = fmaxf(mx1, __shfl_xor_sync(0xffffffffu, mx1, 2));

        const float s0 = fexp(m0 - mx0);
        const float s1 = fexp(m1 - mx1);
        m0 = mx0; m1 = mx1;
        l0 *= s0;  l1 *= s1;
#pragma unroll
        for (int n = 0; n < 8; n++) {
            oacc[n][0] *= s0; oacc[n][1] *= s0;
            oacc[n][2] *= s1; oacc[n][3] *= s1;
        }

        const int prow = warp * 16 + g;
        uint32_t* pw0 = (uint32_t*)sP + prow * SPW;
        uint32_t* pw1 = (uint32_t*)sP + (prow + 8) * SPW;
        float ls0 = 0.0f, ls1 = 0.0f;
#pragma unroll
        for (int nt = 0; nt < 16; nt++) {
            const float p0 = fexp(sc[nt][0] - mx0);
            const float p1 = fexp(sc[nt][1] - mx0);
            const float p2 = fexp(sc[nt][2] - mx1);
            const float p3 = fexp(sc[nt][3] - mx1);
            ls0 += p0 + p1;
            ls1 += p2 + p3;
            const __half2 h01 = __floats2half2_rn(p0, p1);
            const __half2 h23 = __floats2half2_rn(p2, p3);
            pw0[nt * 4 + t4] = *(const uint32_t*)&h01;
            pw1[nt * 4 + t4] = *(const uint32_t*)&h23;
        }
        l0 += ls0; l1 += ls1;
        __syncthreads();

        // ---- O += P @ V (ldmatrix.trans V frags) ----
        const uint32_t vBase = sV_u + (uint32_t)(buf * 128 * 144) + vLane;
        const uint32_t* pa0 = (const uint32_t*)sP + prow * SPW + t4;
        const uint32_t* pa1 = (const uint32_t*)sP + (prow + 8) * SPW + t4;
#pragma unroll
        for (int ks = 0; ks < 8; ks++) {
            uint32_t af[4];
            af[0] = pa0[ks * 8];
            af[1] = pa1[ks * 8];
            af[2] = pa0[ks * 8 + 4];
            af[3] = pa1[ks * 8 + 4];
            const uint32_t vks = vBase + (uint32_t)(ks * 16 * 144);
#pragma unroll
            for (int nt2 = 0; nt2 < 4; nt2++) {
                uint32_t vr[4];
                ldmx4_trans(vr, vks + (uint32_t)(nt2 * 32));
                mma_f16(oacc[nt2 * 2],     af, vr);
                mma_f16(oacc[nt2 * 2 + 1], af, vr + 2);
            }
        }
        __syncthreads();
    }

    l0 += __shfl_xor_sync(0xffffffffu, l0, 1);
    l0 += __shfl_xor_sync(0xffffffffu, l0, 2);
    l1 += __shfl_xor_sync(0xffffffffu, l1, 1);
    l1 += __shfl_xor_sync(0xffffffffu, l1, 2);
    const float inv0 = 1.0f / l0;
    const float inv1 = 1.0f / l1;

    const size_t row = base + q0 + warp * 16 + g;
    __half* Og = O + row * DDIM + h * HDIM;
#pragma unroll
    for (int nt = 0; nt < 8; nt++) {
        const int col = nt * 8 + 2 * t4;
        *(__half2*)(Og + col) =
            __floats2half2_rn(oacc[nt][0] * inv0, oacc[nt][1] * inv0);
        *(__half2*)(Og + 8 * DDIM + col) =
            __floats2half2_rn(oacc[nt][2] * inv1, oacc[nt][3] * inv1);
    }
}

// ---------------------------------------------------------------------------
// LayerNorm (D=1024), one block per row; optional fp16 twin output.
// ---------------------------------------------------------------------------
__global__ __launch_bounds__(256)
void ln_kernel(const float* __restrict__ x, const float* __restrict__ g,
               const float* __restrict__ b, float* __restrict__ y,
               __half* __restrict__ yh)
{
    const int D = DDIM;
    const int row = blockIdx.x;
    const float* xr = x + (size_t)row * D;

    float v[4];
    float s = 0.f, s2 = 0.f;
#pragma unroll
    for (int i = 0; i < 4; i++) {
        v[i] = xr[threadIdx.x + i * 256];
        s += v[i];
        s2 = fmaf(v[i], v[i], s2);
    }
#pragma unroll
    for (int o = 16; o > 0; o >>= 1) {
        s  += __shfl_xor_sync(0xffffffffu, s, o);
        s2 += __shfl_xor_sync(0xffffffffu, s2, o);
    }
    __shared__ float ss[8], ss2[8];
    const int w = threadIdx.x >> 5;
    if ((threadIdx.x & 31) == 0) { ss[w] = s; ss2[w] = s2; }
    __syncthreads();
    if (threadIdx.x < 32) {
        s  = (threadIdx.x < 8) ? ss[threadIdx.x]  : 0.f;
        s2 = (threadIdx.x < 8) ? ss2[threadIdx.x] : 0.f;
#pragma unroll
        for (int o = 4; o > 0; o >>= 1) {
            s  += __shfl_xor_sync(0xffffffffu, s, o);
            s2 += __shfl_xor_sync(0xffffffffu, s2, o);
        }
        if (threadIdx.x == 0) { ss[0] = s; ss2[0] = s2; }
    }
    __syncthreads();
    const float mu  = ss[0] * (1.0f / D);
    const float var = ss2[0] * (1.0f / D) - mu * mu;
    const float inv = rsqrtf(var + 1e-5f);
#pragma unroll
    for (int i = 0; i < 4; i++) {
        const int c = threadIdx.x + i * 256;
        const float val = (v[i] - mu) * inv * g[c] + b[c];
        y[(size_t)row * D + c] = val;
        if (yh) yh[(size_t)row * D + c] = __float2half_rn(val);
    }
}

// ---------------------------------------------------------------------------
// Launch
// ---------------------------------------------------------------------------
extern "C" void kernel_launch(void* const* d_in, const int* in_sizes, int n_in,
                              void* d_out, int out_size)
{
    (void)in_sizes; (void)n_in; (void)out_size;
    const float* x     = (const float*)d_in[0];
    const float* Wq    = (const float*)d_in[1];
    const float* bq    = (const float*)d_in[2];
    const float* Wk    = (const float*)d_in[3];
    const float* bk    = (const float*)d_in[4];
    const float* Wv    = (const float*)d_in[5];
    const float* bv    = (const float*)d_in[6];
    const float* Wo    = (const float*)d_in[7];
    const float* bo    = (const float*)d_in[8];
    const float* W1    = (const float*)d_in[9];
    const float* b1    = (const float*)d_in[10];
    const float* W2    = (const float*)d_in[11];
    const float* b2    = (const float*)d_in[12];
    const float* g1    = (const float*)d_in[13];
    const float* beta1 = (const float*)d_in[14];
    const float* g2    = (const float*)d_in[15];
    const float* beta2 = (const float*)d_in[16];
    float* out = (float*)d_out;

    float* scr = nullptr;
    cudaGetSymbolAddress((void**)&scr, g_scratch);
    __half* qkvh  = (__half*)(scr + OFF_QKVH);
    float*  x1    = scr + OFF_X1;
    float*  x2    = scr + OFF_X2;
    float*  x3    = scr + OFF_X3;
    __half* atth  = (__half*)(scr + OFF_ATTH);
    __half* x2h   = (__half*)(scr + OFF_X2H);
    __half* hh    = (__half*)(scr + OFF_HH);
    __half* xh    = (__half*)(scr + OFF_XH);
    __half* WqkvT = (__half*)(scr + OFF_WQKVT);
    __half* WoT   = (__half*)(scr + OFF_WOT);
    __half* W1T   = (__half*)(scr + OFF_W1T);
    __half* W2T   = (__half*)(scr + OFF_W2T);
    float*  bqkv  = scr + OFF_BQKV;

    cudaFuncSetAttribute(gemm_h<0,1>, cudaFuncAttributeMaxDynamicSharedMemorySize, GT_SMEM);
    cudaFuncSetAttribute(gemm_h<1,1>, cudaFuncAttributeMaxDynamicSharedMemorySize, GT_SMEM);
    cudaFuncSetAttribute(gemm_h<2,0>, cudaFuncAttributeMaxDynamicSharedMemorySize, GT_SMEM);
    cudaFuncSetAttribute(attn_h_kernel, cudaFuncAttributeMaxDynamicSharedMemorySize, AT_SMEM);

    // prep
    f2h_kernel<<<(MTOK * DDIM / 4) / 256, 256>>>(x, xh);
    prep_weights<<<12288, 256>>>(Wq, Wk, Wv, Wo, W1, W2, WqkvT, WoT, W1T, W2T);
    bias_concat_kernel<<<QKVD / 256, 256>>>(bq, bk, bv, bqkv);

    // fused QKV projection -> fp16
    gemm_h<0,1><<<dim3(QKVD / BN, MTOK / BM), 512, GT_SMEM>>>(
        xh, WqkvT, bqkv, nullptr, qkvh, MTOK, QKVD, DDIM);

    // attention (fp16 tensor cores, no scaling)
    attn_h_kernel<<<dim3(SEQ / 128, NHEAD, BATCH), 256, AT_SMEM>>>(qkvh, atth);

    // output projection + residual
    gemm_h<2,0><<<dim3(DDIM / BN, MTOK / BM), 512, GT_SMEM>>>(
        atth, WoT, bo, x, x1, MTOK, DDIM, DDIM);

    // LN1
    ln_kernel<<<MTOK, 256>>>(x1, g1, beta1, x2, x2h);

    // FFN
    gemm_h<1,1><<<dim3(FFDIM / BN, MTOK / BM), 512, GT_SMEM>>>(
        x2h, W1T, b1, nullptr, hh, MTOK, FFDIM, DDIM);
    gemm_h<2,0><<<dim3(DDIM / BN, MTOK / BM), 512, GT_SMEM>>>(
        hh, W2T, b2, x2, x3, MTOK, DDIM, FFDIM);

    // LN2 -> output
    ln_kernel<<<MTOK, 256>>>(x3, g2, beta2, out, nullptr);
}

// round 11
// speedup vs baseline: 5.1605x; 1.0103x over previous
#include <cuda_runtime.h>
#include <cuda_fp16.h>
#include <math.h>
#include <cstdint>

// ---------------------------------------------------------------------------
// Transformer block. All GEMMs + attention via mma.sync fp16 (fp32 accum),
// fragment loads via ldmatrix. GEMM: 128x128 tiles, 2 CTAs/SM.
// M=4096, D=1024, H=16, hd=64, FF=4096.
// ---------------------------------------------------------------------------

#define MTOK 4096
#define DDIM 1024
#define QKVD 3072
#define FFDIM 4096
#define NHEAD 16
#define HDIM 64
#define SEQ 2048
#define BATCH 2

// scratch layout (units: floats)
#define OFF_QKVH  ((size_t)0)
#define OFF_X1    (OFF_QKVH + (size_t)MTOK*QKVD/2)
#define OFF_X2    (OFF_X1   + (size_t)MTOK*DDIM)
#define OFF_X3    (OFF_X2   + (size_t)MTOK*DDIM)
#define OFF_ATTH  (OFF_X3   + (size_t)MTOK*DDIM)
#define OFF_X2H   (OFF_ATTH + (size_t)MTOK*DDIM/2)
#define OFF_HH    (OFF_X2H  + (size_t)MTOK*DDIM/2)
#define OFF_XH    (OFF_HH   + (size_t)MTOK*FFDIM/2)
#define OFF_WQKVT (OFF_XH   + (size_t)MTOK*DDIM/2)
#define OFF_WOT   (OFF_WQKVT+ (size_t)QKVD*DDIM/2)
#define OFF_W1T   (OFF_WOT  + (size_t)DDIM*DDIM/2)
#define OFF_W2T   (OFF_W1T  + (size_t)DDIM*FFDIM/2)
#define OFF_BQKV  (OFF_W2T  + (size_t)FFDIM*DDIM/2)
#define SCRATCH_FLOATS (OFF_BQKV + (size_t)QKVD)

__device__ float g_scratch[SCRATCH_FLOATS];

// ---------------- PTX helpers ----------------
__device__ __forceinline__ void cp_async16(uint32_t dst, const void* src) {
    asm volatile("cp.async.cg.shared.global [%0], [%1], 16;"
                 :: "r"(dst), "l"(src) : "memory");
}
__device__ __forceinline__ void cp_commit() {
    asm volatile("cp.async.commit_group;" ::: "memory");
}
__device__ __forceinline__ void cp_wait0() {
    asm volatile("cp.async.wait_group 0;" ::: "memory");
}
__device__ __forceinline__ void cp_wait1() {
    asm volatile("cp.async.wait_group 1;" ::: "memory");
}
__device__ __forceinline__ uint32_t smem_u32(const void* p) {
    uint32_t a;
    asm("{ .reg .u64 t; cvta.to.shared.u64 t, %1; cvt.u32.u64 %0, t; }"
        : "=r"(a) : "l"(p));
    return a;
}
__device__ __forceinline__ void mma_f16(float* c, const uint32_t* a,
                                        const uint32_t* b) {
    asm volatile(
        "mma.sync.aligned.m16n8k16.row.col.f32.f16.f16.f32 "
        "{%0,%1,%2,%3}, {%4,%5,%6,%7}, {%8,%9}, {%0,%1,%2,%3};"
        : "+f"(c[0]), "+f"(c[1]), "+f"(c[2]), "+f"(c[3])
        : "r"(a[0]), "r"(a[1]), "r"(a[2]), "r"(a[3]), "r"(b[0]), "r"(b[1]));
}
__device__ __forceinline__ void ldmx4(uint32_t* r, uint32_t addr) {
    asm volatile(
        "ldmatrix.sync.aligned.m8n8.x4.shared.b16 {%0,%1,%2,%3}, [%4];"
        : "=r"(r[0]), "=r"(r[1]), "=r"(r[2]), "=r"(r[3]) : "r"(addr));
}
__device__ __forceinline__ void ldmx4_trans(uint32_t* r, uint32_t addr) {
    asm volatile(
        "ldmatrix.sync.aligned.m8n8.x4.trans.shared.b16 {%0,%1,%2,%3}, [%4];"
        : "=r"(r[0]), "=r"(r[1]), "=r"(r[2]), "=r"(r[3]) : "r"(addr));
}

// Fast exp on the FMA pipe (no MUFU).
__device__ __forceinline__ float fexp(float x) {
    float t = x * 1.4426950408889634f;
    t = fmaxf(t, -126.0f);
    const float fn = rintf(t);
    const float f = t - fn;
    float p = 1.33336500e-3f;
    p = fmaf(p, f, 9.61823766e-3f);
    p = fmaf(p, f, 5.55041087e-2f);
    p = fmaf(p, f, 2.40226507e-1f);
    p = fmaf(p, f, 6.93147182e-1f);
    p = fmaf(p, f, 1.0f);
    const int n = (int)fn;
    return p * __int_as_float((n + 127) << 23);
}

// ---------------------------------------------------------------------------
// fp16 GEMM: C[M,N] = A[M,K] @ Bt[N,K]^T + bias (+ epilogue)
// CTA 128x128, BK=32 halfs, 256 threads, double-buffered cp.async,
// ldmatrix.x4 fragment loads. 72KB smem -> 2 CTAs/SM.
// ---------------------------------------------------------------------------
#define BM 128
#define BN 128
#define ATILE_B (128 * 144)        // bytes per A buffer
#define BTILE_B (128 * 144)
#define GT_SMEM (2 * ATILE_B + 2 * BTILE_B)   // 73728

template <int EPI, int HOUT>
__global__ __launch_bounds__(256, 2)
void gemm_h(const __half* __restrict__ A, const __half* __restrict__ Bt,
            const float* __restrict__ bias, const float* __restrict__ res,
            void* __restrict__ Cout, int M, int N, int K)
{
    extern __shared__ __half smh[];
    const uint32_t As_u = smem_u32(smh);
    const uint32_t Bs_u = As_u + 2 * ATILE_B;

    const int tid  = threadIdx.x;
    const int warp = tid >> 5;
    const int lane = tid & 31;
    const int g    = lane >> 2;
    const int t4   = lane & 3;
    const int wm   = warp >> 2;     // 0..1, 64 rows each
    const int wn   = warp & 3;      // 0..3, 32 cols each

    const int m0 = blockIdx.y * BM;
    const int n0 = blockIdx.x * BN;

    // loaders: 128 rows x 4 chunks of 16B each for A and B; 256 thr x 2 each
    const int lrow = tid >> 1;
    const int l16  = (tid & 1) * 2;
    const __half* Ag = A + (size_t)(m0 + lrow) * K + l16 * 8;
    const __half* Bg = Bt + (size_t)(n0 + lrow) * K + l16 * 8;
    const uint32_t Asm = As_u + (uint32_t)(lrow * 144 + l16 * 16);
    const uint32_t Bsm = Bs_u + (uint32_t)(lrow * 144 + l16 * 16);

    // ldmatrix per-lane offsets
    const uint32_t aLane = (uint32_t)((wm * 64 + (lane & 15)) * 144 +
                                      (lane >> 4) * 16);
    const uint32_t bLane = (uint32_t)((wn * 32 + (lane >> 4) * 8 + (lane & 7)) * 144 +
                                      ((lane >> 3) & 1) * 16);

    float acc[4][4][4];
#pragma unroll
    for (int mi = 0; mi < 4; mi++)
#pragma unroll
        for (int ni = 0; ni < 4; ni++)
#pragma unroll
            for (int r = 0; r < 4; r++) acc[mi][ni][r] = 0.0f;

    const int T = K >> 5;

    cp_async16(Asm, Ag);
    cp_async16(Asm + 16, Ag + 8);
    cp_async16(Bsm, Bg);
    cp_async16(Bsm + 16, Bg + 8);
    cp_commit();

    for (int tb = 0; tb < T; tb++) {
        const int b = tb & 1;
        if (tb + 1 < T) {
            const uint32_t ao = (uint32_t)((b ^ 1) * ATILE_B);
            const uint32_t bo = (uint32_t)((b ^ 1) * BTILE_B);
            const size_t ko = (size_t)(tb + 1) * 32;
            cp_async16(Asm + ao, Ag + ko);
            cp_async16(Asm + ao + 16, Ag + ko + 8);
            cp_async16(Bsm + bo, Bg + ko);
            cp_async16(Bsm + bo + 16, Bg + ko + 8);
            cp_commit();
            cp_wait1();
        } else {
            cp_wait0();
        }
        __syncthreads();

        const uint32_t aBase = As_u + (uint32_t)(b * ATILE_B) + aLane;
        const uint32_t bBase = Bs_u + (uint32_t)(b * BTILE_B) + bLane;
#pragma unroll
        for (int kk = 0; kk < 2; kk++) {
            uint32_t af[4][4], bf4[2][4];
#pragma unroll
            for (int mi = 0; mi < 4; mi++)
                ldmx4(af[mi], aBase + mi * (16 * 144) + kk * 32);
#pragma unroll
            for (int p = 0; p < 2; p++)
                ldmx4(bf4[p], bBase + p * (16 * 144) + kk * 32);
#pragma unroll
            for (int mi = 0; mi < 4; mi++)
#pragma unroll
                for (int ni = 0; ni < 4; ni++)
                    mma_f16(acc[mi][ni], af[mi], bf4[ni >> 1] + (ni & 1) * 2);
        }
        __syncthreads();
    }

    float* Cf = (float*)Cout;
    __half* Ch = (__half*)Cout;
#pragma unroll
    for (int mi = 0; mi < 4; mi++) {
        const int row0 = m0 + wm * 64 + mi * 16 + g;
#pragma unroll
        for (int ni = 0; ni < 4; ni++) {
            const int col = n0 + wn * 32 + ni * 8 + t4 * 2;
            const float b0 = bias[col], b1 = bias[col + 1];
            float v0 = acc[mi][ni][0] + b0;
            float v1 = acc[mi][ni][1] + b1;
            float v2 = acc[mi][ni][2] + b0;
            float v3 = acc[mi][ni][3] + b1;
            if (EPI == 1) {
                v0 = 0.5f * v0 * (1.0f + erff(v0 * 0.70710678118654752f));
                v1 = 0.5f * v1 * (1.0f + erff(v1 * 0.70710678118654752f));
                v2 = 0.5f * v2 * (1.0f + erff(v2 * 0.70710678118654752f));
                v3 = 0.5f * v3 * (1.0f + erff(v3 * 0.70710678118654752f));
            } else if (EPI == 2) {
                const float2 r0 = *(const float2*)(res + (size_t)row0 * N + col);
                const float2 r1 = *(const float2*)(res + (size_t)(row0 + 8) * N + col);
                v0 += r0.x; v1 += r0.y; v2 += r1.x; v3 += r1.y;
            }
            if (HOUT) {
                *(__half2*)(Ch + (size_t)row0 * N + col) = __floats2half2_rn(v0, v1);
                *(__half2*)(Ch + (size_t)(row0 + 8) * N + col) = __floats2half2_rn(v2, v3);
            } else {
                *(float2*)(Cf + (size_t)row0 * N + col) = make_float2(v0, v1);
                *(float2*)(Cf + (size_t)(row0 + 8) * N + col) = make_float2(v2, v3);
            }
        }
    }
}

// ---------------------------------------------------------------------------
// Merged weight prep: all 6 transposes in ONE kernel (fp32 -> fp16^T).
// ---------------------------------------------------------------------------
__global__ __launch_bounds__(256)
void prep_weights(const float* __restrict__ Wq, const float* __restrict__ Wk,
                  const float* __restrict__ Wv, const float* __restrict__ Wo,
                  const float* __restrict__ W1, const float* __restrict__ W2,
                  __half* __restrict__ WqkvT, __half* __restrict__ WoT,
                  __half* __restrict__ W1T, __half* __restrict__ W2T)
{
    const int b = blockIdx.x;
    const float* in;
    __half* out;
    int R, C, tile;
    if (b < 4096) {
        const int w = b >> 10;
        tile = b & 1023;
        R = 1024; C = 1024;
        in  = (w == 0) ? Wq : (w == 1) ? Wk : (w == 2) ? Wv : Wo;
        out = (w < 3) ? WqkvT + (size_t)w * 1024 * 1024 : WoT;
    } else if (b < 8192) {
        tile = b - 4096; R = 1024; C = 4096; in = W1; out = W1T;
    } else {
        tile = b - 8192; R = 4096; C = 1024; in = W2; out = W2T;
    }
    const int tcx = C >> 5;
    const int c0 = (tile % tcx) * 32, r0 = (tile / tcx) * 32;

    __shared__ float t[32][33];
    const int tx = threadIdx.x & 31, ty = threadIdx.x >> 5;
#pragma unroll
    for (int i = ty; i < 32; i += 8)
        t[i][tx] = in[(size_t)(r0 + i) * C + c0 + tx];
    __syncthreads();
#pragma unroll
    for (int i = ty; i < 32; i += 8)
        out[(size_t)(c0 + i) * R + r0 + tx] = __float2half_rn(t[tx][i]);
}

__global__ void bias_concat_kernel(const float* __restrict__ bq,
                                   const float* __restrict__ bk,
                                   const float* __restrict__ bv,
                                   float* __restrict__ bqkv)
{
    const int i = blockIdx.x * 256 + threadIdx.x;
    if (i < DDIM) bqkv[i] = bq[i];
    else if (i < 2 * DDIM) bqkv[i] = bk[i - DDIM];
    else bqkv[i] = bv[i - 2 * DDIM];
}

__global__ __launch_bounds__(256)
void f2h_kernel(const float* __restrict__ in, __half* __restrict__ out)
{
    const int i = blockIdx.x * 256 + threadIdx.x;
    const float4 v = ((const float4*)in)[i];
    ((__half2*)out)[2 * i]     = __floats2half2_rn(v.x, v.y);
    ((__half2*)out)[2 * i + 1] = __floats2half2_rn(v.z, v.w);
}

// ---------------------------------------------------------------------------
// fp16 tensor-core flash attention (no scaling). ldmatrix for K and V frags.
// ---------------------------------------------------------------------------
#define SPW 68            // P stride in 32-bit words (136 halfs)
#define NKB (SEQ / 128)
#define AT_P_BYTES (128 * 136 * 2)
#define AT_K_BYTES (2 * 128 * 144)
#define AT_SMEM (AT_P_BYTES + 2 * AT_K_BYTES)

__global__ __launch_bounds__(256)
void attn_h_kernel(const __half* __restrict__ QKV, __half* __restrict__ O)
{
    extern __shared__ char smc[];
    __half* sP = (__half*)smc;                       // [128][136]
    const uint32_t sP_u = smem_u32(sP);
    const uint32_t sK_u = sP_u + AT_P_BYTES;
    const uint32_t sV_u = sK_u + AT_K_BYTES;
    __half* sQstage = sP;                            // Q staged at stride 72

    const int bz   = blockIdx.z;
    const int h    = blockIdx.y;
    const int q0   = blockIdx.x * 128;
    const int tid  = threadIdx.x;
    const int warp = tid >> 5;
    const int lane = tid & 31;
    const int g    = lane >> 2;
    const int t4   = lane & 3;

    const size_t base = (size_t)bz * SEQ;
    const __half* Qg = QKV + (base + q0) * QKVD + h * HDIM;
    const __half* Kg = QKV + base * QKVD + DDIM + h * HDIM;
    const __half* Vg = QKV + base * QKVD + 2 * DDIM + h * HDIM;

    for (int i = tid; i < 128 * 8; i += 256) {
        const int r = i >> 3, c = (i & 7) * 8;
        *(uint4*)(sQstage + r * 72 + c) = *(const uint4*)(Qg + (size_t)r * QKVD + c);
    }
    __syncthreads();

    uint32_t qf[4][4];
    {
        const uint32_t* qrow = (const uint32_t*)sQstage + (warp * 16 + g) * 36;
#pragma unroll
        for (int ks = 0; ks < 4; ks++) {
            qf[ks][0] = qrow[ks * 8 + t4];
            qf[ks][1] = qrow[8 * 36 + ks * 8 + t4];
            qf[ks][2] = qrow[ks * 8 + t4 + 4];
            qf[ks][3] = qrow[8 * 36 + ks * 8 + t4 + 4];
        }
    }
    __syncthreads();

    float oacc[8][4];
#pragma unroll
    for (int n = 0; n < 8; n++)
#pragma unroll
        for (int r = 0; r < 4; r++) oacc[n][r] = 0.0f;
    float m0 = -1e30f, m1 = -1e30f, l0 = 0.0f, l1 = 0.0f;

    const uint32_t kLane = (uint32_t)(((lane >> 4) * 8 + (lane & 7)) * 144 +
                                      ((lane >> 3) & 1) * 16);
    const int lmat = lane >> 3;
    const int lrow = lane & 7;
    const uint32_t vLane = (uint32_t)(((lmat & 1) * 8 + lrow) * 144 +
                                      ((lmat >> 1) * 8) * 2);

#pragma unroll
    for (int i = 0; i < 4; i++) {
        const int idx = tid + i * 256;
        const int r = idx >> 3, c = (idx & 7) * 8;
        cp_async16(sK_u + (uint32_t)(r * 144 + c * 2), Kg + (size_t)r * QKVD + c);
        cp_async16(sV_u + (uint32_t)(r * 144 + c * 2), Vg + (size_t)r * QKVD + c);
    }
    cp_commit();

    for (int kb = 0; kb < NKB; kb++) {
        const int buf = kb & 1;

        if (kb + 1 < NKB) {
            const __half* Kt = Kg + (size_t)(kb + 1) * 128 * QKVD;
            const __half* Vt = Vg + (size_t)(kb + 1) * 128 * QKVD;
            const uint32_t so = (uint32_t)((buf ^ 1) * 128 * 144);
#pragma unroll
            for (int i = 0; i < 4; i++) {
                const int idx = tid + i * 256;
                const int r = idx >> 3, c = (idx & 7) * 8;
                cp_async16(sK_u + so + (uint32_t)(r * 144 + c * 2),
                           Kt + (size_t)r * QKVD + c);
                cp_async16(sV_u + so + (uint32_t)(r * 144 + c * 2),
                           Vt + (size_t)r * QKVD + c);
            }
            cp_commit();
            cp_wait1();
        } else {
            cp_wait0();
        }
        __syncthreads();

        float sc[16][4];
#pragma unroll
        for (int nt = 0; nt < 16; nt++) {
#pragma unroll
            for (int r = 0; r < 4; r++) sc[nt][r] = 0.0f;
        }
        const uint32_t kBase = sK_u + (uint32_t)(buf * 128 * 144) + kLane;
#pragma unroll
        for (int p = 0; p < 8; p++) {
            const uint32_t kp = kBase + (uint32_t)(p * 16 * 144);
#pragma unroll
            for (int ks = 0; ks < 4; ks++) {
                uint32_t kf[4];
                ldmx4(kf, kp + ks * 32);
                mma_f16(sc[2 * p],     qf[ks], kf);
                mma_f16(sc[2 * p + 1], qf[ks], kf + 2);
            }
        }

        float mx0 = m0, mx1 = m1;
#pragma unroll
        for (int nt = 0; nt < 16; nt++) {
            mx0 = fmaxf(mx0, fmaxf(sc[nt][0], sc[nt][1]));
            mx1 = fmaxf(mx1, fmaxf(sc[nt][2], sc[nt][3]));
        }
        mx0 = fmaxf(mx0, __shfl_xor_sync(0xffffffffu, mx0, 1));
        mx0 = fmaxf(mx0, __shfl_xor_sync(0xffffffffu, mx0, 2));
        mx1 = fmaxf(mx1, __shfl_xor_sync(0xffffffffu, mx1, 1));
        mx1 = fmaxf(mx1, __shfl_xor_sync(0xffffffffu, mx1, 2));

        const float s0 = fexp(m0 - mx0);
        const float s1 = fexp(m1 - mx1);
        m0 = mx0; m1 = mx1;
        l0 *= s0;  l1 *= s1;
#pragma unroll
        for (int n = 0; n < 8; n++) {
            oacc[n][0] *= s0; oacc[n][1] *= s0;
            oacc[n][2] *= s1; oacc[n][3] *= s1;
        }

        const int prow = warp * 16 + g;
        uint32_t* pw0 = (uint32_t*)sP + prow * SPW;
        uint32_t* pw1 = (uint32_t*)sP + (prow + 8) * SPW;
        float ls0 = 0.0f, ls1 = 0.0f;
#pragma unroll
        for (int nt = 0; nt < 16; nt++) {
            const float p0 = fexp(sc[nt][0] - mx0);
            const float p1 = fexp(sc[nt][1] - mx0);
            const float p2 = fexp(sc[nt][2] - mx1);
            const float p3 = fexp(sc[nt][3] - mx1);
            ls0 += p0 + p1;
            ls1 += p2 + p3;
            const __half2 h01 = __floats2half2_rn(p0, p1);
            const __half2 h23 = __floats2half2_rn(p2, p3);
            pw0[nt * 4 + t4] = *(const uint32_t*)&h01;
            pw1[nt * 4 + t4] = *(const uint32_t*)&h23;
        }
        l0 += ls0; l1 += ls1;
        __syncthreads();

        const uint32_t vBase = sV_u + (uint32_t)(buf * 128 * 144) + vLane;
        const uint32_t* pa0 = (const uint32_t*)sP + prow * SPW + t4;
        const uint32_t* pa1 = (const uint32_t*)sP + (prow + 8) * SPW + t4;
#pragma unroll
        for (int ks = 0; ks < 8; ks++) {
            uint32_t af[4];
            af[0] = pa0[ks * 8];
            af[1] = pa1[ks * 8];
            af[2] = pa0[ks * 8 + 4];
            af[3] = pa1[ks * 8 + 4];
            const uint32_t vks = vBase + (uint32_t)(ks * 16 * 144);
#pragma unroll
            for (int nt2 = 0; nt2 < 4; nt2++) {
                uint32_t vr[4];
                ldmx4_trans(vr, vks + (uint32_t)(nt2 * 32));
                mma_f16(oacc[nt2 * 2],     af, vr);
                mma_f16(oacc[nt2 * 2 + 1], af, vr + 2);
            }
        }
        __syncthreads();
    }

    l0 += __shfl_xor_sync(0xffffffffu, l0, 1);
    l0 += __shfl_xor_sync(0xffffffffu, l0, 2);
    l1 += __shfl_xor_sync(0xffffffffu, l1, 1);
    l1 += __shfl_xor_sync(0xffffffffu, l1, 2);
    const float inv0 = 1.0f / l0;
    const float inv1 = 1.0f / l1;

    const size_t row = base + q0 + warp * 16 + g;
    __half* Og = O + row * DDIM + h * HDIM;
#pragma unroll
    for (int nt = 0; nt < 8; nt++) {
        const int col = nt * 8 + 2 * t4;
        *(__half2*)(Og + col) =
            __floats2half2_rn(oacc[nt][0] * inv0, oacc[nt][1] * inv0);
        *(__half2*)(Og + 8 * DDIM + col) =
            __floats2half2_rn(oacc[nt][2] * inv1, oacc[nt][3] * inv1);
    }
}

// ---------------------------------------------------------------------------
// LayerNorm (D=1024), one block per row; optional fp16 twin output.
// ---------------------------------------------------------------------------
__global__ __launch_bounds__(256)
void ln_kernel(const float* __restrict__ x, const float* __restrict__ g,
               const float* __restrict__ b, float* __restrict__ y,
               __half* __restrict__ yh)
{
    const int D = DDIM;
    const int row = blockIdx.x;
    const float* xr = x + (size_t)row * D;

    float v[4];
    float s = 0.f, s2 = 0.f;
#pragma unroll
    for (int i = 0; i < 4; i++) {
        v[i] = xr[threadIdx.x + i * 256];
        s += v[i];
        s2 = fmaf(v[i], v[i], s2);
    }
#pragma unroll
    for (int o = 16; o > 0; o >>= 1) {
        s  += __shfl_xor_sync(0xffffffffu, s, o);
        s2 += __shfl_xor_sync(0xffffffffu, s2, o);
    }
    __shared__ float ss[8], ss2[8];
    const int w = threadIdx.x >> 5;
    if ((threadIdx.x & 31) == 0) { ss[w] = s; ss2[w] = s2; }
    __syncthreads();
    if (threadIdx.x < 32) {
        s  = (threadIdx.x < 8) ? ss[threadIdx.x]  : 0.f;
        s2 = (threadIdx.x < 8) ? ss2[threadIdx.x] : 0.f;
#pragma unroll
        for (int o = 4; o > 0; o >>= 1) {
            s  += __shfl_xor_sync(0xffffffffu, s, o);
            s2 += __shfl_xor_sync(0xffffffffu, s2, o);
        }
        if (threadIdx.x == 0) { ss[0] = s; ss2[0] = s2; }
    }
    __syncthreads();
    const float mu  = ss[0] * (1.0f / D);
    const float var = ss2[0] * (1.0f / D) - mu * mu;
    const float inv = rsqrtf(var + 1e-5f);
#pragma unroll
    for (int i = 0; i < 4; i++) {
        const int c = threadIdx.x + i * 256;
        const float val = (v[i] - mu) * inv * g[c] + b[c];
        y[(size_t)row * D + c] = val;
        if (yh) yh[(size_t)row * D + c] = __float2half_rn(val);
    }
}

// ---------------------------------------------------------------------------
// Launch
// ---------------------------------------------------------------------------
extern "C" void kernel_launch(void* const* d_in, const int* in_sizes, int n_in,
                              void* d_out, int out_size)
{
    (void)in_sizes; (void)n_in; (void)out_size;
    const float* x     = (const float*)d_in[0];
    const float* Wq    = (const float*)d_in[1];
    const float* bq    = (const float*)d_in[2];
    const float* Wk    = (const float*)d_in[3];
    const float* bk    = (const float*)d_in[4];
    const float* Wv    = (const float*)d_in[5];
    const float* bv    = (const float*)d_in[6];
    const float* Wo    = (const float*)d_in[7];
    const float* bo    = (const float*)d_in[8];
    const float* W1    = (const float*)d_in[9];
    const float* b1    = (const float*)d_in[10];
    const float* W2    = (const float*)d_in[11];
    const float* b2    = (const float*)d_in[12];
    const float* g1    = (const float*)d_in[13];
    const float* beta1 = (const float*)d_in[14];
    const float* g2    = (const float*)d_in[15];
    const float* beta2 = (const float*)d_in[16];
    float* out = (float*)d_out;

    float* scr = nullptr;
    cudaGetSymbolAddress((void**)&scr, g_scratch);
    __half* qkvh  = (__half*)(scr + OFF_QKVH);
    float*  x1    = scr + OFF_X1;
    float*  x2    = scr + OFF_X2;
    float*  x3    = scr + OFF_X3;
    __half* atth  = (__half*)(scr + OFF_ATTH);
    __half* x2h   = (__half*)(scr + OFF_X2H);
    __half* hh    = (__half*)(scr + OFF_HH);
    __half* xh    = (__half*)(scr + OFF_XH);
    __half* WqkvT = (__half*)(scr + OFF_WQKVT);
    __half* WoT   = (__half*)(scr + OFF_WOT);
    __half* W1T   = (__half*)(scr + OFF_W1T);
    __half* W2T   = (__half*)(scr + OFF_W2T);
    float*  bqkv  = scr + OFF_BQKV;

    cudaFuncSetAttribute(gemm_h<0,1>, cudaFuncAttributeMaxDynamicSharedMemorySize, GT_SMEM);
    cudaFuncSetAttribute(gemm_h<1,1>, cudaFuncAttributeMaxDynamicSharedMemorySize, GT_SMEM);
    cudaFuncSetAttribute(gemm_h<2,0>, cudaFuncAttributeMaxDynamicSharedMemorySize, GT_SMEM);
    cudaFuncSetAttribute(attn_h_kernel, cudaFuncAttributeMaxDynamicSharedMemorySize, AT_SMEM);

    // prep
    f2h_kernel<<<(MTOK * DDIM / 4) / 256, 256>>>(x, xh);
    prep_weights<<<12288, 256>>>(Wq, Wk, Wv, Wo, W1, W2, WqkvT, WoT, W1T, W2T);
    bias_concat_kernel<<<QKVD / 256, 256>>>(bq, bk, bv, bqkv);

    // fused QKV projection -> fp16
    gemm_h<0,1><<<dim3(QKVD / BN, MTOK / BM), 256, GT_SMEM>>>(
        xh, WqkvT, bqkv, nullptr, qkvh, MTOK, QKVD, DDIM);

    // attention (fp16 tensor cores, no scaling)
    attn_h_kernel<<<dim3(SEQ / 128, NHEAD, BATCH), 256, AT_SMEM>>>(qkvh, atth);

    // output projection + residual
    gemm_h<2,0><<<dim3(DDIM / BN, MTOK / BM), 256, GT_SMEM>>>(
        atth, WoT, bo, x, x1, MTOK, DDIM, DDIM);

    // LN1
    ln_kernel<<<MTOK, 256>>>(x1, g1, beta1, x2, x2h);

    // FFN
    gemm_h<1,1><<<dim3(FFDIM / BN, MTOK / BM), 256, GT_SMEM>>>(
        x2h, W1T, b1, nullptr, hh, MTOK, FFDIM, DDIM);
    gemm_h<2,0><<<dim3(DDIM / BN, MTOK / BM), 256, GT_SMEM>>>(
        hh, W2T, b2, x2, x3, MTOK, DDIM, FFDIM);

    // LN2 -> output
    ln_kernel<<<MTOK, 256>>>(x3, g2, beta2, out, nullptr);
}